// round 1
// baseline (speedup 1.0000x reference)
#include <cuda_runtime.h>

// ---------------- problem constants ----------------
#define BATCH 2
#define C 64          // channels in/out
#define DW 128        // hidden width
#define HH 256
#define WW 256
#define HWPIX 65536   // H*W
#define GRID 8
#define CELLS 64      // per batch
#define PH 32         // cell side

// ---------------- scratch (device globals: allocation-free launch) ----------------
static __device__ float g_t[(size_t)BATCH * DW * HWPIX];     // conv1 output (67MB)
static __device__ float g_ymid[(size_t)BATCH * C * HWPIX];   // gated dw output (33.5MB)
static __device__ float g_sums[BATCH * CELLS * C];           // per-cell channel sums
static __device__ float g_s[BATCH * C];                      // SCA scale per (b, ch)

// ---------------- packed fp32x2 FMA (Blackwell FFMA2) ----------------
__device__ __forceinline__ float2 ffma2(const float2 a, const float2 b, const float2 c) {
    unsigned long long ra = *reinterpret_cast<const unsigned long long*>(&a);
    unsigned long long rb = *reinterpret_cast<const unsigned long long*>(&b);
    unsigned long long rc = *reinterpret_cast<const unsigned long long*>(&c);
    unsigned long long rd;
    asm("fma.rn.f32x2 %0, %1, %2, %3;" : "=l"(rd) : "l"(ra), "l"(rb), "l"(rc));
    return *reinterpret_cast<float2*>(&rd);
}

// =====================================================================
// K1: LN1 + modulated conv1x1 (C=64 -> DW=128), per-cell weights
// grid = 128 CTAs (b, u, v), block = 256
// =====================================================================
__global__ __launch_bounds__(256) void k1_ln_conv1(
    const float* __restrict__ x,
    const float* __restrict__ w1, const float* __restrict__ b1,
    const float* __restrict__ n1w, const float* __restrict__ n1b,
    const float* __restrict__ mod1)
{
    __shared__ float w1s[DW][C];
    __shared__ float b1s[DW];
    __shared__ float n1ws[C], n1bs[C];

    const int cta  = blockIdx.x;
    const int b    = cta >> 6;
    const int cell = cta & 63;
    const int u    = cell >> 3;
    const int v    = cell & 7;
    const int tid  = threadIdx.x;

    // ---- per-cell demodulated weights into smem ----
    if (tid < DW) {
        const int o = tid;
        const float* wrow = w1 + o * C;
        const float* mrow = mod1 + ((size_t)(b * DW + o) * C) * 64 + cell; // stride 64 per c
        float ss = 0.f;
        for (int c = 0; c < C; c++) {
            float wv = wrow[c] * mrow[(size_t)c * 64];
            w1s[o][c] = wv;
            ss += wv * wv;
        }
        float ri = rsqrtf(ss);
        for (int c = 0; c < C; c++) w1s[o][c] *= ri;
        b1s[o] = b1[o];
    }
    if (tid < C) { n1ws[tid] = n1w[tid]; n1bs[tid] = n1b[tid]; }
    __syncthreads();

    const size_t xbase = (size_t)b * C * HWPIX;
    const size_t tbase = (size_t)b * DW * HWPIX;

    for (int k = 0; k < 4; k++) {
        const int p  = k * 256 + tid;
        const int ph = p >> 5, pw = p & 31;
        const int h  = u * PH + ph, w = v * PH + pw;
        const int pix = h * WW + w;

        // load channel vector + LN statistics
        float2 va[32];
        float sum = 0.f, sumsq = 0.f;
        #pragma unroll
        for (int j = 0; j < 32; j++) {
            float v0 = x[xbase + (size_t)(2 * j) * HWPIX + pix];
            float v1 = x[xbase + (size_t)(2 * j + 1) * HWPIX + pix];
            va[j] = make_float2(v0, v1);
            sum += v0 + v1;
            sumsq += v0 * v0 + v1 * v1;
        }
        const float mu   = sum * (1.f / 64.f);
        const float var  = sumsq * (1.f / 64.f) - mu * mu;
        const float rstd = rsqrtf(var + 1e-6f);
        #pragma unroll
        for (int j = 0; j < 32; j++) {
            va[j].x = (va[j].x - mu) * rstd * n1ws[2 * j]     + n1bs[2 * j];
            va[j].y = (va[j].y - mu) * rstd * n1ws[2 * j + 1] + n1bs[2 * j + 1];
        }

        float* tout = g_t + tbase + pix;
        #pragma unroll 1
        for (int o = 0; o < DW; o += 2) {
            float2 acc0 = make_float2(0.f, 0.f), acc1 = make_float2(0.f, 0.f);
            const float4* r0 = reinterpret_cast<const float4*>(&w1s[o][0]);
            const float4* r1 = reinterpret_cast<const float4*>(&w1s[o + 1][0]);
            #pragma unroll
            for (int j4 = 0; j4 < 16; j4++) {
                float4 q0 = r0[j4], q1 = r1[j4];
                acc0 = ffma2(make_float2(q0.x, q0.y), va[2 * j4],     acc0);
                acc0 = ffma2(make_float2(q0.z, q0.w), va[2 * j4 + 1], acc0);
                acc1 = ffma2(make_float2(q1.x, q1.y), va[2 * j4],     acc1);
                acc1 = ffma2(make_float2(q1.z, q1.w), va[2 * j4 + 1], acc1);
            }
            tout[(size_t)o * HWPIX]       = acc0.x + acc0.y + b1s[o];
            tout[(size_t)(o + 1) * HWPIX] = acc1.x + acc1.y + b1s[o + 1];
        }
    }
}

// =====================================================================
// K2: modulated depthwise 3x3 + SimpleGate + per-cell channel sums
// grid = 128 CTAs, block = 256
// =====================================================================
__global__ __launch_bounds__(256) void k2_dw_gate(
    const float* __restrict__ w2, const float* __restrict__ b2,
    const float* __restrict__ mod2)
{
    __shared__ float w2s[DW][9];
    __shared__ float b2s[DW];
    __shared__ float ta[34 * 34];
    __shared__ float tg[34 * 34];
    __shared__ float redbuf[8];

    const int cta  = blockIdx.x;
    const int b    = cta >> 6;
    const int cell = cta & 63;
    const int u    = cell >> 3;
    const int v    = cell & 7;
    const int tid  = threadIdx.x;

    if (tid < DW) {
        const int ch = tid;
        const float m = mod2[(size_t)(b * DW + ch) * 64 + cell];
        float ss = 0.f;
        for (int k = 0; k < 9; k++) {
            float wv = w2[ch * 9 + k] * m;
            w2s[ch][k] = wv;
            ss += wv * wv;
        }
        float ri = rsqrtf(ss);
        for (int k = 0; k < 9; k++) w2s[ch][k] *= ri;
        b2s[ch] = b2[ch];
    }
    __syncthreads();

    const int h0 = u * PH - 1, w0 = v * PH - 1;

    for (int c = 0; c < C; c++) {
        // stage the two feature maps (a-channel c, g-channel c+64) with halo
        for (int i = tid; i < 34 * 34; i += 256) {
            const int ih = i / 34, iw = i % 34;
            const int hh = h0 + ih, ww2 = w0 + iw;
            const bool in = (hh >= 0) & (hh < HH) & (ww2 >= 0) & (ww2 < WW);
            const int pix = hh * WW + ww2;
            ta[i] = in ? g_t[(((size_t)(b * DW + c))      << 16) + pix] : 0.f;
            tg[i] = in ? g_t[(((size_t)(b * DW + c + 64)) << 16) + pix] : 0.f;
        }
        __syncthreads();

        float lsum = 0.f;
        for (int k = 0; k < 4; k++) {
            const int p  = k * 256 + tid;
            const int ph = p >> 5, pw = p & 31;
            float a = b2s[c], g = b2s[c + 64];
            #pragma unroll
            for (int dh = 0; dh < 3; dh++) {
                #pragma unroll
                for (int dw2 = 0; dw2 < 3; dw2++) {
                    const int ti = (ph + dh) * 34 + pw + dw2;
                    a += w2s[c][dh * 3 + dw2] * ta[ti];
                    g += w2s[c + 64][dh * 3 + dw2] * tg[ti];
                }
            }
            const float val = a * g;
            const int h = u * PH + ph, w = v * PH + pw;
            g_ymid[(((size_t)(b * C + c)) << 16) + h * WW + w] = val;
            lsum += val;
        }

        // deterministic block reduction of channel sum
        for (int off = 16; off; off >>= 1) lsum += __shfl_down_sync(0xffffffffu, lsum, off);
        if ((tid & 31) == 0) redbuf[tid >> 5] = lsum;
        __syncthreads();
        if (tid == 0) {
            float s = 0.f;
            for (int i = 0; i < 8; i++) s += redbuf[i];
            g_sums[((size_t)b * CELLS + cell) * C + c] = s;
        }
        __syncthreads(); // protect tiles + redbuf for next channel
    }
}

// =====================================================================
// K3: SCA vector  s[b,o] = sum_c sca_w[o,c]*mean[b,c] + sca_b[o]
// grid = 1 CTA, block = 128
// =====================================================================
__global__ void k3_sca(const float* __restrict__ sca_w, const float* __restrict__ sca_b)
{
    __shared__ float meanb[BATCH][C];
    const int t = threadIdx.x;
    const int b = t >> 6, c = t & 63;
    float s = 0.f;
    for (int cell = 0; cell < CELLS; cell++)
        s += g_sums[((size_t)b * CELLS + cell) * C + c];
    meanb[b][c] = s * (1.f / (float)HWPIX);
    __syncthreads();
    float acc = sca_b[c];
    for (int cc = 0; cc < C; cc++)
        acc += sca_w[c * C + cc] * meanb[b][cc];
    g_s[b * C + c] = acc;
}

// =====================================================================
// K4: *s -> conv3 -> y1 = x + beta*.. -> LN2 -> conv4 + gate -> conv5 -> out
// grid = 128 CTAs, block = 256, dynamic smem ~131KB
// =====================================================================
#define K4_SMEM_FLOATS (4096 + 8192 + 4096 + 256 * 65 + 576)
#define K4_SMEM_BYTES  (K4_SMEM_FLOATS * 4)

__global__ __launch_bounds__(256) void k4_second_half(
    const float* __restrict__ x,
    const float* __restrict__ w3, const float* __restrict__ b3,
    const float* __restrict__ w4, const float* __restrict__ b4,
    const float* __restrict__ w5, const float* __restrict__ b5,
    const float* __restrict__ n2w, const float* __restrict__ n2b,
    const float* __restrict__ beta, const float* __restrict__ gamma,
    const float* __restrict__ mod3, const float* __restrict__ mod4,
    const float* __restrict__ mod5,
    float* __restrict__ out)
{
    extern __shared__ float sm[];
    float* w3s   = sm;                 // [64][64]
    float* w4s   = w3s + 4096;         // [128][64]
    float* w5ts  = w4s + 8192;         // [c][o] transposed [64][64]
    float* y1buf = w5ts + 4096;        // [256][65] padded
    float* par   = y1buf + 256 * 65;
    float* ssm    = par;        // 64
    float* b3s    = par + 64;   // 64
    float* b4s    = par + 128;  // 128
    float* b5s    = par + 256;  // 64
    float* n2ws   = par + 320;  // 64
    float* n2bs   = par + 384;  // 64
    float* betas  = par + 448;  // 64
    float* gammas = par + 512;  // 64

    const int cta  = blockIdx.x;
    const int b    = cta >> 6;
    const int cell = cta & 63;
    const int u    = cell >> 3;
    const int v    = cell & 7;
    const int tid  = threadIdx.x;

    // ---- per-cell demodulated weights ----
    if (tid < 64) {
        const int o = tid;
        const float* wr = w3 + o * C;
        const float* mr = mod3 + ((size_t)(b * C + o) * C) * 64 + cell;
        float* dst = w3s + o * C;
        float ss = 0.f;
        for (int c = 0; c < C; c++) {
            float wv = wr[c] * mr[(size_t)c * 64];
            dst[c] = wv; ss += wv * wv;
        }
        float ri = rsqrtf(ss);
        for (int c = 0; c < C; c++) dst[c] *= ri;
    } else if (tid < 192) {
        const int o = tid - 64;
        const float* wr = w4 + o * C;
        const float* mr = mod4 + ((size_t)(b * DW + o) * C) * 64 + cell;
        float* dst = w4s + o * C;
        float ss = 0.f;
        for (int c = 0; c < C; c++) {
            float wv = wr[c] * mr[(size_t)c * 64];
            dst[c] = wv; ss += wv * wv;
        }
        float ri = rsqrtf(ss);
        for (int c = 0; c < C; c++) dst[c] *= ri;
    } else {
        const int o = tid - 192;
        const float* wr = w5 + o * C;
        const float* mr = mod5 + ((size_t)(b * C + o) * C) * 64 + cell;
        float ss = 0.f;
        for (int c = 0; c < C; c++) {
            float wv = wr[c] * mr[(size_t)c * 64];
            w5ts[c * C + o] = wv; ss += wv * wv;
        }
        float ri = rsqrtf(ss);
        for (int c = 0; c < C; c++) w5ts[c * C + o] *= ri;
    }
    if (tid < 64) {
        ssm[tid]    = g_s[b * C + tid];
        b3s[tid]    = b3[tid];
        b5s[tid]    = b5[tid];
        n2ws[tid]   = n2w[tid];
        n2bs[tid]   = n2b[tid];
        betas[tid]  = beta[tid];
        gammas[tid] = gamma[tid];
    }
    if (tid < 128) b4s[tid] = b4[tid];
    __syncthreads();

    const size_t xbase = (size_t)b * C * HWPIX;
    float* y1p = y1buf + tid * 65;

    for (int k = 0; k < 4; k++) {
        const int p  = k * 256 + tid;
        const int ph = p >> 5, pw = p & 31;
        const int h  = u * PH + ph, w = v * PH + pw;
        const int pix = h * WW + w;

        // activation = ymid * s
        float2 va[32];
        #pragma unroll
        for (int j = 0; j < 32; j++) {
            float a0 = g_ymid[xbase + (size_t)(2 * j) * HWPIX + pix]     * ssm[2 * j];
            float a1 = g_ymid[xbase + (size_t)(2 * j + 1) * HWPIX + pix] * ssm[2 * j + 1];
            va[j] = make_float2(a0, a1);
        }

        // conv3 -> y1 (into smem) + LN2 stats
        float sum = 0.f, sumsq = 0.f;
        #pragma unroll 1
        for (int o = 0; o < C; o += 2) {
            float2 acc0 = make_float2(0.f, 0.f), acc1 = make_float2(0.f, 0.f);
            const float4* r0 = reinterpret_cast<const float4*>(w3s + o * C);
            const float4* r1 = reinterpret_cast<const float4*>(w3s + (o + 1) * C);
            #pragma unroll
            for (int j4 = 0; j4 < 16; j4++) {
                float4 q0 = r0[j4], q1 = r1[j4];
                acc0 = ffma2(make_float2(q0.x, q0.y), va[2 * j4],     acc0);
                acc0 = ffma2(make_float2(q0.z, q0.w), va[2 * j4 + 1], acc0);
                acc1 = ffma2(make_float2(q1.x, q1.y), va[2 * j4],     acc1);
                acc1 = ffma2(make_float2(q1.z, q1.w), va[2 * j4 + 1], acc1);
            }
            const float u0 = acc0.x + acc0.y + b3s[o];
            const float u1 = acc1.x + acc1.y + b3s[o + 1];
            const float y10 = x[xbase + (size_t)o * HWPIX + pix]       + u0 * betas[o];
            const float y11 = x[xbase + (size_t)(o + 1) * HWPIX + pix] + u1 * betas[o + 1];
            y1p[o] = y10; y1p[o + 1] = y11;
            sum += y10 + y11;
            sumsq += y10 * y10 + y11 * y11;
        }
        const float mu   = sum * (1.f / 64.f);
        const float rstd = rsqrtf(sumsq * (1.f / 64.f) - mu * mu + 1e-6f);

        // normalized activation for conv4
        #pragma unroll
        for (int j = 0; j < 32; j++) {
            const float y0 = y1p[2 * j], y1v = y1p[2 * j + 1];
            va[j].x = (y0 - mu)  * rstd * n2ws[2 * j]     + n2bs[2 * j];
            va[j].y = (y1v - mu) * rstd * n2ws[2 * j + 1] + n2bs[2 * j + 1];
        }

        // conv4 + gate fused with incremental conv5
        float2 z5[32];
        #pragma unroll
        for (int j = 0; j < 32; j++) z5[j] = make_float2(0.f, 0.f);

        #pragma unroll 1
        for (int c = 0; c < C; c++) {
            float2 aa = make_float2(0.f, 0.f), gg = make_float2(0.f, 0.f);
            const float4* ra = reinterpret_cast<const float4*>(w4s + c * C);
            const float4* rg = reinterpret_cast<const float4*>(w4s + (c + 64) * C);
            #pragma unroll
            for (int j4 = 0; j4 < 16; j4++) {
                float4 qa = ra[j4], qg = rg[j4];
                aa = ffma2(make_float2(qa.x, qa.y), va[2 * j4],     aa);
                aa = ffma2(make_float2(qa.z, qa.w), va[2 * j4 + 1], aa);
                gg = ffma2(make_float2(qg.x, qg.y), va[2 * j4],     gg);
                gg = ffma2(make_float2(qg.z, qg.w), va[2 * j4 + 1], gg);
            }
            const float zc = (aa.x + aa.y + b4s[c]) * (gg.x + gg.y + b4s[c + 64]);
            const float2 zz = make_float2(zc, zc);
            const float4* rw5 = reinterpret_cast<const float4*>(w5ts + c * C);
            #pragma unroll
            for (int j4 = 0; j4 < 16; j4++) {
                float4 q = rw5[j4];
                z5[2 * j4]     = ffma2(make_float2(q.x, q.y), zz, z5[2 * j4]);
                z5[2 * j4 + 1] = ffma2(make_float2(q.z, q.w), zz, z5[2 * j4 + 1]);
            }
        }

        // epilogue: out = y1 + (z5 + b5) * gamma
        float* op = out + xbase + pix;
        #pragma unroll
        for (int j = 0; j < 32; j++) {
            const int o = 2 * j;
            const float o0 = y1p[o]     + (z5[j].x + b5s[o])     * gammas[o];
            const float o1 = y1p[o + 1] + (z5[j].y + b5s[o + 1]) * gammas[o + 1];
            op[(size_t)o * HWPIX]       = o0;
            op[(size_t)(o + 1) * HWPIX] = o1;
        }
    }
}

// =====================================================================
// launch
// =====================================================================
extern "C" void kernel_launch(void* const* d_in, const int* in_sizes, int n_in,
                              void* d_out, int out_size)
{
    (void)in_sizes; (void)n_in; (void)out_size;
    const float* x     = (const float*)d_in[0];
    const float* w1    = (const float*)d_in[1];
    const float* b1    = (const float*)d_in[2];
    const float* w2    = (const float*)d_in[3];
    const float* b2    = (const float*)d_in[4];
    const float* w3    = (const float*)d_in[5];
    const float* b3    = (const float*)d_in[6];
    const float* scaw  = (const float*)d_in[7];
    const float* scab  = (const float*)d_in[8];
    const float* w4    = (const float*)d_in[9];
    const float* b4    = (const float*)d_in[10];
    const float* w5    = (const float*)d_in[11];
    const float* b5    = (const float*)d_in[12];
    const float* n1w   = (const float*)d_in[13];
    const float* n1b   = (const float*)d_in[14];
    const float* n2w   = (const float*)d_in[15];
    const float* n2b   = (const float*)d_in[16];
    const float* beta  = (const float*)d_in[17];
    const float* gamma = (const float*)d_in[18];
    const float* mod1  = (const float*)d_in[19];
    const float* mod2  = (const float*)d_in[20];
    const float* mod3  = (const float*)d_in[21];
    const float* mod4  = (const float*)d_in[22];
    const float* mod5  = (const float*)d_in[23];
    float* out = (float*)d_out;

    cudaFuncSetAttribute(k4_second_half,
                         cudaFuncAttributeMaxDynamicSharedMemorySize, K4_SMEM_BYTES);

    k1_ln_conv1<<<BATCH * CELLS, 256>>>(x, w1, b1, n1w, n1b, mod1);
    k2_dw_gate<<<BATCH * CELLS, 256>>>(w2, b2, mod2);
    k3_sca<<<1, 128>>>(scaw, scab);
    k4_second_half<<<BATCH * CELLS, 256, K4_SMEM_BYTES>>>(
        x, w3, b3, w4, b4, w5, b5, n2w, n2b, beta, gamma,
        mod3, mod4, mod5, out);
}

// round 2
// speedup vs baseline: 1.1234x; 1.1234x over previous
#include <cuda_runtime.h>

// ---------------- problem constants ----------------
#define BATCH 2
#define C 64          // channels in/out
#define DW 128        // hidden width
#define HH 256
#define WW 256
#define HWPIX 65536   // H*W
#define CELLS 64      // per batch
// per-cell demod weight scratch layout
#define W1OFF 0        // 128x64
#define W3OFF 8192     // 64x64
#define W4OFF 12288    // 128x64 (n2w-folded)
#define W5OFF 20480    // 64x64
#define AOFF  24576    // 128
#define BOFF  24704    // 128
#define PERCELL 24832

// ---------------- scratch (device globals: allocation-free launch) ----------------
static __device__ float g_t[(size_t)BATCH * DW * HWPIX];     // conv1 output
static __device__ float g_ymid[(size_t)BATCH * C * HWPIX];   // gated dw output
static __device__ float g_sums[BATCH * CELLS * C];           // per-cell channel sums
static __device__ float g_s[BATCH * C];                      // SCA scale per (b, ch)
static __device__ float g_wd[(size_t)BATCH * CELLS * PERCELL]; // demod weights

// ---------------- packed fp32x2 FMA ----------------
__device__ __forceinline__ float2 ffma2(const float2 a, const float2 b, const float2 c) {
    unsigned long long ra = *reinterpret_cast<const unsigned long long*>(&a);
    unsigned long long rb = *reinterpret_cast<const unsigned long long*>(&b);
    unsigned long long rc = *reinterpret_cast<const unsigned long long*>(&c);
    unsigned long long rd;
    asm("fma.rn.f32x2 %0, %1, %2, %3;" : "=l"(rd) : "l"(ra), "l"(rb), "l"(rc));
    return *reinterpret_cast<float2*>(&rd);
}

// =====================================================================
// K0: demodulate all 1x1 conv weights once per (b, cell, output row).
// grid = 2 * 384 CTAs (one per output row), block = 256.
// Coalesced mod loads (dense 64x64 tiles); w4 gets LN2 affine folded.
// =====================================================================
__global__ __launch_bounds__(256) void k0_demod(
    const float* __restrict__ w1, const float* __restrict__ w3,
    const float* __restrict__ w4, const float* __restrict__ w5,
    const float* __restrict__ b4,
    const float* __restrict__ n2w, const float* __restrict__ n2b,
    const float* __restrict__ mod1, const float* __restrict__ mod3,
    const float* __restrict__ mod4, const float* __restrict__ mod5)
{
    __shared__ float tile[4096];   // [c][cell]
    __shared__ float psA[256];
    __shared__ float psB[256];
    __shared__ float ri[64];

    const int bid = blockIdx.x;
    const int b   = (bid >= 384) ? 1 : 0;
    const int rid = bid - 384 * b;
    const int tid = threadIdx.x;

    const float* wrow; const float* mblk; int dstoff; int isW4 = 0; int o;
    if (rid < 128)      { o = rid;       wrow = w1 + o * 64; mblk = mod1 + ((size_t)(b * 128 + o) << 12); dstoff = W1OFF + o * 64; }
    else if (rid < 192) { o = rid - 128; wrow = w3 + o * 64; mblk = mod3 + ((size_t)(b * 64  + o) << 12); dstoff = W3OFF + o * 64; }
    else if (rid < 320) { o = rid - 192; wrow = w4 + o * 64; mblk = mod4 + ((size_t)(b * 128 + o) << 12); dstoff = W4OFF + o * 64; isW4 = 1; }
    else                { o = rid - 320; wrow = w5 + o * 64; mblk = mod5 + ((size_t)(b * 64  + o) << 12); dstoff = W5OFF + o * 64; }

    for (int i = tid; i < 1024; i += 256)
        reinterpret_cast<float4*>(tile)[i] = reinterpret_cast<const float4*>(mblk)[i];
    __syncthreads();

    const int cell = tid & 63, part = tid >> 6;
    const int c0 = part * 16;
    float wv[16];
    float ss = 0.f;
    #pragma unroll
    for (int j = 0; j < 16; j++) {
        float t = wrow[c0 + j] * tile[(c0 + j) * 64 + cell];
        wv[j] = t; ss += t * t;
    }
    psA[part * 64 + cell] = ss;
    __syncthreads();
    if (tid < 64) ri[tid] = rsqrtf(psA[tid] + psA[64 + tid] + psA[128 + tid] + psA[192 + tid]);
    __syncthreads();
    const float r = ri[cell];
    float* dbase = g_wd + ((size_t)(b * 64 + cell)) * PERCELL + dstoff;

    if (!isW4) {
        #pragma unroll
        for (int j = 0; j < 16; j++) dbase[c0 + j] = wv[j] * r;
    } else {
        float aA = 0.f, bB = 0.f;
        #pragma unroll
        for (int j = 0; j < 16; j++) {
            float wd = wv[j] * r;
            float wn = wd * n2w[c0 + j];
            dbase[c0 + j] = wn;
            aA += wn;
            bB += wd * n2b[c0 + j];
        }
        psA[part * 64 + cell] = aA;
        psB[part * 64 + cell] = bB;
        __syncthreads();
        if (tid < 64) {
            float* cw = g_wd + ((size_t)(b * 64 + tid)) * PERCELL;
            cw[AOFF + o] = psA[tid] + psA[64 + tid] + psA[128 + tid] + psA[192 + tid];
            cw[BOFF + o] = psB[tid] + psB[64 + tid] + psB[128 + tid] + psB[192 + tid] + b4[o];
        }
    }
}

// =====================================================================
// K1: LN1 + conv1x1 (64->128). grid = 512 (quarter cells), 2 CTA/SM.
// =====================================================================
__global__ __launch_bounds__(256, 2) void k1_ln_conv1(
    const float* __restrict__ x, const float* __restrict__ b1,
    const float* __restrict__ n1w, const float* __restrict__ n1b)
{
    __shared__ float w1s[8192];
    __shared__ float b1s[128];
    __shared__ float n1ws[64], n1bs[64];

    const int cta  = blockIdx.x;            // [0,512)
    const int b    = cta >> 8;
    const int cell = (cta >> 2) & 63;
    const int q    = cta & 3;
    const int u    = cell >> 3, v = cell & 7;
    const int tid  = threadIdx.x;

    const float* wsrc = g_wd + ((size_t)(b * 64 + cell)) * PERCELL + W1OFF;
    for (int i = tid; i < 2048; i += 256)
        reinterpret_cast<float4*>(w1s)[i] = reinterpret_cast<const float4*>(wsrc)[i];
    if (tid < 128) b1s[tid] = b1[tid];
    if (tid < 64) { n1ws[tid] = n1w[tid]; n1bs[tid] = n1b[tid]; }
    __syncthreads();

    const int ph = tid >> 5, pw = tid & 31;
    const int h = u * 32 + q * 8 + ph, w = v * 32 + pw;
    const int pix = h * WW + w;
    const size_t xbase = (size_t)b * C * HWPIX;
    const size_t tbase = (size_t)b * DW * HWPIX;

    float2 va[32];
    float sum = 0.f, sumsq = 0.f;
    #pragma unroll
    for (int j = 0; j < 32; j++) {
        float v0 = x[xbase + (size_t)(2 * j) * HWPIX + pix];
        float v1 = x[xbase + (size_t)(2 * j + 1) * HWPIX + pix];
        va[j] = make_float2(v0, v1);
        sum += v0 + v1;
        sumsq += v0 * v0 + v1 * v1;
    }
    const float mu   = sum * (1.f / 64.f);
    const float rstd = rsqrtf(sumsq * (1.f / 64.f) - mu * mu + 1e-6f);
    #pragma unroll
    for (int j = 0; j < 32; j++) {
        va[j].x = (va[j].x - mu) * rstd * n1ws[2 * j]     + n1bs[2 * j];
        va[j].y = (va[j].y - mu) * rstd * n1ws[2 * j + 1] + n1bs[2 * j + 1];
    }

    float* tout = g_t + tbase + pix;
    #pragma unroll 1
    for (int o = 0; o < DW; o += 2) {
        float2 acc0 = make_float2(0.f, 0.f), acc1 = make_float2(0.f, 0.f);
        const float4* r0 = reinterpret_cast<const float4*>(w1s + o * 64);
        const float4* r1 = reinterpret_cast<const float4*>(w1s + (o + 1) * 64);
        #pragma unroll
        for (int j4 = 0; j4 < 16; j4++) {
            float4 q0 = r0[j4], q1 = r1[j4];
            acc0 = ffma2(make_float2(q0.x, q0.y), va[2 * j4],     acc0);
            acc0 = ffma2(make_float2(q0.z, q0.w), va[2 * j4 + 1], acc0);
            acc1 = ffma2(make_float2(q1.x, q1.y), va[2 * j4],     acc1);
            acc1 = ffma2(make_float2(q1.z, q1.w), va[2 * j4 + 1], acc1);
        }
        tout[(size_t)o * HWPIX]       = acc0.x + acc0.y + b1s[o];
        tout[(size_t)(o + 1) * HWPIX] = acc1.x + acc1.y + b1s[o + 1];
    }
}

// =====================================================================
// K2: depthwise 3x3 + SimpleGate + per-cell channel sums.
// grid = 1024 (cell x 8 channel-groups), block = 256, dyn smem 72.25KB.
// =====================================================================
#define K2_SMEMB (16 * 1156 * 4)
__global__ __launch_bounds__(256, 2) void k2_dw_gate(
    const float* __restrict__ w2, const float* __restrict__ b2,
    const float* __restrict__ mod2)
{
    extern __shared__ float tiles[];          // [16][1156]
    __shared__ float w2s[16 * 9];
    __shared__ float b2s[16];
    __shared__ float redbuf[64];

    const int bidx = blockIdx.x;              // [0,1024)
    const int b    = bidx >> 9;
    const int cell = (bidx >> 3) & 63;
    const int grp  = bidx & 7;
    const int u    = cell >> 3, v = cell & 7;
    const int tid  = threadIdx.x;
    const int cbase = grp * 8;

    if (tid < 16) {
        const int ch = (tid < 8) ? (cbase + tid) : (64 + cbase + tid - 8);
        const float m = mod2[(size_t)(b * DW + ch) * 64 + cell];
        float ss = 0.f;
        float wv[9];
        #pragma unroll
        for (int k = 0; k < 9; k++) { wv[k] = w2[ch * 9 + k] * m; ss += wv[k] * wv[k]; }
        const float rr = rsqrtf(ss);
        #pragma unroll
        for (int k = 0; k < 9; k++) w2s[tid * 9 + k] = wv[k] * rr;
        b2s[tid] = b2[ch];
    }

    const int h0 = u * 32 - 1, w0 = v * 32 - 1;
    #pragma unroll 1
    for (int t = 0; t < 16; t++) {
        const int ch = (t < 8) ? (cbase + t) : (64 + cbase + t - 8);
        const float* gp = g_t + (((size_t)(b * DW + ch)) << 16);
        float* tp = tiles + t * 1156;
        for (int i = tid; i < 1156; i += 256) {
            const int ih = i / 34, iw = i - ih * 34;
            const int hh = h0 + ih, ww2 = w0 + iw;
            const bool in = (hh >= 0) & (hh < HH) & (ww2 >= 0) & (ww2 < WW);
            tp[i] = in ? gp[hh * WW + ww2] : 0.f;
        }
    }
    __syncthreads();

    const int lane = tid & 31, warp = tid >> 5;
    #pragma unroll 1
    for (int j = 0; j < 8; j++) {
        const float* tA = tiles + j * 1156;
        const float* tG = tiles + (8 + j) * 1156;
        const float* wA = w2s + j * 9;
        const float* wG = w2s + (8 + j) * 9;
        const size_t obase = ((size_t)(b * 64 + cbase + j)) << 16;
        float ls = 0.f;
        #pragma unroll
        for (int k = 0; k < 4; k++) {
            const int p = k * 256 + tid;
            const int ph = p >> 5, pw = p & 31;
            float a = b2s[j], g = b2s[8 + j];
            #pragma unroll
            for (int dh = 0; dh < 3; dh++) {
                #pragma unroll
                for (int dw2 = 0; dw2 < 3; dw2++) {
                    const int ti = (ph + dh) * 34 + pw + dw2;
                    a += wA[dh * 3 + dw2] * tA[ti];
                    g += wG[dh * 3 + dw2] * tG[ti];
                }
            }
            const float val = a * g;
            g_ymid[obase + (u * 32 + ph) * WW + (v * 32 + pw)] = val;
            ls += val;
        }
        for (int off = 16; off; off >>= 1) ls += __shfl_down_sync(0xffffffffu, ls, off);
        if (lane == 0) redbuf[j * 8 + warp] = ls;
    }
    __syncthreads();
    if (tid < 8) {
        float s = 0.f;
        #pragma unroll
        for (int i = 0; i < 8; i++) s += redbuf[tid * 8 + i];
        g_sums[((size_t)b * CELLS + cell) * C + cbase + tid] = s;
    }
}

// =====================================================================
// K3: SCA vector
// =====================================================================
__global__ void k3_sca(const float* __restrict__ sca_w, const float* __restrict__ sca_b)
{
    __shared__ float meanb[BATCH][C];
    const int t = threadIdx.x;
    const int b = t >> 6, c = t & 63;
    float s = 0.f;
    for (int cell = 0; cell < CELLS; cell++)
        s += g_sums[((size_t)b * CELLS + cell) * C + c];
    meanb[b][c] = s * (1.f / (float)HWPIX);
    __syncthreads();
    float acc = sca_b[c];
    for (int cc = 0; cc < C; cc++)
        acc += sca_w[c * C + cc] * meanb[b][cc];
    g_s[b * C + c] = acc;
}

// =====================================================================
// K4: *s -> conv3 -> y1 -> (folded LN2) conv4+gate -> conv5 -> out
// grid = 512 (quarter cells), block = 256, 2 CTA/SM, dyn smem ~102KB.
// Phased smem: wbuf reused w3 -> w4n -> w5; zc buf reused y1 -> zc.
// =====================================================================
#define K4_SMEMF (8192 + 256 * 68 + 576)
#define K4_SMEMB (K4_SMEMF * 4)

__global__ __launch_bounds__(256, 2) void k4_second_half(
    const float* __restrict__ x,
    const float* __restrict__ b3, const float* __restrict__ b5,
    const float* __restrict__ beta, const float* __restrict__ gamma,
    float* __restrict__ out)
{
    extern __shared__ float sm[];
    float* wbuf = sm;                    // 8192 floats (reused per phase)
    float* zcb  = sm + 8192;             // 256 x 68
    float* par  = sm + 8192 + 256 * 68;
    float* ssm    = par;                 // 64
    float* b3s    = par + 64;
    float* betas  = par + 128;
    float* b5s    = par + 192;
    float* gammas = par + 256;
    float* As     = par + 320;           // 128
    float* Bbs    = par + 448;           // 128

    const int cta  = blockIdx.x;         // [0,512)
    const int b    = cta >> 8;
    const int cell = (cta >> 2) & 63;
    const int q    = cta & 3;
    const int u    = cell >> 3, v = cell & 7;
    const int tid  = threadIdx.x;

    const float* cellw = g_wd + ((size_t)(b * 64 + cell)) * PERCELL;

    // P0: w3 + params
    for (int i = tid; i < 1024; i += 256)
        reinterpret_cast<float4*>(wbuf)[i] = reinterpret_cast<const float4*>(cellw + W3OFF)[i];
    if (tid < 64) {
        ssm[tid]    = g_s[b * C + tid];
        b3s[tid]    = b3[tid];
        betas[tid]  = beta[tid];
        b5s[tid]    = b5[tid];
        gammas[tid] = gamma[tid];
    }
    if (tid < 128) { As[tid] = cellw[AOFF + tid]; Bbs[tid] = cellw[BOFF + tid]; }
    __syncthreads();

    const int ph = tid >> 5, pw = tid & 31;
    const int h = u * 32 + q * 8 + ph, w = v * 32 + pw;
    const int pix = h * WW + w;
    const size_t xbase = (size_t)b * C * HWPIX;
    float* zrow = zcb + tid * 68;

    // P1: act = ymid * s ; conv3 ; y1 = x + (.)*beta -> zcb + LN2 stats
    float2 va[32];
    #pragma unroll
    for (int j = 0; j < 32; j++) {
        float a0 = g_ymid[xbase + (size_t)(2 * j) * HWPIX + pix]     * ssm[2 * j];
        float a1 = g_ymid[xbase + (size_t)(2 * j + 1) * HWPIX + pix] * ssm[2 * j + 1];
        va[j] = make_float2(a0, a1);
    }
    float sum = 0.f, sumsq = 0.f;
    #pragma unroll 1
    for (int o = 0; o < 64; o += 2) {
        float2 acc0 = make_float2(0.f, 0.f), acc1 = make_float2(0.f, 0.f);
        const float4* r0 = reinterpret_cast<const float4*>(wbuf + o * 64);
        const float4* r1 = reinterpret_cast<const float4*>(wbuf + (o + 1) * 64);
        #pragma unroll
        for (int j4 = 0; j4 < 16; j4++) {
            float4 q0 = r0[j4], q1 = r1[j4];
            acc0 = ffma2(make_float2(q0.x, q0.y), va[2 * j4],     acc0);
            acc0 = ffma2(make_float2(q0.z, q0.w), va[2 * j4 + 1], acc0);
            acc1 = ffma2(make_float2(q1.x, q1.y), va[2 * j4],     acc1);
            acc1 = ffma2(make_float2(q1.z, q1.w), va[2 * j4 + 1], acc1);
        }
        const float y10 = x[xbase + (size_t)o * HWPIX + pix]       + (acc0.x + acc0.y + b3s[o])     * betas[o];
        const float y11 = x[xbase + (size_t)(o + 1) * HWPIX + pix] + (acc1.x + acc1.y + b3s[o + 1]) * betas[o + 1];
        zrow[o] = y10; zrow[o + 1] = y11;
        sum += y10 + y11;
        sumsq += y10 * y10 + y11 * y11;
    }
    const float mu   = sum * (1.f / 64.f);
    const float rstd = rsqrtf(sumsq * (1.f / 64.f) - mu * mu + 1e-6f);

    __syncthreads();   // done reading w3
    // P2: load w4n (folded LN2 affine)
    for (int i = tid; i < 2048; i += 256)
        reinterpret_cast<float4*>(wbuf)[i] = reinterpret_cast<const float4*>(cellw + W4OFF)[i];
    // reload raw y1 into registers (kept through conv4/conv5 for the epilogue)
    #pragma unroll
    for (int j4 = 0; j4 < 16; j4++) {
        float4 qy = reinterpret_cast<const float4*>(zrow)[j4];
        va[2 * j4]     = make_float2(qy.x, qy.y);
        va[2 * j4 + 1] = make_float2(qy.z, qy.w);
    }
    __syncthreads();

    // P3: conv4 + gate (LN folded: dot = rstd*(dotn - mu*A) + Bb), zc -> zcb
    #pragma unroll 1
    for (int c = 0; c < 64; c++) {
        float2 a2 = make_float2(0.f, 0.f), g2 = make_float2(0.f, 0.f);
        const float4* ra = reinterpret_cast<const float4*>(wbuf + c * 64);
        const float4* rg = reinterpret_cast<const float4*>(wbuf + (c + 64) * 64);
        #pragma unroll
        for (int j4 = 0; j4 < 16; j4++) {
            float4 qa = ra[j4], qg = rg[j4];
            a2 = ffma2(make_float2(qa.x, qa.y), va[2 * j4],     a2);
            a2 = ffma2(make_float2(qa.z, qa.w), va[2 * j4 + 1], a2);
            g2 = ffma2(make_float2(qg.x, qg.y), va[2 * j4],     g2);
            g2 = ffma2(make_float2(qg.z, qg.w), va[2 * j4 + 1], g2);
        }
        const float za = rstd * ((a2.x + a2.y) - mu * As[c])      + Bbs[c];
        const float zg = rstd * ((g2.x + g2.y) - mu * As[c + 64]) + Bbs[c + 64];
        zrow[c] = za * zg;
    }
    __syncthreads();   // done reading w4n
    // P4: load w5
    for (int i = tid; i < 1024; i += 256)
        reinterpret_cast<float4*>(wbuf)[i] = reinterpret_cast<const float4*>(cellw + W5OFF)[i];
    __syncthreads();

    // P5: conv5 + epilogue (y1 still in va)
    const float4* zp4 = reinterpret_cast<const float4*>(zrow);
    float* op = out + xbase + pix;
    #pragma unroll 1
    for (int o = 0; o < 64; o += 2) {
        float2 acc0 = make_float2(0.f, 0.f), acc1 = make_float2(0.f, 0.f);
        const float4* r0 = reinterpret_cast<const float4*>(wbuf + o * 64);
        const float4* r1 = reinterpret_cast<const float4*>(wbuf + (o + 1) * 64);
        #pragma unroll
        for (int j4 = 0; j4 < 16; j4++) {
            float4 z4 = zp4[j4];
            float2 z01 = make_float2(z4.x, z4.y), z23 = make_float2(z4.z, z4.w);
            float4 q0 = r0[j4], q1 = r1[j4];
            acc0 = ffma2(make_float2(q0.x, q0.y), z01, acc0);
            acc0 = ffma2(make_float2(q0.z, q0.w), z23, acc0);
            acc1 = ffma2(make_float2(q1.x, q1.y), z01, acc1);
            acc1 = ffma2(make_float2(q1.z, q1.w), z23, acc1);
        }
        const float2 y1p = va[o >> 1];
        op[(size_t)o * HWPIX]       = y1p.x + (acc0.x + acc0.y + b5s[o])     * gammas[o];
        op[(size_t)(o + 1) * HWPIX] = y1p.y + (acc1.x + acc1.y + b5s[o + 1]) * gammas[o + 1];
    }
}

// =====================================================================
// launch
// =====================================================================
extern "C" void kernel_launch(void* const* d_in, const int* in_sizes, int n_in,
                              void* d_out, int out_size)
{
    (void)in_sizes; (void)n_in; (void)out_size;
    const float* x     = (const float*)d_in[0];
    const float* w1    = (const float*)d_in[1];
    const float* b1    = (const float*)d_in[2];
    const float* w2    = (const float*)d_in[3];
    const float* b2    = (const float*)d_in[4];
    const float* w3    = (const float*)d_in[5];
    const float* b3    = (const float*)d_in[6];
    const float* scaw  = (const float*)d_in[7];
    const float* scab  = (const float*)d_in[8];
    const float* w4    = (const float*)d_in[9];
    const float* b4    = (const float*)d_in[10];
    const float* w5    = (const float*)d_in[11];
    const float* b5    = (const float*)d_in[12];
    const float* n1w   = (const float*)d_in[13];
    const float* n1b   = (const float*)d_in[14];
    const float* n2w   = (const float*)d_in[15];
    const float* n2b   = (const float*)d_in[16];
    const float* beta  = (const float*)d_in[17];
    const float* gamma = (const float*)d_in[18];
    const float* mod1  = (const float*)d_in[19];
    const float* mod2  = (const float*)d_in[20];
    const float* mod3  = (const float*)d_in[21];
    const float* mod4  = (const float*)d_in[22];
    const float* mod5  = (const float*)d_in[23];
    float* out = (float*)d_out;

    cudaFuncSetAttribute(k2_dw_gate, cudaFuncAttributeMaxDynamicSharedMemorySize, K2_SMEMB);
    cudaFuncSetAttribute(k4_second_half, cudaFuncAttributeMaxDynamicSharedMemorySize, K4_SMEMB);

    k0_demod<<<2 * 384, 256>>>(w1, w3, w4, w5, b4, n2w, n2b, mod1, mod3, mod4, mod5);
    k1_ln_conv1<<<512, 256>>>(x, b1, n1w, n1b);
    k2_dw_gate<<<1024, 256, K2_SMEMB>>>(w2, b2, mod2);
    k3_sca<<<1, 128>>>(scaw, scab);
    k4_second_half<<<512, 256, K4_SMEMB>>>(x, b3, b5, beta, gamma, out);
}

// round 4
// speedup vs baseline: 1.3308x; 1.1847x over previous
#include <cuda_runtime.h>
#include <cstdint>

// ---------------- problem constants ----------------
#define BATCH 2
#define C 64
#define DW 128
#define HH 256
#define WW 256
#define HWPIX 65536
#define CELLS 64
// per-cell demod weight scratch layout
#define W1OFF 0        // 128x64
#define W3OFF 8192     // 64x64
#define W4OFF 12288    // 128x64 (n2w-folded)
#define W5OFF 20480    // 64x64
#define AOFF  24576    // 128
#define BOFF  24704    // 128
#define PERCELL 24832

// ---------------- scratch ----------------
static __device__ float g_t[(size_t)BATCH * DW * HWPIX];
static __device__ float g_ymid[(size_t)BATCH * C * HWPIX];
static __device__ float g_sums[BATCH * CELLS * C];
static __device__ float g_s[BATCH * C];
static __device__ float g_wd[(size_t)BATCH * CELLS * PERCELL];

// ---------------- helpers ----------------
// pair-permutation within each 8-channel block: k<4 -> 2k ; k>=4 -> 2(k-4)+1
__device__ __forceinline__ int pp8(int c) {
    int k = c & 7;
    return (c & ~7) + ((k < 4) ? (k << 1) : (((k - 4) << 1) | 1));
}
__device__ __forceinline__ uint32_t tf32r(float f) {
    uint32_t r;
    asm("cvt.rna.tf32.f32 %0, %1;" : "=r"(r) : "f"(f));
    return r;
}
__device__ __forceinline__ void mma_tf32(float& d0, float& d1, float& d2, float& d3,
                                         uint32_t a0, uint32_t a1, uint32_t a2, uint32_t a3,
                                         uint32_t b0, uint32_t b1) {
    asm volatile(
        "mma.sync.aligned.m16n8k8.row.col.f32.tf32.tf32.f32 "
        "{%0,%1,%2,%3},{%4,%5,%6,%7},{%8,%9},{%0,%1,%2,%3};"
        : "+f"(d0), "+f"(d1), "+f"(d2), "+f"(d3)
        : "r"(a0), "r"(a1), "r"(a2), "r"(a3), "r"(b0), "r"(b1));
}

// =====================================================================
// K0: demodulate all 1x1 conv weights once per (b, cell, output row).
// =====================================================================
__global__ __launch_bounds__(256) void k0_demod(
    const float* __restrict__ w1, const float* __restrict__ w3,
    const float* __restrict__ w4, const float* __restrict__ w5,
    const float* __restrict__ b4,
    const float* __restrict__ n2w, const float* __restrict__ n2b,
    const float* __restrict__ mod1, const float* __restrict__ mod3,
    const float* __restrict__ mod4, const float* __restrict__ mod5)
{
    __shared__ float tile[4096];
    __shared__ float psA[256];
    __shared__ float psB[256];
    __shared__ float ri[64];

    const int bid = blockIdx.x;
    const int b   = (bid >= 384) ? 1 : 0;
    const int rid = bid - 384 * b;
    const int tid = threadIdx.x;

    const float* wrow; const float* mblk; int dstoff; int isW4 = 0; int o;
    if (rid < 128)      { o = rid;       wrow = w1 + o * 64; mblk = mod1 + ((size_t)(b * 128 + o) << 12); dstoff = W1OFF + o * 64; }
    else if (rid < 192) { o = rid - 128; wrow = w3 + o * 64; mblk = mod3 + ((size_t)(b * 64  + o) << 12); dstoff = W3OFF + o * 64; }
    else if (rid < 320) { o = rid - 192; wrow = w4 + o * 64; mblk = mod4 + ((size_t)(b * 128 + o) << 12); dstoff = W4OFF + o * 64; isW4 = 1; }
    else                { o = rid - 320; wrow = w5 + o * 64; mblk = mod5 + ((size_t)(b * 64  + o) << 12); dstoff = W5OFF + o * 64; }

    for (int i = tid; i < 1024; i += 256)
        reinterpret_cast<float4*>(tile)[i] = reinterpret_cast<const float4*>(mblk)[i];
    __syncthreads();

    const int cell = tid & 63, part = tid >> 6;
    const int c0 = part * 16;
    float wv[16];
    float ss = 0.f;
    #pragma unroll
    for (int j = 0; j < 16; j++) {
        float t = wrow[c0 + j] * tile[(c0 + j) * 64 + cell];
        wv[j] = t; ss += t * t;
    }
    psA[part * 64 + cell] = ss;
    __syncthreads();
    if (tid < 64) ri[tid] = rsqrtf(psA[tid] + psA[64 + tid] + psA[128 + tid] + psA[192 + tid]);
    __syncthreads();
    const float r = ri[cell];
    float* dbase = g_wd + ((size_t)(b * 64 + cell)) * PERCELL + dstoff;

    if (!isW4) {
        #pragma unroll
        for (int j = 0; j < 16; j++) dbase[c0 + j] = wv[j] * r;
    } else {
        float aA = 0.f, bB = 0.f;
        #pragma unroll
        for (int j = 0; j < 16; j++) {
            float wd = wv[j] * r;
            float wn = wd * n2w[c0 + j];
            dbase[c0 + j] = wn;
            aA += wn;
            bB += wd * n2b[c0 + j];
        }
        psA[part * 64 + cell] = aA;
        psB[part * 64 + cell] = bB;
        __syncthreads();
        if (tid < 64) {
            float* cw = g_wd + ((size_t)(b * 64 + tid)) * PERCELL;
            cw[AOFF + o] = psA[tid] + psA[64 + tid] + psA[128 + tid] + psA[192 + tid];
            cw[BOFF + o] = psB[tid] + psB[64 + tid] + psB[128 + tid] + psB[192 + tid] + b4[o];
        }
    }
}

// =====================================================================
// K1 (mma.sync tf32): LN1 + conv1x1 (64->128) per cell.
// grid=128 (one cell), block=512 (16 warps x 16 pixel rows), 4 tiles of 256 pix.
// =====================================================================
#define K1_AS   0                        // 256*72
#define K1_WS   (256*72)                 // 128*72
#define K1_DS   (256*72 + 128*72)        // 256*65
#define K1_B1   (K1_DS + 256*65)         // 128
#define K1_N1W  (K1_B1 + 128)            // 64 (pair-permuted)
#define K1_N1B  (K1_N1W + 64)            // 64
#define K1_SMEMF (K1_N1B + 64)
#define K1_SMEMB (K1_SMEMF * 4)

__global__ __launch_bounds__(512) void k1_tc(
    const float* __restrict__ x, const float* __restrict__ b1,
    const float* __restrict__ n1w, const float* __restrict__ n1b)
{
    extern __shared__ float sm[];
    float* As   = sm + K1_AS;
    float* Ws   = sm + K1_WS;
    float* Ds   = sm + K1_DS;
    float* b1s  = sm + K1_B1;
    float* n1wp = sm + K1_N1W;
    float* n1bp = sm + K1_N1B;

    const int tid = threadIdx.x;
    const int wid = tid >> 5, lane = tid & 31;
    const int g = lane >> 2, tig = lane & 3;
    const int cta = blockIdx.x;
    const int b = cta >> 6, cell = cta & 63;
    const int u = cell >> 3, v = cell & 7;

    // stage demod W1 (tf32, pair layout)
    const float* cellw = g_wd + ((size_t)(b * 64 + cell)) * PERCELL;
    for (int i = tid; i < 8192; i += 512) {
        int o = i >> 6, c = i & 63;
        Ws[o * 72 + pp8(c)] = __uint_as_float(tf32r(cellw[W1OFF + i]));
    }
    if (tid < 128) b1s[tid] = b1[tid];
    if (tid < 64) { n1wp[pp8(tid)] = n1w[tid]; n1bp[pp8(tid)] = n1b[tid]; }
    __syncthreads();

    const size_t xbase = (size_t)b * C * HWPIX;
    const size_t tbase = (size_t)b * DW * HWPIX;
    const int w16 = wid * 16;

    #pragma unroll 1
    for (int t = 0; t < 4; t++) {
        const int pix0 = (u * 32 + t * 8) * WW + v * 32;

        // load x tile -> As (raw f32, pair layout)
        for (int i = tid; i < 16384; i += 512) {
            int p = i & 255, ch = i >> 8;
            int gp = pix0 + ((p >> 5) << 8) + (p & 31);
            As[p * 72 + pp8(ch)] = x[xbase + (size_t)ch * HWPIX + gp];
        }
        __syncthreads();

        // LN per pixel (threads 0..255), write back normalized tf32
        if (tid < 256) {
            float* row = As + tid * 72;
            float s = 0.f, sq = 0.f;
            #pragma unroll
            for (int q = 0; q < 32; q++) {
                float2 p2 = reinterpret_cast<const float2*>(row)[q];
                s += p2.x + p2.y; sq += p2.x * p2.x + p2.y * p2.y;
            }
            const float mu = s * (1.f / 64.f);
            const float rstd = rsqrtf(sq * (1.f / 64.f) - mu * mu + 1e-6f);
            #pragma unroll
            for (int q = 0; q < 64; q++)
                row[q] = __uint_as_float(tf32r((row[q] - mu) * rstd * n1wp[q] + n1bp[q]));
        }
        __syncthreads();

        // GEMM: 16 pix x 128 out per warp
        float acc[64];
        #pragma unroll
        for (int i = 0; i < 64; i++) acc[i] = 0.f;
        const float* aR0 = As + (w16 + g) * 72 + tig * 2;
        const float* aR1 = aR0 + 8 * 72;
        #pragma unroll
        for (int kt = 0; kt < 8; kt++) {
            uint2 a02 = *reinterpret_cast<const uint2*>(aR0 + kt * 8);
            uint2 a13 = *reinterpret_cast<const uint2*>(aR1 + kt * 8);
            #pragma unroll
            for (int nt = 0; nt < 16; nt++) {
                uint2 bb = *reinterpret_cast<const uint2*>(Ws + (nt * 8 + g) * 72 + kt * 8 + tig * 2);
                mma_tf32(acc[nt * 4], acc[nt * 4 + 1], acc[nt * 4 + 2], acc[nt * 4 + 3],
                         a02.x, a13.x, a02.y, a13.y, bb.x, bb.y);
            }
        }
        __syncthreads();   // As reads done (Ds overlaps nothing; needed before next tile As reuse anyway)

        // epilogue via Ds staging, 2 halves of 64 out-channels
        #pragma unroll 1
        for (int half = 0; half < 2; half++) {
            #pragma unroll
            for (int ntl = 0; ntl < 8; ntl++) {
                int nt = half * 8 + ntl;
                int c0 = ntl * 8 + 2 * tig;
                float* d0 = Ds + (w16 + g) * 65 + c0;
                d0[0] = acc[nt * 4];     d0[1] = acc[nt * 4 + 1];
                float* d1 = Ds + (w16 + g + 8) * 65 + c0;
                d1[0] = acc[nt * 4 + 2]; d1[1] = acc[nt * 4 + 3];
            }
            __syncthreads();
            for (int i = tid; i < 16384; i += 512) {
                int p = i & 255, ch = i >> 8;
                int gp = pix0 + ((p >> 5) << 8) + (p & 31);
                g_t[tbase + (size_t)(half * 64 + ch) * HWPIX + gp] = Ds[p * 65 + ch] + b1s[half * 64 + ch];
            }
            __syncthreads();
        }
    }
}

// =====================================================================
// K2: depthwise 3x3 + SimpleGate + per-cell channel sums. (unchanged)
// =====================================================================
#define K2_SMEMB (16 * 1156 * 4)
__global__ __launch_bounds__(256, 2) void k2_dw_gate(
    const float* __restrict__ w2, const float* __restrict__ b2,
    const float* __restrict__ mod2)
{
    extern __shared__ float tiles[];
    __shared__ float w2s[16 * 9];
    __shared__ float b2s[16];
    __shared__ float redbuf[64];

    const int bidx = blockIdx.x;
    const int b    = bidx >> 9;
    const int cell = (bidx >> 3) & 63;
    const int grp  = bidx & 7;
    const int u    = cell >> 3, v = cell & 7;
    const int tid  = threadIdx.x;
    const int cbase = grp * 8;

    if (tid < 16) {
        const int ch = (tid < 8) ? (cbase + tid) : (64 + cbase + tid - 8);
        const float m = mod2[(size_t)(b * DW + ch) * 64 + cell];
        float ss = 0.f;
        float wv[9];
        #pragma unroll
        for (int k = 0; k < 9; k++) { wv[k] = w2[ch * 9 + k] * m; ss += wv[k] * wv[k]; }
        const float rr = rsqrtf(ss);
        #pragma unroll
        for (int k = 0; k < 9; k++) w2s[tid * 9 + k] = wv[k] * rr;
        b2s[tid] = b2[ch];
    }

    const int h0 = u * 32 - 1, w0 = v * 32 - 1;
    #pragma unroll 1
    for (int t = 0; t < 16; t++) {
        const int ch = (t < 8) ? (cbase + t) : (64 + cbase + t - 8);
        const float* gp = g_t + (((size_t)(b * DW + ch)) << 16);
        float* tp = tiles + t * 1156;
        for (int i = tid; i < 1156; i += 256) {
            const int ih = i / 34, iw = i - ih * 34;
            const int hh = h0 + ih, ww2 = w0 + iw;
            const bool in = (hh >= 0) & (hh < HH) & (ww2 >= 0) & (ww2 < WW);
            tp[i] = in ? gp[hh * WW + ww2] : 0.f;
        }
    }
    __syncthreads();

    const int lane = tid & 31, warp = tid >> 5;
    #pragma unroll 1
    for (int j = 0; j < 8; j++) {
        const float* tA = tiles + j * 1156;
        const float* tG = tiles + (8 + j) * 1156;
        const float* wA = w2s + j * 9;
        const float* wG = w2s + (8 + j) * 9;
        const size_t obase = ((size_t)(b * 64 + cbase + j)) << 16;
        float ls = 0.f;
        #pragma unroll
        for (int k = 0; k < 4; k++) {
            const int p = k * 256 + tid;
            const int ph = p >> 5, pw = p & 31;
            float a = b2s[j], g = b2s[8 + j];
            #pragma unroll
            for (int dh = 0; dh < 3; dh++) {
                #pragma unroll
                for (int dw2 = 0; dw2 < 3; dw2++) {
                    const int ti = (ph + dh) * 34 + pw + dw2;
                    a += wA[dh * 3 + dw2] * tA[ti];
                    g += wG[dh * 3 + dw2] * tG[ti];
                }
            }
            const float val = a * g;
            g_ymid[obase + (u * 32 + ph) * WW + (v * 32 + pw)] = val;
            ls += val;
        }
        for (int off = 16; off; off >>= 1) ls += __shfl_down_sync(0xffffffffu, ls, off);
        if (lane == 0) redbuf[j * 8 + warp] = ls;
    }
    __syncthreads();
    if (tid < 8) {
        float s = 0.f;
        #pragma unroll
        for (int i = 0; i < 8; i++) s += redbuf[tid * 8 + i];
        g_sums[((size_t)b * CELLS + cell) * C + cbase + tid] = s;
    }
}

// =====================================================================
// K3: SCA vector
// =====================================================================
__global__ void k3_sca(const float* __restrict__ sca_w, const float* __restrict__ sca_b)
{
    __shared__ float part[256];
    __shared__ float meanv[64];
    const int b = blockIdx.x;
    const int tid = threadIdx.x;
    const int c = tid & 63, seg = tid >> 6;
    float s = 0.f;
    #pragma unroll 4
    for (int cell = seg * 16; cell < seg * 16 + 16; cell++)
        s += g_sums[((size_t)b * CELLS + cell) * C + c];
    part[tid] = s;
    __syncthreads();
    if (tid < 64)
        meanv[tid] = (part[tid] + part[64 + tid] + part[128 + tid] + part[192 + tid]) * (1.f / (float)HWPIX);
    __syncthreads();
    if (tid < 64) {
        float acc = sca_b[tid];
        #pragma unroll 8
        for (int cc = 0; cc < 64; cc++) acc += sca_w[tid * 64 + cc] * meanv[cc];
        g_s[b * C + tid] = acc;
    }
}

// =====================================================================
// K4 (mma.sync tf32): *s -> conv3 -> y1 -> folded-LN2 conv4+gate -> conv5 -> out
// grid=128 (one cell), block=512, 4 tiles of 256 pixels.
// =====================================================================
#define K4_AS   0                          // 256*72 (act -> zc)
#define K4_YS   (256*72)                   // 256*72 (x -> y1 -> out)
#define K4_W3   (2*256*72)                 // 64*72
#define K4_W4   (K4_W3 + 64*72)            // 128*72
#define K4_W5   (K4_W4 + 128*72)           // 64*72
#define K4_MU   (K4_W5 + 64*72)            // 256
#define K4_RS   (K4_MU + 256)              // 256
#define K4_SSM  (K4_RS + 256)              // 64
#define K4_B3   (K4_SSM + 64)              // 64
#define K4_BE   (K4_B3 + 64)               // 64
#define K4_B5   (K4_BE + 64)               // 64
#define K4_GA   (K4_B5 + 64)               // 64
#define K4_AW   (K4_GA + 64)               // 128
#define K4_BW   (K4_AW + 128)              // 128
#define K4_SMEMF (K4_BW + 128)
#define K4_SMEMB (K4_SMEMF * 4)

__global__ __launch_bounds__(512) void k4_tc(
    const float* __restrict__ x,
    const float* __restrict__ b3, const float* __restrict__ b5,
    const float* __restrict__ beta, const float* __restrict__ gamma,
    float* __restrict__ out)
{
    extern __shared__ float sm[];
    float* As  = sm + K4_AS;
    float* Ys  = sm + K4_YS;
    float* w3s = sm + K4_W3;
    float* w4s = sm + K4_W4;
    float* w5s = sm + K4_W5;
    float* muA = sm + K4_MU;
    float* rsA = sm + K4_RS;
    float* ssm = sm + K4_SSM;
    float* b3s = sm + K4_B3;
    float* bes = sm + K4_BE;
    float* b5s = sm + K4_B5;
    float* gas = sm + K4_GA;
    float* Aw  = sm + K4_AW;
    float* Bw  = sm + K4_BW;

    const int tid = threadIdx.x;
    const int wid = tid >> 5, lane = tid & 31;
    const int g = lane >> 2, tig = lane & 3;
    const int cta = blockIdx.x;
    const int b = cta >> 6, cell = cta & 63;
    const int u = cell >> 3, v = cell & 7;

    const float* cellw = g_wd + ((size_t)(b * 64 + cell)) * PERCELL;
    // stage weights (tf32, pair layout)
    for (int i = tid; i < 4096; i += 512) {
        int o = i >> 6, c = i & 63;
        w3s[o * 72 + pp8(c)] = __uint_as_float(tf32r(cellw[W3OFF + i]));
        w5s[o * 72 + pp8(c)] = __uint_as_float(tf32r(cellw[W5OFF + i]));
    }
    for (int i = tid; i < 8192; i += 512) {
        int o = i >> 6, c = i & 63;
        w4s[o * 72 + pp8(c)] = __uint_as_float(tf32r(cellw[W4OFF + i]));
    }
    if (tid < 64) {
        ssm[tid] = g_s[b * C + tid];
        b3s[tid] = b3[tid];
        bes[tid] = beta[tid];
        b5s[tid] = b5[tid];
        gas[tid] = gamma[tid];
    }
    if (tid < 128) { Aw[tid] = cellw[AOFF + tid]; Bw[tid] = cellw[BOFF + tid]; }
    __syncthreads();

    const size_t xbase = (size_t)b * C * HWPIX;
    const int w16 = wid * 16;

    #pragma unroll 1
    for (int t = 0; t < 4; t++) {
        const int pix0 = (u * 32 + t * 8) * WW + v * 32;

        // load act = ymid*s (tf32) and x (raw)
        for (int i = tid; i < 16384; i += 512) {
            int p = i & 255, ch = i >> 8;
            int gp = pix0 + ((p >> 5) << 8) + (p & 31);
            int sl = p * 72 + pp8(ch);
            As[sl] = __uint_as_float(tf32r(g_ymid[xbase + (size_t)ch * HWPIX + gp] * ssm[ch]));
            Ys[sl] = x[xbase + (size_t)ch * HWPIX + gp];
        }
        __syncthreads();

        const float* aR0 = As + (w16 + g) * 72 + tig * 2;
        const float* aR1 = aR0 + 8 * 72;
        const float* yR0 = Ys + (w16 + g) * 72 + tig * 2;
        const float* yR1 = yR0 + 8 * 72;

        // ---- GEMM1: conv3 (N=64) ----
        {
            float acc[32];
            #pragma unroll
            for (int i = 0; i < 32; i++) acc[i] = 0.f;
            #pragma unroll
            for (int kt = 0; kt < 8; kt++) {
                uint2 a02 = *reinterpret_cast<const uint2*>(aR0 + kt * 8);
                uint2 a13 = *reinterpret_cast<const uint2*>(aR1 + kt * 8);
                #pragma unroll
                for (int nt = 0; nt < 8; nt++) {
                    uint2 bb = *reinterpret_cast<const uint2*>(w3s + (nt * 8 + g) * 72 + kt * 8 + tig * 2);
                    mma_tf32(acc[nt * 4], acc[nt * 4 + 1], acc[nt * 4 + 2], acc[nt * 4 + 3],
                             a02.x, a13.x, a02.y, a13.y, bb.x, bb.y);
                }
            }
            // epilogue: y1 = x + (dot + b3)*beta, stored into Ys
            #pragma unroll
            for (int nt = 0; nt < 8; nt++) {
                #pragma unroll
                for (int j = 0; j < 2; j++) {
                    int c = nt * 8 + 2 * tig + j;
                    int q = pp8(c);
                    float* y0 = Ys + (w16 + g) * 72 + q;
                    float* y1 = Ys + (w16 + g + 8) * 72 + q;
                    *y0 = *y0 + (acc[nt * 4 + j]     + b3s[c]) * bes[c];
                    *y1 = *y1 + (acc[nt * 4 + 2 + j] + b3s[c]) * bes[c];
                }
            }
        }
        __syncthreads();

        // ---- LN2 stats per pixel ----
        if (tid < 256) {
            const float* row = Ys + tid * 72;
            float s = 0.f, sq = 0.f;
            #pragma unroll
            for (int q = 0; q < 32; q++) {
                float2 p2 = reinterpret_cast<const float2*>(row)[q];
                s += p2.x + p2.y; sq += p2.x * p2.x + p2.y * p2.y;
            }
            const float mu = s * (1.f / 64.f);
            muA[tid] = mu;
            rsA[tid] = rsqrtf(sq * (1.f / 64.f) - mu * mu + 1e-6f);
        }
        __syncthreads();

        // ---- GEMM2: conv4 (N=128, LN folded) + gate -> As (zc, tf32) ----
        {
            float acc[64];
            #pragma unroll
            for (int i = 0; i < 64; i++) acc[i] = 0.f;
            #pragma unroll
            for (int kt = 0; kt < 8; kt++) {
                uint2 a02 = *reinterpret_cast<const uint2*>(yR0 + kt * 8);
                uint2 a13 = *reinterpret_cast<const uint2*>(yR1 + kt * 8);
                #pragma unroll
                for (int nt = 0; nt < 16; nt++) {
                    uint2 bb = *reinterpret_cast<const uint2*>(w4s + (nt * 8 + g) * 72 + kt * 8 + tig * 2);
                    mma_tf32(acc[nt * 4], acc[nt * 4 + 1], acc[nt * 4 + 2], acc[nt * 4 + 3],
                             a02.x, a13.x, a02.y, a13.y, bb.x, bb.y);
                }
            }
            const float mu0 = muA[w16 + g],     rs0 = rsA[w16 + g];
            const float mu1 = muA[w16 + g + 8], rs1 = rsA[w16 + g + 8];
            #pragma unroll
            for (int nt = 0; nt < 8; nt++) {
                #pragma unroll
                for (int j = 0; j < 2; j++) {
                    int c = nt * 8 + 2 * tig + j;
                    int q = pp8(c);
                    float za0 = rs0 * (acc[nt * 4 + j]           - mu0 * Aw[c])      + Bw[c];
                    float zg0 = rs0 * (acc[(nt + 8) * 4 + j]     - mu0 * Aw[c + 64]) + Bw[c + 64];
                    float za1 = rs1 * (acc[nt * 4 + 2 + j]       - mu1 * Aw[c])      + Bw[c];
                    float zg1 = rs1 * (acc[(nt + 8) * 4 + 2 + j] - mu1 * Aw[c + 64]) + Bw[c + 64];
                    As[(w16 + g) * 72 + q]     = __uint_as_float(tf32r(za0 * zg0));
                    As[(w16 + g + 8) * 72 + q] = __uint_as_float(tf32r(za1 * zg1));
                }
            }
        }
        __syncthreads();

        // ---- GEMM3: conv5 (N=64) + final epilogue -> Ys ----
        {
            float acc[32];
            #pragma unroll
            for (int i = 0; i < 32; i++) acc[i] = 0.f;
            #pragma unroll
            for (int kt = 0; kt < 8; kt++) {
                uint2 a02 = *reinterpret_cast<const uint2*>(aR0 + kt * 8);
                uint2 a13 = *reinterpret_cast<const uint2*>(aR1 + kt * 8);
                #pragma unroll
                for (int nt = 0; nt < 8; nt++) {
                    uint2 bb = *reinterpret_cast<const uint2*>(w5s + (nt * 8 + g) * 72 + kt * 8 + tig * 2);
                    mma_tf32(acc[nt * 4], acc[nt * 4 + 1], acc[nt * 4 + 2], acc[nt * 4 + 3],
                             a02.x, a13.x, a02.y, a13.y, bb.x, bb.y);
                }
            }
            #pragma unroll
            for (int nt = 0; nt < 8; nt++) {
                #pragma unroll
                for (int j = 0; j < 2; j++) {
                    int c = nt * 8 + 2 * tig + j;
                    int q = pp8(c);
                    float* y0 = Ys + (w16 + g) * 72 + q;
                    float* y1 = Ys + (w16 + g + 8) * 72 + q;
                    *y0 = *y0 + (acc[nt * 4 + j]     + b5s[c]) * gas[c];
                    *y1 = *y1 + (acc[nt * 4 + 2 + j] + b5s[c]) * gas[c];
                }
            }
        }
        __syncthreads();

        // coalesced store
        for (int i = tid; i < 16384; i += 512) {
            int p = i & 255, ch = i >> 8;
            int gp = pix0 + ((p >> 5) << 8) + (p & 31);
            out[xbase + (size_t)ch * HWPIX + gp] = Ys[p * 72 + pp8(ch)];
        }
        __syncthreads();
    }
}

// =====================================================================
// launch
// =====================================================================
extern "C" void kernel_launch(void* const* d_in, const int* in_sizes, int n_in,
                              void* d_out, int out_size)
{
    (void)in_sizes; (void)n_in; (void)out_size;
    const float* x     = (const float*)d_in[0];
    const float* w1    = (const float*)d_in[1];
    const float* b1    = (const float*)d_in[2];
    const float* w2    = (const float*)d_in[3];
    const float* b2    = (const float*)d_in[4];
    const float* w3    = (const float*)d_in[5];
    const float* b3    = (const float*)d_in[6];
    const float* scaw  = (const float*)d_in[7];
    const float* scab  = (const float*)d_in[8];
    const float* w4    = (const float*)d_in[9];
    const float* b4    = (const float*)d_in[10];
    const float* w5    = (const float*)d_in[11];
    const float* b5    = (const float*)d_in[12];
    const float* n1w   = (const float*)d_in[13];
    const float* n1b   = (const float*)d_in[14];
    const float* n2w   = (const float*)d_in[15];
    const float* n2b   = (const float*)d_in[16];
    const float* beta  = (const float*)d_in[17];
    const float* gamma = (const float*)d_in[18];
    const float* mod1  = (const float*)d_in[19];
    const float* mod2  = (const float*)d_in[20];
    const float* mod3  = (const float*)d_in[21];
    const float* mod4  = (const float*)d_in[22];
    const float* mod5  = (const float*)d_in[23];
    float* out = (float*)d_out;

    cudaFuncSetAttribute(k1_tc, cudaFuncAttributeMaxDynamicSharedMemorySize, K1_SMEMB);
    cudaFuncSetAttribute(k2_dw_gate, cudaFuncAttributeMaxDynamicSharedMemorySize, K2_SMEMB);
    cudaFuncSetAttribute(k4_tc, cudaFuncAttributeMaxDynamicSharedMemorySize, K4_SMEMB);

    k0_demod<<<2 * 384, 256>>>(w1, w3, w4, w5, b4, n2w, n2b, mod1, mod3, mod4, mod5);
    k1_tc<<<BATCH * CELLS, 512, K1_SMEMB>>>(x, b1, n1w, n1b);
    k2_dw_gate<<<1024, 256, K2_SMEMB>>>(w2, b2, mod2);
    k3_sca<<<BATCH, 256>>>(scaw, scab);
    k4_tc<<<BATCH * CELLS, 512, K4_SMEMB>>>(x, b3, b5, beta, gamma, out);
}

// round 6
// speedup vs baseline: 1.7663x; 1.3272x over previous
#include <cuda_runtime.h>
#include <cstdint>

// ---------------- problem constants ----------------
#define BATCH 2
#define C 64
#define DW 128
#define HH 256
#define WW 256
#define HWPIX 65536
#define CELLS 64
// per-cell demod weight scratch layout
#define W1OFF 0        // 128x64
#define W3OFF 8192     // 64x64
#define W4OFF 12288    // 128x64 (n2w-folded)
#define W5OFF 20480    // 64x64
#define AOFF  24576    // 128
#define BOFF  24704    // 128
#define PERCELL 24832

// ---------------- scratch ----------------
// g_t: CHANNEL-LAST [b][pix][128];  g_ymid: CHANNEL-LAST [b][pix][64]
static __device__ float g_t[(size_t)BATCH * HWPIX * DW];
static __device__ float g_ymid[(size_t)BATCH * HWPIX * C];
static __device__ float g_sums[BATCH * CELLS * C];
static __device__ float g_wd[(size_t)BATCH * CELLS * PERCELL];

// ---------------- helpers ----------------
// pair-permutation within each 8-channel block (K-dim layout for mma frags)
__device__ __forceinline__ int pp8(int c) {
    int k = c & 7;
    return (c & ~7) + ((k < 4) ? (k << 1) : (((k - 4) << 1) | 1));
}
__device__ __forceinline__ uint32_t tf32r(float f) {
    uint32_t r;
    asm("cvt.rna.tf32.f32 %0, %1;" : "=r"(r) : "f"(f));
    return r;
}
__device__ __forceinline__ void mma_tf32(float& d0, float& d1, float& d2, float& d3,
                                         uint32_t a0, uint32_t a1, uint32_t a2, uint32_t a3,
                                         uint32_t b0, uint32_t b1) {
    asm volatile(
        "mma.sync.aligned.m16n8k8.row.col.f32.tf32.tf32.f32 "
        "{%0,%1,%2,%3},{%4,%5,%6,%7},{%8,%9},{%0,%1,%2,%3};"
        : "+f"(d0), "+f"(d1), "+f"(d2), "+f"(d3)
        : "r"(a0), "r"(a1), "r"(a2), "r"(a3), "r"(b0), "r"(b1));
}

// =====================================================================
// K0: demodulate all 1x1 conv weights once per (b, cell, output row).
// =====================================================================
__global__ __launch_bounds__(256) void k0_demod(
    const float* __restrict__ w1, const float* __restrict__ w3,
    const float* __restrict__ w4, const float* __restrict__ w5,
    const float* __restrict__ b4,
    const float* __restrict__ n2w, const float* __restrict__ n2b,
    const float* __restrict__ mod1, const float* __restrict__ mod3,
    const float* __restrict__ mod4, const float* __restrict__ mod5)
{
    __shared__ float tile[4096];
    __shared__ float psA[256];
    __shared__ float psB[256];
    __shared__ float ri[64];

    const int bid = blockIdx.x;
    const int b   = (bid >= 384) ? 1 : 0;
    const int rid = bid - 384 * b;
    const int tid = threadIdx.x;

    const float* wrow; const float* mblk; int dstoff; int isW4 = 0; int o;
    if (rid < 128)      { o = rid;       wrow = w1 + o * 64; mblk = mod1 + ((size_t)(b * 128 + o) << 12); dstoff = W1OFF + o * 64; }
    else if (rid < 192) { o = rid - 128; wrow = w3 + o * 64; mblk = mod3 + ((size_t)(b * 64  + o) << 12); dstoff = W3OFF + o * 64; }
    else if (rid < 320) { o = rid - 192; wrow = w4 + o * 64; mblk = mod4 + ((size_t)(b * 128 + o) << 12); dstoff = W4OFF + o * 64; isW4 = 1; }
    else                { o = rid - 320; wrow = w5 + o * 64; mblk = mod5 + ((size_t)(b * 64  + o) << 12); dstoff = W5OFF + o * 64; }

    for (int i = tid; i < 1024; i += 256)
        reinterpret_cast<float4*>(tile)[i] = reinterpret_cast<const float4*>(mblk)[i];
    __syncthreads();

    const int cell = tid & 63, part = tid >> 6;
    const int c0 = part * 16;
    float wv[16];
    float ss = 0.f;
    #pragma unroll
    for (int j = 0; j < 16; j++) {
        float t = wrow[c0 + j] * tile[(c0 + j) * 64 + cell];
        wv[j] = t; ss += t * t;
    }
    psA[part * 64 + cell] = ss;
    __syncthreads();
    if (tid < 64) ri[tid] = rsqrtf(psA[tid] + psA[64 + tid] + psA[128 + tid] + psA[192 + tid]);
    __syncthreads();
    const float r = ri[cell];
    float* dbase = g_wd + ((size_t)(b * 64 + cell)) * PERCELL + dstoff;

    if (!isW4) {
        #pragma unroll
        for (int j = 0; j < 16; j++) dbase[c0 + j] = wv[j] * r;
    } else {
        float aA = 0.f, bB = 0.f;
        #pragma unroll
        for (int j = 0; j < 16; j++) {
            float wd = wv[j] * r;
            float wn = wd * n2w[c0 + j];
            dbase[c0 + j] = wn;
            aA += wn;
            bB += wd * n2b[c0 + j];
        }
        psA[part * 64 + cell] = aA;
        psB[part * 64 + cell] = bB;
        __syncthreads();
        if (tid < 64) {
            float* cw = g_wd + ((size_t)(b * 64 + tid)) * PERCELL;
            cw[AOFF + o] = psA[tid] + psA[64 + tid] + psA[128 + tid] + psA[192 + tid];
            cw[BOFF + o] = psB[tid] + psB[64 + tid] + psB[128 + tid] + psB[192 + tid] + b4[o];
        }
    }
}

// =====================================================================
// K1 (mma.sync tf32): LN1 + conv1x1 (64->128) per cell, direct CL stores.
// grid=128, block=512 (16 warps), 4 tiles of 256 pix, smem ~112KB.
// =====================================================================
#define K1_AS   0                        // 256*72
#define K1_WS   (256*72)                 // 128*72
#define K1_B1   (K1_WS + 128*72)         // 128
#define K1_N1W  (K1_B1 + 128)            // 64 (pair-permuted)
#define K1_N1B  (K1_N1W + 64)            // 64
#define K1_SMEMF (K1_N1B + 64)
#define K1_SMEMB (K1_SMEMF * 4)

__global__ __launch_bounds__(512) void k1_tc(
    const float* __restrict__ x, const float* __restrict__ b1,
    const float* __restrict__ n1w, const float* __restrict__ n1b)
{
    extern __shared__ float sm[];
    float* As   = sm + K1_AS;
    float* Ws   = sm + K1_WS;
    float* b1s  = sm + K1_B1;
    float* n1wp = sm + K1_N1W;
    float* n1bp = sm + K1_N1B;

    const int tid = threadIdx.x;
    const int wid = tid >> 5, lane = tid & 31;
    const int g = lane >> 2, tig = lane & 3;
    const int cta = blockIdx.x;
    const int b = cta >> 6, cell = cta & 63;
    const int u = cell >> 3, v = cell & 7;

    const float* cellw = g_wd + ((size_t)(b * 64 + cell)) * PERCELL;
    for (int i = tid; i < 8192; i += 512) {
        int o = i >> 6, c = i & 63;
        Ws[o * 72 + pp8(c)] = __uint_as_float(tf32r(cellw[W1OFF + i]));
    }
    if (tid < 128) b1s[tid] = b1[tid];
    if (tid < 64) { n1wp[pp8(tid)] = n1w[tid]; n1bp[pp8(tid)] = n1b[tid]; }
    __syncthreads();

    const size_t xbase = (size_t)b * C * HWPIX;
    const size_t tb2   = (size_t)b * HWPIX * DW;
    const int w16 = wid * 16;

    #pragma unroll 1
    for (int t = 0; t < 4; t++) {
        const int pix0 = (u * 32 + t * 8) * WW + v * 32;

        // load x tile -> As (channel-major source, pair layout dest)
        for (int i = tid; i < 16384; i += 512) {
            int p = i & 255, ch = i >> 8;
            int gp = pix0 + ((p >> 5) << 8) + (p & 31);
            As[p * 72 + pp8(ch)] = x[xbase + (size_t)ch * HWPIX + gp];
        }
        __syncthreads();

        // LN per pixel, write back normalized tf32
        if (tid < 256) {
            float* row = As + tid * 72;
            float s = 0.f, sq = 0.f;
            #pragma unroll
            for (int q = 0; q < 32; q++) {
                float2 p2 = reinterpret_cast<const float2*>(row)[q];
                s += p2.x + p2.y; sq += p2.x * p2.x + p2.y * p2.y;
            }
            const float mu = s * (1.f / 64.f);
            const float rstd = rsqrtf(sq * (1.f / 64.f) - mu * mu + 1e-6f);
            #pragma unroll
            for (int q = 0; q < 64; q++)
                row[q] = __uint_as_float(tf32r((row[q] - mu) * rstd * n1wp[q] + n1bp[q]));
        }
        __syncthreads();

        // GEMM: 16 pix x 128 out per warp
        float acc[64];
        #pragma unroll
        for (int i = 0; i < 64; i++) acc[i] = 0.f;
        const float* aR0 = As + (w16 + g) * 72 + tig * 2;
        const float* aR1 = aR0 + 8 * 72;
        #pragma unroll
        for (int kt = 0; kt < 8; kt++) {
            uint2 a02 = *reinterpret_cast<const uint2*>(aR0 + kt * 8);
            uint2 a13 = *reinterpret_cast<const uint2*>(aR1 + kt * 8);
            #pragma unroll
            for (int nt = 0; nt < 16; nt++) {
                uint2 bb = *reinterpret_cast<const uint2*>(Ws + (nt * 8 + g) * 72 + kt * 8 + tig * 2);
                mma_tf32(acc[nt * 4], acc[nt * 4 + 1], acc[nt * 4 + 2], acc[nt * 4 + 3],
                         a02.x, a13.x, a02.y, a13.y, bb.x, bb.y);
            }
        }

        // direct channel-last store: thread owns channels (nt*8+2tig, +1) for 2 pixel rows
        {
            const int p0 = w16 + g, p1 = p0 + 8;
            float* o0 = g_t + tb2 + (size_t)(pix0 + ((p0 >> 5) << 8) + (p0 & 31)) * DW;
            float* o1 = g_t + tb2 + (size_t)(pix0 + ((p1 >> 5) << 8) + (p1 & 31)) * DW;
            #pragma unroll
            for (int nt = 0; nt < 16; nt++) {
                const int o = nt * 8 + 2 * tig;
                *reinterpret_cast<float2*>(o0 + o) =
                    make_float2(acc[nt * 4]     + b1s[o], acc[nt * 4 + 1] + b1s[o + 1]);
                *reinterpret_cast<float2*>(o1 + o) =
                    make_float2(acc[nt * 4 + 2] + b1s[o], acc[nt * 4 + 3] + b1s[o + 1]);
            }
        }
        __syncthreads();
    }
}

// =====================================================================
// K2: depthwise 3x3 + SimpleGate + per-cell channel sums (channel-last IO).
// grid = 1024 (b, cell, 8 channel-groups), block = 256.
// =====================================================================
#define K2_SMEMB (16 * 1156 * 4)
__global__ __launch_bounds__(256, 2) void k2_dw_gate(
    const float* __restrict__ w2, const float* __restrict__ b2,
    const float* __restrict__ mod2)
{
    extern __shared__ float tiles[];          // [16][1156]
    __shared__ float w2s[16 * 9];
    __shared__ float b2s[16];
    __shared__ float redbuf[64];

    const int bidx = blockIdx.x;
    const int b    = bidx >> 9;
    const int cell = (bidx >> 3) & 63;
    const int grp  = bidx & 7;
    const int u    = cell >> 3, v = cell & 7;
    const int tid  = threadIdx.x;
    const int cbase = grp * 8;

    if (tid < 16) {
        const int ch = (tid < 8) ? (cbase + tid) : (64 + cbase + tid - 8);
        const float m = mod2[(size_t)(b * DW + ch) * 64 + cell];
        float ss = 0.f;
        float wv[9];
        #pragma unroll
        for (int k = 0; k < 9; k++) { wv[k] = w2[ch * 9 + k] * m; ss += wv[k] * wv[k]; }
        const float rr = rsqrtf(ss);
        #pragma unroll
        for (int k = 0; k < 9; k++) w2s[tid * 9 + k] = wv[k] * rr;
        b2s[tid] = b2[ch];
    }
    __syncthreads();

    const size_t tb2 = (size_t)b * HWPIX * DW;
    const int h0 = u * 32 - 1, w0 = v * 32 - 1;

    // halo tile load: 4x float4 per pixel from channel-last g_t
    for (int i = tid; i < 1156; i += 256) {
        const int ih = i / 34, iw = i - ih * 34;
        const int hh = h0 + ih, ww2 = w0 + iw;
        float4 qa0, qa1, qg0, qg1;
        if ((hh >= 0) & (hh < HH) & (ww2 >= 0) & (ww2 < WW)) {
            const float* bp = g_t + tb2 + (size_t)(hh * WW + ww2) * DW;
            qa0 = *reinterpret_cast<const float4*>(bp + cbase);
            qa1 = *reinterpret_cast<const float4*>(bp + cbase + 4);
            qg0 = *reinterpret_cast<const float4*>(bp + 64 + cbase);
            qg1 = *reinterpret_cast<const float4*>(bp + 64 + cbase + 4);
        } else {
            qa0 = qa1 = qg0 = qg1 = make_float4(0.f, 0.f, 0.f, 0.f);
        }
        tiles[0 * 1156 + i] = qa0.x;  tiles[1 * 1156 + i] = qa0.y;
        tiles[2 * 1156 + i] = qa0.z;  tiles[3 * 1156 + i] = qa0.w;
        tiles[4 * 1156 + i] = qa1.x;  tiles[5 * 1156 + i] = qa1.y;
        tiles[6 * 1156 + i] = qa1.z;  tiles[7 * 1156 + i] = qa1.w;
        tiles[8 * 1156 + i] = qg0.x;  tiles[9 * 1156 + i] = qg0.y;
        tiles[10 * 1156 + i] = qg0.z; tiles[11 * 1156 + i] = qg0.w;
        tiles[12 * 1156 + i] = qg1.x; tiles[13 * 1156 + i] = qg1.y;
        tiles[14 * 1156 + i] = qg1.z; tiles[15 * 1156 + i] = qg1.w;
    }
    __syncthreads();

    const int lane = tid & 31, warp = tid >> 5;
    const size_t ymb = (size_t)b * HWPIX * C;
    float csum[8];
    #pragma unroll
    for (int j = 0; j < 8; j++) csum[j] = 0.f;

    #pragma unroll
    for (int k = 0; k < 4; k++) {
        const int p = k * 256 + tid;
        const int ph = p >> 5, pw = p & 31;
        float ov[8];
        #pragma unroll
        for (int j = 0; j < 8; j++) {
            float a = b2s[j], gg = b2s[8 + j];
            const float* wA = w2s + j * 9;
            const float* wG = w2s + (8 + j) * 9;
            const float* tA = tiles + j * 1156;
            const float* tG = tiles + (8 + j) * 1156;
            #pragma unroll
            for (int dh = 0; dh < 3; dh++) {
                #pragma unroll
                for (int dw2 = 0; dw2 < 3; dw2++) {
                    const int ti = (ph + dh) * 34 + pw + dw2;
                    a += wA[dh * 3 + dw2] * tA[ti];
                    gg += wG[dh * 3 + dw2] * tG[ti];
                }
            }
            ov[j] = a * gg;
            csum[j] += ov[j];
        }
        float* yp = g_ymid + ymb + (size_t)((u * 32 + ph) * WW + v * 32 + pw) * C + cbase;
        *reinterpret_cast<float4*>(yp)     = make_float4(ov[0], ov[1], ov[2], ov[3]);
        *reinterpret_cast<float4*>(yp + 4) = make_float4(ov[4], ov[5], ov[6], ov[7]);
    }

    #pragma unroll
    for (int j = 0; j < 8; j++) {
        float ls = csum[j];
        for (int off = 16; off; off >>= 1) ls += __shfl_down_sync(0xffffffffu, ls, off);
        if (lane == 0) redbuf[j * 8 + warp] = ls;
    }
    __syncthreads();
    if (tid < 8) {
        float s = 0.f;
        #pragma unroll
        for (int i = 0; i < 8; i++) s += redbuf[tid * 8 + i];
        g_sums[((size_t)b * CELLS + cell) * C + cbase + tid] = s;
    }
}

// =====================================================================
// K4 (mma.sync tf32): SCA(in-prologue) -> conv3 -> y1 -> folded-LN2 conv4+gate
//                      -> conv5 -> out.  grid=128, block=512.
// =====================================================================
#define K4_AS   0                          // 256*72 (act -> zc)
#define K4_YS   (256*72)                   // 256*72 (x -> y1)
#define K4_W3   (2*256*72)                 // 64*72
#define K4_W4   (K4_W3 + 64*72)            // 128*72
#define K4_W5   (K4_W4 + 128*72)           // 64*72
#define K4_MU   (K4_W5 + 64*72)            // 256
#define K4_RS   (K4_MU + 256)              // 256
#define K4_SSM  (K4_RS + 256)              // 64
#define K4_B3   (K4_SSM + 64)              // 64
#define K4_BE   (K4_B3 + 64)               // 64
#define K4_B5   (K4_BE + 64)               // 64
#define K4_GA   (K4_B5 + 64)               // 64
#define K4_AW   (K4_GA + 64)               // 128
#define K4_BW   (K4_AW + 128)              // 128
#define K4_SMEMF (K4_BW + 128)
#define K4_SMEMB (K4_SMEMF * 4)

__global__ __launch_bounds__(512) void k4_tc(
    const float* __restrict__ x,
    const float* __restrict__ b3, const float* __restrict__ b5,
    const float* __restrict__ beta, const float* __restrict__ gamma,
    const float* __restrict__ scaw, const float* __restrict__ scab,
    float* __restrict__ out)
{
    extern __shared__ float sm[];
    float* As  = sm + K4_AS;
    float* Ys  = sm + K4_YS;
    float* w3s = sm + K4_W3;
    float* w4s = sm + K4_W4;
    float* w5s = sm + K4_W5;
    float* muA = sm + K4_MU;
    float* rsA = sm + K4_RS;
    float* ssm = sm + K4_SSM;
    float* b3s = sm + K4_B3;
    float* bes = sm + K4_BE;
    float* b5s = sm + K4_B5;
    float* gas = sm + K4_GA;
    float* Aw  = sm + K4_AW;
    float* Bw  = sm + K4_BW;

    const int tid = threadIdx.x;
    const int wid = tid >> 5, lane = tid & 31;
    const int g = lane >> 2, tig = lane & 3;
    const int cta = blockIdx.x;
    const int b = cta >> 6, cell = cta & 63;
    const int u = cell >> 3, v = cell & 7;

    // ---- SCA in prologue (redundant per CTA; uses muA/rsA as scratch) ----
    if (tid < 256) {
        const int c = tid & 63, seg = tid >> 6;
        float s = 0.f;
        #pragma unroll 4
        for (int cl = seg * 16; cl < seg * 16 + 16; cl++)
            s += g_sums[((size_t)b * CELLS + cl) * C + c];
        muA[tid] = s;
    }
    // ---- stage weights (tf32, pair layout) concurrently ----
    const float* cellw = g_wd + ((size_t)(b * 64 + cell)) * PERCELL;
    for (int i = tid; i < 4096; i += 512) {
        int o = i >> 6, c = i & 63;
        w3s[o * 72 + pp8(c)] = __uint_as_float(tf32r(cellw[W3OFF + i]));
        w5s[o * 72 + pp8(c)] = __uint_as_float(tf32r(cellw[W5OFF + i]));
    }
    for (int i = tid; i < 8192; i += 512) {
        int o = i >> 6, c = i & 63;
        w4s[o * 72 + pp8(c)] = __uint_as_float(tf32r(cellw[W4OFF + i]));
    }
    if (tid < 64) {
        b3s[tid] = b3[tid];
        bes[tid] = beta[tid];
        b5s[tid] = b5[tid];
        gas[tid] = gamma[tid];
    }
    if (tid < 128) { Aw[tid] = cellw[AOFF + tid]; Bw[tid] = cellw[BOFF + tid]; }
    __syncthreads();
    if (tid < 64)
        rsA[tid] = (muA[tid] + muA[64 + tid] + muA[128 + tid] + muA[192 + tid]) * (1.f / (float)HWPIX);
    __syncthreads();
    if (tid < 64) {
        float acc = scab[tid];
        #pragma unroll 8
        for (int cc = 0; cc < 64; cc++) acc += scaw[tid * 64 + cc] * rsA[cc];
        ssm[tid] = acc;
    }
    __syncthreads();

    const size_t xbase = (size_t)b * C * HWPIX;
    const size_t ymb   = (size_t)b * HWPIX * C;
    const int w16 = wid * 16;

    #pragma unroll 1
    for (int t = 0; t < 4; t++) {
        const int pix0 = (u * 32 + t * 8) * WW + v * 32;

        // act = ymid*s from channel-last g_ymid (vectorized)
        for (int i = tid; i < 4096; i += 512) {
            const int p = i >> 4, q4 = i & 15;
            const int gp = pix0 + ((p >> 5) << 8) + (p & 31);
            float4 y = *reinterpret_cast<const float4*>(g_ymid + ymb + (size_t)gp * C + q4 * 4);
            const int c0 = q4 * 4;
            float* row = As + p * 72;
            row[pp8(c0)]     = __uint_as_float(tf32r(y.x * ssm[c0]));
            row[pp8(c0 + 1)] = __uint_as_float(tf32r(y.y * ssm[c0 + 1]));
            row[pp8(c0 + 2)] = __uint_as_float(tf32r(y.z * ssm[c0 + 2]));
            row[pp8(c0 + 3)] = __uint_as_float(tf32r(y.w * ssm[c0 + 3]));
        }
        // x (channel-major harness layout)
        for (int i = tid; i < 16384; i += 512) {
            int p = i & 255, ch = i >> 8;
            int gp = pix0 + ((p >> 5) << 8) + (p & 31);
            Ys[p * 72 + pp8(ch)] = x[xbase + (size_t)ch * HWPIX + gp];
        }
        __syncthreads();

        const float* aR0 = As + (w16 + g) * 72 + tig * 2;
        const float* aR1 = aR0 + 8 * 72;
        const float* yR0 = Ys + (w16 + g) * 72 + tig * 2;
        const float* yR1 = yR0 + 8 * 72;

        // ---- GEMM1: conv3 (N=64) ----
        {
            float acc[32];
            #pragma unroll
            for (int i = 0; i < 32; i++) acc[i] = 0.f;
            #pragma unroll
            for (int kt = 0; kt < 8; kt++) {
                uint2 a02 = *reinterpret_cast<const uint2*>(aR0 + kt * 8);
                uint2 a13 = *reinterpret_cast<const uint2*>(aR1 + kt * 8);
                #pragma unroll
                for (int nt = 0; nt < 8; nt++) {
                    uint2 bb = *reinterpret_cast<const uint2*>(w3s + (nt * 8 + g) * 72 + kt * 8 + tig * 2);
                    mma_tf32(acc[nt * 4], acc[nt * 4 + 1], acc[nt * 4 + 2], acc[nt * 4 + 3],
                             a02.x, a13.x, a02.y, a13.y, bb.x, bb.y);
                }
            }
            #pragma unroll
            for (int nt = 0; nt < 8; nt++) {
                #pragma unroll
                for (int j = 0; j < 2; j++) {
                    int c = nt * 8 + 2 * tig + j;
                    int q = pp8(c);
                    float* y0 = Ys + (w16 + g) * 72 + q;
                    float* y1 = Ys + (w16 + g + 8) * 72 + q;
                    *y0 = *y0 + (acc[nt * 4 + j]     + b3s[c]) * bes[c];
                    *y1 = *y1 + (acc[nt * 4 + 2 + j] + b3s[c]) * bes[c];
                }
            }
        }
        __syncthreads();

        // ---- LN2 stats per pixel ----
        if (tid < 256) {
            const float* row = Ys + tid * 72;
            float s = 0.f, sq = 0.f;
            #pragma unroll
            for (int q = 0; q < 32; q++) {
                float2 p2 = reinterpret_cast<const float2*>(row)[q];
                s += p2.x + p2.y; sq += p2.x * p2.x + p2.y * p2.y;
            }
            const float mu = s * (1.f / 64.f);
            muA[tid] = mu;
            rsA[tid] = rsqrtf(sq * (1.f / 64.f) - mu * mu + 1e-6f);
        }
        __syncthreads();

        // ---- GEMM2: conv4 (N=128, LN folded) + gate -> As ----
        {
            float acc[64];
            #pragma unroll
            for (int i = 0; i < 64; i++) acc[i] = 0.f;
            #pragma unroll
            for (int kt = 0; kt < 8; kt++) {
                uint2 a02 = *reinterpret_cast<const uint2*>(yR0 + kt * 8);
                uint2 a13 = *reinterpret_cast<const uint2*>(yR1 + kt * 8);
                #pragma unroll
                for (int nt = 0; nt < 16; nt++) {
                    uint2 bb = *reinterpret_cast<const uint2*>(w4s + (nt * 8 + g) * 72 + kt * 8 + tig * 2);
                    mma_tf32(acc[nt * 4], acc[nt * 4 + 1], acc[nt * 4 + 2], acc[nt * 4 + 3],
                             a02.x, a13.x, a02.y, a13.y, bb.x, bb.y);
                }
            }
            const float mu0 = muA[w16 + g],     rs0 = rsA[w16 + g];
            const float mu1 = muA[w16 + g + 8], rs1 = rsA[w16 + g + 8];
            #pragma unroll
            for (int nt = 0; nt < 8; nt++) {
                #pragma unroll
                for (int j = 0; j < 2; j++) {
                    int c = nt * 8 + 2 * tig + j;
                    int q = pp8(c);
                    float za0 = rs0 * (acc[nt * 4 + j]           - mu0 * Aw[c])      + Bw[c];
                    float zg0 = rs0 * (acc[(nt + 8) * 4 + j]     - mu0 * Aw[c + 64]) + Bw[c + 64];
                    float za1 = rs1 * (acc[nt * 4 + 2 + j]       - mu1 * Aw[c])      + Bw[c];
                    float zg1 = rs1 * (acc[(nt + 8) * 4 + 2 + j] - mu1 * Aw[c + 64]) + Bw[c + 64];
                    As[(w16 + g) * 72 + q]     = __uint_as_float(tf32r(za0 * zg0));
                    As[(w16 + g + 8) * 72 + q] = __uint_as_float(tf32r(za1 * zg1));
                }
            }
        }
        __syncthreads();

        // ---- GEMM3: conv5 (N=64) + final epilogue -> Ys ----
        {
            float acc[32];
            #pragma unroll
            for (int i = 0; i < 32; i++) acc[i] = 0.f;
            #pragma unroll
            for (int kt = 0; kt < 8; kt++) {
                uint2 a02 = *reinterpret_cast<const uint2*>(aR0 + kt * 8);
                uint2 a13 = *reinterpret_cast<const uint2*>(aR1 + kt * 8);
                #pragma unroll
                for (int nt = 0; nt < 8; nt++) {
                    uint2 bb = *reinterpret_cast<const uint2*>(w5s + (nt * 8 + g) * 72 + kt * 8 + tig * 2);
                    mma_tf32(acc[nt * 4], acc[nt * 4 + 1], acc[nt * 4 + 2], acc[nt * 4 + 3],
                             a02.x, a13.x, a02.y, a13.y, bb.x, bb.y);
                }
            }
            #pragma unroll
            for (int nt = 0; nt < 8; nt++) {
                #pragma unroll
                for (int j = 0; j < 2; j++) {
                    int c = nt * 8 + 2 * tig + j;
                    int q = pp8(c);
                    float* y0 = Ys + (w16 + g) * 72 + q;
                    float* y1 = Ys + (w16 + g + 8) * 72 + q;
                    *y0 = *y0 + (acc[nt * 4 + j]     + b5s[c]) * gas[c];
                    *y1 = *y1 + (acc[nt * 4 + 2 + j] + b5s[c]) * gas[c];
                }
            }
        }
        __syncthreads();

        // coalesced store (channel-major out, harness layout)
        for (int i = tid; i < 16384; i += 512) {
            int p = i & 255, ch = i >> 8;
            int gp = pix0 + ((p >> 5) << 8) + (p & 31);
            out[xbase + (size_t)ch * HWPIX + gp] = Ys[p * 72 + pp8(ch)];
        }
        __syncthreads();
    }
}

// =====================================================================
// launch
// =====================================================================
extern "C" void kernel_launch(void* const* d_in, const int* in_sizes, int n_in,
                              void* d_out, int out_size)
{
    (void)in_sizes; (void)n_in; (void)out_size;
    const float* x     = (const float*)d_in[0];
    const float* w1    = (const float*)d_in[1];
    const float* b1    = (const float*)d_in[2];
    const float* w2    = (const float*)d_in[3];
    const float* b2    = (const float*)d_in[4];
    const float* w3    = (const float*)d_in[5];
    const float* b3    = (const float*)d_in[6];
    const float* scaw  = (const float*)d_in[7];
    const float* scab  = (const float*)d_in[8];
    const float* w4    = (const float*)d_in[9];
    const float* b4    = (const float*)d_in[10];
    const float* w5    = (const float*)d_in[11];
    const float* b5    = (const float*)d_in[12];
    const float* n1w   = (const float*)d_in[13];
    const float* n1b   = (const float*)d_in[14];
    const float* n2w   = (const float*)d_in[15];
    const float* n2b   = (const float*)d_in[16];
    const float* beta  = (const float*)d_in[17];
    const float* gamma = (const float*)d_in[18];
    const float* mod1  = (const float*)d_in[19];
    const float* mod2  = (const float*)d_in[20];
    const float* mod3  = (const float*)d_in[21];
    const float* mod4  = (const float*)d_in[22];
    const float* mod5  = (const float*)d_in[23];
    float* out = (float*)d_out;

    cudaFuncSetAttribute(k1_tc, cudaFuncAttributeMaxDynamicSharedMemorySize, K1_SMEMB);
    cudaFuncSetAttribute(k2_dw_gate, cudaFuncAttributeMaxDynamicSharedMemorySize, K2_SMEMB);
    cudaFuncSetAttribute(k4_tc, cudaFuncAttributeMaxDynamicSharedMemorySize, K4_SMEMB);

    k0_demod<<<2 * 384, 256>>>(w1, w3, w4, w5, b4, n2w, n2b, mod1, mod3, mod4, mod5);
    k1_tc<<<BATCH * CELLS, 512, K1_SMEMB>>>(x, b1, n1w, n1b);
    k2_dw_gate<<<1024, 256, K2_SMEMB>>>(w2, b2, mod2);
    k4_tc<<<BATCH * CELLS, 512, K4_SMEMB>>>(x, b3, b5, beta, gamma, scaw, scab, out);
}

// round 7
// speedup vs baseline: 2.2165x; 1.2549x over previous
#include <cuda_runtime.h>
#include <cstdint>

// ---------------- problem constants ----------------
#define BATCH 2
#define C 64
#define DW 128
#define HH 256
#define WW 256
#define HWPIX 65536
#define CELLS 64
#define TS 68          // smem row stride (68 % 32 == 4 -> conflict-free patterns)
// per-cell demod weight scratch layout
#define W1OFF 0        // 128x64
#define W3OFF 8192     // 64x64
#define W4OFF 12288    // 128x64 (n2w-folded)
#define W5OFF 20480    // 64x64
#define AOFF  24576    // 128
#define BOFF  24704    // 128
#define PERCELL 24832

// ---------------- scratch ----------------
// g_t: CHANNEL-LAST [b][pix][128];  g_ymid: CHANNEL-LAST [b][pix][64]
static __device__ float g_t[(size_t)BATCH * HWPIX * DW];
static __device__ float g_ymid[(size_t)BATCH * HWPIX * C];
static __device__ float g_sums[BATCH * CELLS * C];
static __device__ float g_wd[(size_t)BATCH * CELLS * PERCELL];

// ---------------- helpers ----------------
__device__ __forceinline__ uint32_t tf32r(float f) {
    uint32_t r;
    asm("cvt.rna.tf32.f32 %0, %1;" : "=r"(r) : "f"(f));
    return r;
}
__device__ __forceinline__ float tf32f(float f) { return __uint_as_float(tf32r(f)); }
__device__ __forceinline__ void mma_tf32(float& d0, float& d1, float& d2, float& d3,
                                         uint32_t a0, uint32_t a1, uint32_t a2, uint32_t a3,
                                         uint32_t b0, uint32_t b1) {
    asm volatile(
        "mma.sync.aligned.m16n8k8.row.col.f32.tf32.tf32.f32 "
        "{%0,%1,%2,%3},{%4,%5,%6,%7},{%8,%9},{%0,%1,%2,%3};"
        : "+f"(d0), "+f"(d1), "+f"(d2), "+f"(d3)
        : "r"(a0), "r"(a1), "r"(a2), "r"(a3), "r"(b0), "r"(b1));
}

// =====================================================================
// K0: demodulate all 1x1 conv weights once per (b, cell, output row).
// =====================================================================
__global__ __launch_bounds__(256) void k0_demod(
    const float* __restrict__ w1, const float* __restrict__ w3,
    const float* __restrict__ w4, const float* __restrict__ w5,
    const float* __restrict__ b4,
    const float* __restrict__ n2w, const float* __restrict__ n2b,
    const float* __restrict__ mod1, const float* __restrict__ mod3,
    const float* __restrict__ mod4, const float* __restrict__ mod5)
{
    __shared__ float tile[4096];
    __shared__ float psA[256];
    __shared__ float psB[256];
    __shared__ float ri[64];

    const int bid = blockIdx.x;
    const int b   = (bid >= 384) ? 1 : 0;
    const int rid = bid - 384 * b;
    const int tid = threadIdx.x;

    const float* wrow; const float* mblk; int dstoff; int isW4 = 0; int o;
    if (rid < 128)      { o = rid;       wrow = w1 + o * 64; mblk = mod1 + ((size_t)(b * 128 + o) << 12); dstoff = W1OFF + o * 64; }
    else if (rid < 192) { o = rid - 128; wrow = w3 + o * 64; mblk = mod3 + ((size_t)(b * 64  + o) << 12); dstoff = W3OFF + o * 64; }
    else if (rid < 320) { o = rid - 192; wrow = w4 + o * 64; mblk = mod4 + ((size_t)(b * 128 + o) << 12); dstoff = W4OFF + o * 64; isW4 = 1; }
    else                { o = rid - 320; wrow = w5 + o * 64; mblk = mod5 + ((size_t)(b * 64  + o) << 12); dstoff = W5OFF + o * 64; }

    for (int i = tid; i < 1024; i += 256)
        reinterpret_cast<float4*>(tile)[i] = reinterpret_cast<const float4*>(mblk)[i];
    __syncthreads();

    const int cell = tid & 63, part = tid >> 6;
    const int c0 = part * 16;
    float wv[16];
    float ss = 0.f;
    #pragma unroll
    for (int j = 0; j < 16; j++) {
        float t = wrow[c0 + j] * tile[(c0 + j) * 64 + cell];
        wv[j] = t; ss += t * t;
    }
    psA[part * 64 + cell] = ss;
    __syncthreads();
    if (tid < 64) ri[tid] = rsqrtf(psA[tid] + psA[64 + tid] + psA[128 + tid] + psA[192 + tid]);
    __syncthreads();
    const float r = ri[cell];
    float* dbase = g_wd + ((size_t)(b * 64 + cell)) * PERCELL + dstoff;

    if (!isW4) {
        #pragma unroll
        for (int j = 0; j < 16; j++) dbase[c0 + j] = wv[j] * r;
    } else {
        float aA = 0.f, bB = 0.f;
        #pragma unroll
        for (int j = 0; j < 16; j++) {
            float wd = wv[j] * r;
            float wn = wd * n2w[c0 + j];
            dbase[c0 + j] = wn;
            aA += wn;
            bB += wd * n2b[c0 + j];
        }
        psA[part * 64 + cell] = aA;
        psB[part * 64 + cell] = bB;
        __syncthreads();
        if (tid < 64) {
            float* cw = g_wd + ((size_t)(b * 64 + tid)) * PERCELL;
            cw[AOFF + o] = psA[tid] + psA[64 + tid] + psA[128 + tid] + psA[192 + tid];
            cw[BOFF + o] = psB[tid] + psB[64 + tid] + psB[128 + tid] + psB[192 + tid] + b4[o];
        }
    }
}

// =====================================================================
// K1 (mma.sync tf32): LN1 + conv1x1 (64->128) per cell.
// grid=128, block=512, stride-68 conflict-free smem, direct CL stores.
// =====================================================================
#define K1_AS    0                       // 256*TS
#define K1_WS    (256*TS)                // 128*TS
#define K1_B1    (K1_WS + 128*TS)        // 128
#define K1_N1W   (K1_B1 + 128)           // 64
#define K1_N1B   (K1_N1W + 64)           // 64
#define K1_SMEMF (K1_N1B + 64)
#define K1_SMEMB (K1_SMEMF * 4)

__global__ __launch_bounds__(512) void k1_tc(
    const float* __restrict__ x, const float* __restrict__ b1,
    const float* __restrict__ n1w, const float* __restrict__ n1b)
{
    extern __shared__ float sm[];
    float* As   = sm + K1_AS;
    float* Ws   = sm + K1_WS;
    float* b1s  = sm + K1_B1;
    float* n1ws = sm + K1_N1W;
    float* n1bs = sm + K1_N1B;

    const int tid = threadIdx.x;
    const int wid = tid >> 5, lane = tid & 31;
    const int g = lane >> 2, tig = lane & 3;
    const int cta = blockIdx.x;
    const int b = cta >> 6, cell = cta & 63;
    const int u = cell >> 3, v = cell & 7;

    const float* cellw = g_wd + ((size_t)(b * 64 + cell)) * PERCELL;
    for (int i = tid; i < 2048; i += 512) {      // 128 rows x 16 float4
        int o = i >> 4, m = i & 15;
        float4 q = *reinterpret_cast<const float4*>(cellw + W1OFF + o * 64 + 4 * m);
        *reinterpret_cast<float4*>(Ws + o * TS + 4 * m) =
            make_float4(tf32f(q.x), tf32f(q.y), tf32f(q.z), tf32f(q.w));
    }
    if (tid < 128) b1s[tid] = b1[tid];
    if (tid < 64) { n1ws[tid] = n1w[tid]; n1bs[tid] = n1b[tid]; }
    __syncthreads();

    const size_t xbase = (size_t)b * C * HWPIX;
    const size_t tb2   = (size_t)b * HWPIX * DW;
    const int w16 = wid * 16;

    #pragma unroll 1
    for (int t = 0; t < 4; t++) {
        const int pix0 = (u * 32 + t * 8) * WW + v * 32;

        // stage x (4 channels per thread -> float4 conflict-free STS)
        for (int i = tid; i < 4096; i += 512) {
            int p = i & 255, m = i >> 8;
            int gp = pix0 + ((p >> 5) << 8) + (p & 31);
            const float* xp = x + xbase + (size_t)(4 * m) * HWPIX + gp;
            *reinterpret_cast<float4*>(As + p * TS + 4 * m) =
                make_float4(xp[0], xp[HWPIX], xp[2 * HWPIX], xp[3 * HWPIX]);
        }
        __syncthreads();

        // LN per pixel (float4 conflict-free)
        if (tid < 256) {
            float* row = As + tid * TS;
            float4 r[16];
            float s = 0.f, sq = 0.f;
            #pragma unroll
            for (int m = 0; m < 16; m++) {
                r[m] = reinterpret_cast<const float4*>(row)[m];
                s  += r[m].x + r[m].y + r[m].z + r[m].w;
                sq += r[m].x * r[m].x + r[m].y * r[m].y + r[m].z * r[m].z + r[m].w * r[m].w;
            }
            const float mu = s * (1.f / 64.f);
            const float rstd = rsqrtf(sq * (1.f / 64.f) - mu * mu + 1e-6f);
            #pragma unroll
            for (int m = 0; m < 16; m++) {
                const int c = 4 * m;
                reinterpret_cast<float4*>(row)[m] = make_float4(
                    tf32f((r[m].x - mu) * rstd * n1ws[c]     + n1bs[c]),
                    tf32f((r[m].y - mu) * rstd * n1ws[c + 1] + n1bs[c + 1]),
                    tf32f((r[m].z - mu) * rstd * n1ws[c + 2] + n1bs[c + 2]),
                    tf32f((r[m].w - mu) * rstd * n1ws[c + 3] + n1bs[c + 3]));
            }
        }
        __syncthreads();

        // GEMM: 16 pix x 128 out per warp (scalar conflict-free frag loads)
        float acc[64];
        #pragma unroll
        for (int i = 0; i < 64; i++) acc[i] = 0.f;
        const float* aR0 = As + (w16 + g) * TS;
        const float* aR1 = aR0 + 8 * TS;
        #pragma unroll
        for (int kt = 0; kt < 8; kt++) {
            const int k0 = kt * 8 + tig;
            uint32_t a0 = __float_as_uint(aR0[k0]);
            uint32_t a1 = __float_as_uint(aR1[k0]);
            uint32_t a2 = __float_as_uint(aR0[k0 + 4]);
            uint32_t a3 = __float_as_uint(aR1[k0 + 4]);
            #pragma unroll
            for (int nt = 0; nt < 16; nt++) {
                const float* bw = Ws + (nt * 8 + g) * TS + k0;
                mma_tf32(acc[nt * 4], acc[nt * 4 + 1], acc[nt * 4 + 2], acc[nt * 4 + 3],
                         a0, a1, a2, a3,
                         __float_as_uint(bw[0]), __float_as_uint(bw[4]));
            }
        }

        // direct channel-last store
        {
            const int p0 = w16 + g, p1 = p0 + 8;
            float* o0 = g_t + tb2 + (size_t)(pix0 + ((p0 >> 5) << 8) + (p0 & 31)) * DW;
            float* o1 = g_t + tb2 + (size_t)(pix0 + ((p1 >> 5) << 8) + (p1 & 31)) * DW;
            #pragma unroll
            for (int nt = 0; nt < 16; nt++) {
                const int o = nt * 8 + 2 * tig;
                *reinterpret_cast<float2*>(o0 + o) =
                    make_float2(acc[nt * 4]     + b1s[o], acc[nt * 4 + 1] + b1s[o + 1]);
                *reinterpret_cast<float2*>(o1 + o) =
                    make_float2(acc[nt * 4 + 2] + b1s[o], acc[nt * 4 + 3] + b1s[o + 1]);
            }
        }
        __syncthreads();
    }
}

// =====================================================================
// K2: depthwise 3x3 + SimpleGate + per-cell channel sums (channel-last IO).
// =====================================================================
#define K2_SMEMB (16 * 1156 * 4)
__global__ __launch_bounds__(256, 2) void k2_dw_gate(
    const float* __restrict__ w2, const float* __restrict__ b2,
    const float* __restrict__ mod2)
{
    extern __shared__ float tiles[];          // [16][1156]
    __shared__ float w2s[16 * 9];
    __shared__ float b2s[16];
    __shared__ float redbuf[64];

    const int bidx = blockIdx.x;
    const int b    = bidx >> 9;
    const int cell = (bidx >> 3) & 63;
    const int grp  = bidx & 7;
    const int u    = cell >> 3, v = cell & 7;
    const int tid  = threadIdx.x;
    const int cbase = grp * 8;

    if (tid < 16) {
        const int ch = (tid < 8) ? (cbase + tid) : (64 + cbase + tid - 8);
        const float m = mod2[(size_t)(b * DW + ch) * 64 + cell];
        float ss = 0.f;
        float wv[9];
        #pragma unroll
        for (int k = 0; k < 9; k++) { wv[k] = w2[ch * 9 + k] * m; ss += wv[k] * wv[k]; }
        const float rr = rsqrtf(ss);
        #pragma unroll
        for (int k = 0; k < 9; k++) w2s[tid * 9 + k] = wv[k] * rr;
        b2s[tid] = b2[ch];
    }
    __syncthreads();

    const size_t tb2 = (size_t)b * HWPIX * DW;
    const int h0 = u * 32 - 1, w0 = v * 32 - 1;

    for (int i = tid; i < 1156; i += 256) {
        const int ih = i / 34, iw = i - ih * 34;
        const int hh = h0 + ih, ww2 = w0 + iw;
        float4 qa0, qa1, qg0, qg1;
        if ((hh >= 0) & (hh < HH) & (ww2 >= 0) & (ww2 < WW)) {
            const float* bp = g_t + tb2 + (size_t)(hh * WW + ww2) * DW;
            qa0 = *reinterpret_cast<const float4*>(bp + cbase);
            qa1 = *reinterpret_cast<const float4*>(bp + cbase + 4);
            qg0 = *reinterpret_cast<const float4*>(bp + 64 + cbase);
            qg1 = *reinterpret_cast<const float4*>(bp + 64 + cbase + 4);
        } else {
            qa0 = qa1 = qg0 = qg1 = make_float4(0.f, 0.f, 0.f, 0.f);
        }
        tiles[0 * 1156 + i] = qa0.x;  tiles[1 * 1156 + i] = qa0.y;
        tiles[2 * 1156 + i] = qa0.z;  tiles[3 * 1156 + i] = qa0.w;
        tiles[4 * 1156 + i] = qa1.x;  tiles[5 * 1156 + i] = qa1.y;
        tiles[6 * 1156 + i] = qa1.z;  tiles[7 * 1156 + i] = qa1.w;
        tiles[8 * 1156 + i] = qg0.x;  tiles[9 * 1156 + i] = qg0.y;
        tiles[10 * 1156 + i] = qg0.z; tiles[11 * 1156 + i] = qg0.w;
        tiles[12 * 1156 + i] = qg1.x; tiles[13 * 1156 + i] = qg1.y;
        tiles[14 * 1156 + i] = qg1.z; tiles[15 * 1156 + i] = qg1.w;
    }
    __syncthreads();

    const int lane = tid & 31, warp = tid >> 5;
    const size_t ymb = (size_t)b * HWPIX * C;
    float csum[8];
    #pragma unroll
    for (int j = 0; j < 8; j++) csum[j] = 0.f;

    #pragma unroll
    for (int k = 0; k < 4; k++) {
        const int p = k * 256 + tid;
        const int ph = p >> 5, pw = p & 31;
        float ov[8];
        #pragma unroll
        for (int j = 0; j < 8; j++) {
            float a = b2s[j], gg = b2s[8 + j];
            const float* wA = w2s + j * 9;
            const float* wG = w2s + (8 + j) * 9;
            const float* tA = tiles + j * 1156;
            const float* tG = tiles + (8 + j) * 1156;
            #pragma unroll
            for (int dh = 0; dh < 3; dh++) {
                #pragma unroll
                for (int dw2 = 0; dw2 < 3; dw2++) {
                    const int ti = (ph + dh) * 34 + pw + dw2;
                    a += wA[dh * 3 + dw2] * tA[ti];
                    gg += wG[dh * 3 + dw2] * tG[ti];
                }
            }
            ov[j] = a * gg;
            csum[j] += ov[j];
        }
        float* yp = g_ymid + ymb + (size_t)((u * 32 + ph) * WW + v * 32 + pw) * C + cbase;
        *reinterpret_cast<float4*>(yp)     = make_float4(ov[0], ov[1], ov[2], ov[3]);
        *reinterpret_cast<float4*>(yp + 4) = make_float4(ov[4], ov[5], ov[6], ov[7]);
    }

    #pragma unroll
    for (int j = 0; j < 8; j++) {
        float ls = csum[j];
        for (int off = 16; off; off >>= 1) ls += __shfl_down_sync(0xffffffffu, ls, off);
        if (lane == 0) redbuf[j * 8 + warp] = ls;
    }
    __syncthreads();
    if (tid < 8) {
        float s = 0.f;
        #pragma unroll
        for (int i = 0; i < 8; i++) s += redbuf[tid * 8 + i];
        g_sums[((size_t)b * CELLS + cell) * C + cbase + tid] = s;
    }
}

// =====================================================================
// K4 (mma.sync tf32): SCA -> conv3 -> y1 -> folded-LN2 conv4+gate -> conv5 -> out
// grid=128, block=512, stride-68 smem, direct global IO in epilogues.
// =====================================================================
#define K4_AS    0                         // 256*TS (act -> zc)
#define K4_YS    (256*TS)                  // 256*TS (y1)
#define K4_W3    (2*256*TS)                // 64*TS
#define K4_W4    (K4_W3 + 64*TS)           // 128*TS
#define K4_W5    (K4_W4 + 128*TS)          // 64*TS
#define K4_MU    (K4_W5 + 64*TS)           // 256
#define K4_RS    (K4_MU + 256)             // 256
#define K4_SSM   (K4_RS + 256)             // 64
#define K4_B3    (K4_SSM + 64)             // 64
#define K4_BE    (K4_B3 + 64)              // 64
#define K4_B5    (K4_BE + 64)              // 64
#define K4_GA    (K4_B5 + 64)              // 64
#define K4_AW    (K4_GA + 64)              // 128
#define K4_BW    (K4_AW + 128)             // 128
#define K4_SMEMF (K4_BW + 128)
#define K4_SMEMB (K4_SMEMF * 4)

__global__ __launch_bounds__(512) void k4_tc(
    const float* __restrict__ x,
    const float* __restrict__ b3, const float* __restrict__ b5,
    const float* __restrict__ beta, const float* __restrict__ gamma,
    const float* __restrict__ scaw, const float* __restrict__ scab,
    float* __restrict__ out)
{
    extern __shared__ float sm[];
    float* As  = sm + K4_AS;
    float* Ys  = sm + K4_YS;
    float* w3s = sm + K4_W3;
    float* w4s = sm + K4_W4;
    float* w5s = sm + K4_W5;
    float* muA = sm + K4_MU;
    float* rsA = sm + K4_RS;
    float* ssm = sm + K4_SSM;
    float* b3s = sm + K4_B3;
    float* bes = sm + K4_BE;
    float* b5s = sm + K4_B5;
    float* gas = sm + K4_GA;
    float* Aw  = sm + K4_AW;
    float* Bw  = sm + K4_BW;

    const int tid = threadIdx.x;
    const int wid = tid >> 5, lane = tid & 31;
    const int g = lane >> 2, tig = lane & 3;
    const int cta = blockIdx.x;
    const int b = cta >> 6, cell = cta & 63;
    const int u = cell >> 3, v = cell & 7;

    // ---- SCA in prologue (muA/rsA as scratch) ----
    if (tid < 256) {
        const int c = tid & 63, seg = tid >> 6;
        float s = 0.f;
        #pragma unroll 4
        for (int cl = seg * 16; cl < seg * 16 + 16; cl++)
            s += g_sums[((size_t)b * CELLS + cl) * C + c];
        muA[tid] = s;
    }
    // ---- stage weights (tf32, stride-68, float4) ----
    const float* cellw = g_wd + ((size_t)(b * 64 + cell)) * PERCELL;
    for (int i = tid; i < 1024; i += 512) {
        int o = i >> 4, m4 = (i & 15) * 4;
        float4 q3 = *reinterpret_cast<const float4*>(cellw + W3OFF + o * 64 + m4);
        float4 q5 = *reinterpret_cast<const float4*>(cellw + W5OFF + o * 64 + m4);
        *reinterpret_cast<float4*>(w3s + o * TS + m4) =
            make_float4(tf32f(q3.x), tf32f(q3.y), tf32f(q3.z), tf32f(q3.w));
        *reinterpret_cast<float4*>(w5s + o * TS + m4) =
            make_float4(tf32f(q5.x), tf32f(q5.y), tf32f(q5.z), tf32f(q5.w));
    }
    for (int i = tid; i < 2048; i += 512) {
        int o = i >> 4, m4 = (i & 15) * 4;
        float4 q = *reinterpret_cast<const float4*>(cellw + W4OFF + o * 64 + m4);
        *reinterpret_cast<float4*>(w4s + o * TS + m4) =
            make_float4(tf32f(q.x), tf32f(q.y), tf32f(q.z), tf32f(q.w));
    }
    if (tid < 64) {
        b3s[tid] = b3[tid];
        bes[tid] = beta[tid];
        b5s[tid] = b5[tid];
        gas[tid] = gamma[tid];
    }
    if (tid < 128) { Aw[tid] = cellw[AOFF + tid]; Bw[tid] = cellw[BOFF + tid]; }
    __syncthreads();
    if (tid < 64)
        rsA[tid] = (muA[tid] + muA[64 + tid] + muA[128 + tid] + muA[192 + tid]) * (1.f / (float)HWPIX);
    __syncthreads();
    if (tid < 64) {
        float acc = scab[tid];
        #pragma unroll 8
        for (int cc = 0; cc < 64; cc++) acc += scaw[tid * 64 + cc] * rsA[cc];
        ssm[tid] = acc;
    }
    __syncthreads();

    const size_t xbase = (size_t)b * C * HWPIX;
    const size_t ymb   = (size_t)b * HWPIX * C;
    const int w16 = wid * 16;
    const int p0 = w16 + g, p1 = p0 + 8;

    #pragma unroll 1
    for (int t = 0; t < 4; t++) {
        const int pix0 = (u * 32 + t * 8) * WW + v * 32;
        const int gp0 = pix0 + ((p0 >> 5) << 8) + (p0 & 31);
        const int gp1 = pix0 + ((p1 >> 5) << 8) + (p1 & 31);

        // act = ymid*s staging (float4, conflict-free)
        for (int i = tid; i < 4096; i += 512) {
            const int p = i >> 4, m4 = (i & 15) * 4;
            const int gp = pix0 + ((p >> 5) << 8) + (p & 31);
            float4 y = *reinterpret_cast<const float4*>(g_ymid + ymb + (size_t)gp * C + m4);
            *reinterpret_cast<float4*>(As + p * TS + m4) = make_float4(
                tf32f(y.x * ssm[m4]),     tf32f(y.y * ssm[m4 + 1]),
                tf32f(y.z * ssm[m4 + 2]), tf32f(y.w * ssm[m4 + 3]));
        }
        __syncthreads();

        const float* aR0 = As + p0 * TS;
        const float* aR1 = aR0 + 8 * TS;
        const float* yR0 = Ys + p0 * TS;
        const float* yR1 = yR0 + 8 * TS;

        // ---- GEMM1: conv3 (N=64) ; epilogue loads x DIRECT, y1 -> Ys ----
        {
            float acc[32];
            #pragma unroll
            for (int i = 0; i < 32; i++) acc[i] = 0.f;
            #pragma unroll
            for (int kt = 0; kt < 8; kt++) {
                const int k0 = kt * 8 + tig;
                uint32_t a0 = __float_as_uint(aR0[k0]);
                uint32_t a1 = __float_as_uint(aR1[k0]);
                uint32_t a2 = __float_as_uint(aR0[k0 + 4]);
                uint32_t a3 = __float_as_uint(aR1[k0 + 4]);
                #pragma unroll
                for (int nt = 0; nt < 8; nt++) {
                    const float* bw = w3s + (nt * 8 + g) * TS + k0;
                    mma_tf32(acc[nt * 4], acc[nt * 4 + 1], acc[nt * 4 + 2], acc[nt * 4 + 3],
                             a0, a1, a2, a3,
                             __float_as_uint(bw[0]), __float_as_uint(bw[4]));
                }
            }
            #pragma unroll
            for (int nt = 0; nt < 8; nt++) {
                const int c = nt * 8 + 2 * tig;
                const float* xp0 = x + xbase + (size_t)c * HWPIX;
                const float x00 = xp0[gp0], x10 = xp0[HWPIX + gp0];
                const float x01 = xp0[gp1], x11 = xp0[HWPIX + gp1];
                *reinterpret_cast<float2*>(Ys + p0 * TS + c) = make_float2(
                    x00 + (acc[nt * 4]     + b3s[c])     * bes[c],
                    x10 + (acc[nt * 4 + 1] + b3s[c + 1]) * bes[c + 1]);
                *reinterpret_cast<float2*>(Ys + p1 * TS + c) = make_float2(
                    x01 + (acc[nt * 4 + 2] + b3s[c])     * bes[c],
                    x11 + (acc[nt * 4 + 3] + b3s[c + 1]) * bes[c + 1]);
            }
        }
        __syncthreads();

        // ---- LN2 stats per pixel (float4 conflict-free) ----
        if (tid < 256) {
            const float* row = Ys + tid * TS;
            float s = 0.f, sq = 0.f;
            #pragma unroll
            for (int m = 0; m < 16; m++) {
                float4 r = reinterpret_cast<const float4*>(row)[m];
                s  += r.x + r.y + r.z + r.w;
                sq += r.x * r.x + r.y * r.y + r.z * r.z + r.w * r.w;
            }
            const float mu = s * (1.f / 64.f);
            muA[tid] = mu;
            rsA[tid] = rsqrtf(sq * (1.f / 64.f) - mu * mu + 1e-6f);
        }
        __syncthreads();

        // ---- GEMM2: conv4 (N=128, LN folded) + gate -> As ----
        {
            float acc[64];
            #pragma unroll
            for (int i = 0; i < 64; i++) acc[i] = 0.f;
            #pragma unroll
            for (int kt = 0; kt < 8; kt++) {
                const int k0 = kt * 8 + tig;
                uint32_t a0 = __float_as_uint(tf32f(yR0[k0]));
                uint32_t a1 = __float_as_uint(tf32f(yR1[k0]));
                uint32_t a2 = __float_as_uint(tf32f(yR0[k0 + 4]));
                uint32_t a3 = __float_as_uint(tf32f(yR1[k0 + 4]));
                #pragma unroll
                for (int nt = 0; nt < 16; nt++) {
                    const float* bw = w4s + (nt * 8 + g) * TS + k0;
                    mma_tf32(acc[nt * 4], acc[nt * 4 + 1], acc[nt * 4 + 2], acc[nt * 4 + 3],
                             a0, a1, a2, a3,
                             __float_as_uint(bw[0]), __float_as_uint(bw[4]));
                }
            }
            const float mu0 = muA[p0], rs0 = rsA[p0];
            const float mu1 = muA[p1], rs1 = rsA[p1];
            #pragma unroll
            for (int nt = 0; nt < 8; nt++) {
                const int c = nt * 8 + 2 * tig;
                float za00 = rs0 * (acc[nt * 4]           - mu0 * Aw[c])      + Bw[c];
                float za01 = rs0 * (acc[nt * 4 + 1]       - mu0 * Aw[c + 1])  + Bw[c + 1];
                float zg00 = rs0 * (acc[(nt + 8) * 4]     - mu0 * Aw[c + 64]) + Bw[c + 64];
                float zg01 = rs0 * (acc[(nt + 8) * 4 + 1] - mu0 * Aw[c + 65]) + Bw[c + 65];
                float za10 = rs1 * (acc[nt * 4 + 2]       - mu1 * Aw[c])      + Bw[c];
                float za11 = rs1 * (acc[nt * 4 + 3]       - mu1 * Aw[c + 1])  + Bw[c + 1];
                float zg10 = rs1 * (acc[(nt + 8) * 4 + 2] - mu1 * Aw[c + 64]) + Bw[c + 64];
                float zg11 = rs1 * (acc[(nt + 8) * 4 + 3] - mu1 * Aw[c + 65]) + Bw[c + 65];
                *reinterpret_cast<float2*>(As + p0 * TS + c) =
                    make_float2(tf32f(za00 * zg00), tf32f(za01 * zg01));
                *reinterpret_cast<float2*>(As + p1 * TS + c) =
                    make_float2(tf32f(za10 * zg10), tf32f(za11 * zg11));
            }
        }
        __syncthreads();

        // ---- GEMM3: conv5 (N=64) + final epilogue (direct STG) ----
        {
            float acc[32];
            #pragma unroll
            for (int i = 0; i < 32; i++) acc[i] = 0.f;
            #pragma unroll
            for (int kt = 0; kt < 8; kt++) {
                const int k0 = kt * 8 + tig;
                uint32_t a0 = __float_as_uint(aR0[k0]);
                uint32_t a1 = __float_as_uint(aR1[k0]);
                uint32_t a2 = __float_as_uint(aR0[k0 + 4]);
                uint32_t a3 = __float_as_uint(aR1[k0 + 4]);
                #pragma unroll
                for (int nt = 0; nt < 8; nt++) {
                    const float* bw = w5s + (nt * 8 + g) * TS + k0;
                    mma_tf32(acc[nt * 4], acc[nt * 4 + 1], acc[nt * 4 + 2], acc[nt * 4 + 3],
                             a0, a1, a2, a3,
                             __float_as_uint(bw[0]), __float_as_uint(bw[4]));
                }
            }
            #pragma unroll
            for (int nt = 0; nt < 8; nt++) {
                const int c = nt * 8 + 2 * tig;
                float2 y0 = *reinterpret_cast<const float2*>(Ys + p0 * TS + c);
                float2 y1 = *reinterpret_cast<const float2*>(Ys + p1 * TS + c);
                float* op0 = out + xbase + (size_t)c * HWPIX;
                op0[gp0]          = y0.x + (acc[nt * 4]     + b5s[c])     * gas[c];
                op0[HWPIX + gp0]  = y0.y + (acc[nt * 4 + 1] + b5s[c + 1]) * gas[c + 1];
                op0[gp1]          = y1.x + (acc[nt * 4 + 2] + b5s[c])     * gas[c];
                op0[HWPIX + gp1]  = y1.y + (acc[nt * 4 + 3] + b5s[c + 1]) * gas[c + 1];
            }
        }
        __syncthreads();
    }
}

// =====================================================================
// launch
// =====================================================================
extern "C" void kernel_launch(void* const* d_in, const int* in_sizes, int n_in,
                              void* d_out, int out_size)
{
    (void)in_sizes; (void)n_in; (void)out_size;
    const float* x     = (const float*)d_in[0];
    const float* w1    = (const float*)d_in[1];
    const float* b1    = (const float*)d_in[2];
    const float* w2    = (const float*)d_in[3];
    const float* b2    = (const float*)d_in[4];
    const float* w3    = (const float*)d_in[5];
    const float* b3    = (const float*)d_in[6];
    const float* scaw  = (const float*)d_in[7];
    const float* scab  = (const float*)d_in[8];
    const float* w4    = (const float*)d_in[9];
    const float* b4    = (const float*)d_in[10];
    const float* w5    = (const float*)d_in[11];
    const float* b5    = (const float*)d_in[12];
    const float* n1w   = (const float*)d_in[13];
    const float* n1b   = (const float*)d_in[14];
    const float* n2w   = (const float*)d_in[15];
    const float* n2b   = (const float*)d_in[16];
    const float* beta  = (const float*)d_in[17];
    const float* gamma = (const float*)d_in[18];
    const float* mod1  = (const float*)d_in[19];
    const float* mod2  = (const float*)d_in[20];
    const float* mod3  = (const float*)d_in[21];
    const float* mod4  = (const float*)d_in[22];
    const float* mod5  = (const float*)d_in[23];
    float* out = (float*)d_out;

    cudaFuncSetAttribute(k1_tc, cudaFuncAttributeMaxDynamicSharedMemorySize, K1_SMEMB);
    cudaFuncSetAttribute(k2_dw_gate, cudaFuncAttributeMaxDynamicSharedMemorySize, K2_SMEMB);
    cudaFuncSetAttribute(k4_tc, cudaFuncAttributeMaxDynamicSharedMemorySize, K4_SMEMB);

    k0_demod<<<2 * 384, 256>>>(w1, w3, w4, w5, b4, n2w, n2b, mod1, mod3, mod4, mod5);
    k1_tc<<<BATCH * CELLS, 512, K1_SMEMB>>>(x, b1, n1w, n1b);
    k2_dw_gate<<<1024, 256, K2_SMEMB>>>(w2, b2, mod2);
    k4_tc<<<BATCH * CELLS, 512, K4_SMEMB>>>(x, b3, b5, beta, gamma, scaw, scab, out);
}

// round 10
// speedup vs baseline: 2.4757x; 1.1169x over previous
#include <cuda_runtime.h>
#include <cuda_bf16.h>
#include <cstdint>

// ---------------- problem constants ----------------
#define BATCH 2
#define C 64
#define DW 128
#define HH 256
#define WW 256
#define HWPIX 65536
#define CELLS 64
#define TSU 36         // u32 row stride for bf16 operand tiles (36 % 32 == 4)
#define TSF 68         // f32 row stride (68 % 32 == 4)
// per-cell demod weight scratch layout
#define W1OFF 0        // 128x64
#define W3OFF 8192     // 64x64
#define W4OFF 12288    // 128x64 (n2w-folded)
#define W5OFF 20480    // 64x64
#define AOFF  24576    // 128
#define BOFF  24704    // 128
#define PERCELL 24832

// ---------------- scratch ----------------
static __device__ float g_t[(size_t)BATCH * HWPIX * DW];     // channel-last
static __device__ float g_ymid[(size_t)BATCH * HWPIX * C];   // channel-last
static __device__ float g_sums[BATCH * CELLS * C];
static __device__ float g_wd[(size_t)BATCH * CELLS * PERCELL];

// ---------------- helpers ----------------
__device__ __forceinline__ uint32_t bfpack(float lo, float hi) {
    __nv_bfloat162 h = __floats2bfloat162_rn(lo, hi);   // x = lo (low half)
    return *reinterpret_cast<uint32_t*>(&h);
}
__device__ __forceinline__ void mma_bf16(float& d0, float& d1, float& d2, float& d3,
                                         uint32_t a0, uint32_t a1, uint32_t a2, uint32_t a3,
                                         uint32_t b0, uint32_t b1) {
    asm volatile(
        "mma.sync.aligned.m16n8k16.row.col.f32.bf16.bf16.f32 "
        "{%0,%1,%2,%3},{%4,%5,%6,%7},{%8,%9},{%0,%1,%2,%3};"
        : "+f"(d0), "+f"(d1), "+f"(d2), "+f"(d3)
        : "r"(a0), "r"(a1), "r"(a2), "r"(a3), "r"(b0), "r"(b1));
}

// =====================================================================
// K0: demodulate all 1x1 conv weights once per (b, cell, output row).
// =====================================================================
__global__ __launch_bounds__(256) void k0_demod(
    const float* __restrict__ w1, const float* __restrict__ w3,
    const float* __restrict__ w4, const float* __restrict__ w5,
    const float* __restrict__ b4,
    const float* __restrict__ n2w, const float* __restrict__ n2b,
    const float* __restrict__ mod1, const float* __restrict__ mod3,
    const float* __restrict__ mod4, const float* __restrict__ mod5)
{
    __shared__ float tile[4096];
    __shared__ float psA[256];
    __shared__ float psB[256];
    __shared__ float ri[64];

    const int bid = blockIdx.x;
    const int b   = (bid >= 384) ? 1 : 0;
    const int rid = bid - 384 * b;
    const int tid = threadIdx.x;

    const float* wrow; const float* mblk; int dstoff; int isW4 = 0; int o;
    if (rid < 128)      { o = rid;       wrow = w1 + o * 64; mblk = mod1 + ((size_t)(b * 128 + o) << 12); dstoff = W1OFF + o * 64; }
    else if (rid < 192) { o = rid - 128; wrow = w3 + o * 64; mblk = mod3 + ((size_t)(b * 64  + o) << 12); dstoff = W3OFF + o * 64; }
    else if (rid < 320) { o = rid - 192; wrow = w4 + o * 64; mblk = mod4 + ((size_t)(b * 128 + o) << 12); dstoff = W4OFF + o * 64; isW4 = 1; }
    else                { o = rid - 320; wrow = w5 + o * 64; mblk = mod5 + ((size_t)(b * 64  + o) << 12); dstoff = W5OFF + o * 64; }

    for (int i = tid; i < 1024; i += 256)
        reinterpret_cast<float4*>(tile)[i] = reinterpret_cast<const float4*>(mblk)[i];
    __syncthreads();

    const int cell = tid & 63, part = tid >> 6;
    const int c0 = part * 16;
    float wv[16];
    float ss = 0.f;
    #pragma unroll
    for (int j = 0; j < 16; j++) {
        float t = wrow[c0 + j] * tile[(c0 + j) * 64 + cell];
        wv[j] = t; ss += t * t;
    }
    psA[part * 64 + cell] = ss;
    __syncthreads();
    if (tid < 64) ri[tid] = rsqrtf(psA[tid] + psA[64 + tid] + psA[128 + tid] + psA[192 + tid]);
    __syncthreads();
    const float r = ri[cell];
    float* dbase = g_wd + ((size_t)(b * 64 + cell)) * PERCELL + dstoff;

    if (!isW4) {
        #pragma unroll
        for (int j = 0; j < 16; j++) dbase[c0 + j] = wv[j] * r;
    } else {
        float aA = 0.f, bB = 0.f;
        #pragma unroll
        for (int j = 0; j < 16; j++) {
            float wd = wv[j] * r;
            float wn = wd * n2w[c0 + j];
            dbase[c0 + j] = wn;
            aA += wn;
            bB += wd * n2b[c0 + j];
        }
        psA[part * 64 + cell] = aA;
        psB[part * 64 + cell] = bB;
        __syncthreads();
        if (tid < 64) {
            float* cw = g_wd + ((size_t)(b * 64 + tid)) * PERCELL;
            cw[AOFF + o] = psA[tid] + psA[64 + tid] + psA[128 + tid] + psA[192 + tid];
            cw[BOFF + o] = psB[tid] + psB[64 + tid] + psB[128 + tid] + psB[192 + tid] + b4[o];
        }
    }
}

// =====================================================================
// K1 (mma bf16 k16): LN1 + conv1x1 (64->128) per cell.
// grid=128, block=512; LN in regs -> bf16 smem; direct CL f32 stores.
// =====================================================================
#define K1_AB    0                         // 256*TSU u32 (bf16 act)
#define K1_WB    (256*TSU*4)               // 128*TSU u32
#define K1_B1    (K1_WB + 128*TSU*4)       // 128 f32
#define K1_N1W   (K1_B1 + 128*4)           // 64 f32
#define K1_N1B   (K1_N1W + 64*4)           // 64 f32
#define K1_SMEMB (K1_N1B + 64*4)

__global__ __launch_bounds__(512) void k1_tc(
    const float* __restrict__ x, const float* __restrict__ b1,
    const float* __restrict__ n1w, const float* __restrict__ n1b)
{
    extern __shared__ char smc[];
    uint32_t* Ab  = reinterpret_cast<uint32_t*>(smc + K1_AB);
    uint32_t* Wb  = reinterpret_cast<uint32_t*>(smc + K1_WB);
    float* b1s  = reinterpret_cast<float*>(smc + K1_B1);
    float* n1ws = reinterpret_cast<float*>(smc + K1_N1W);
    float* n1bs = reinterpret_cast<float*>(smc + K1_N1B);

    const int tid = threadIdx.x;
    const int wid = tid >> 5, lane = tid & 31;
    const int g = lane >> 2, tig = lane & 3;
    const int cta = blockIdx.x;
    const int b = cta >> 6, cell = cta & 63;
    const int u = cell >> 3, v = cell & 7;

    const float* cellw = g_wd + ((size_t)(b * 64 + cell)) * PERCELL;
    for (int i = tid; i < 2048; i += 512) {      // 128 rows x 16 float4
        int o = i >> 4, m = i & 15;
        float4 q = *reinterpret_cast<const float4*>(cellw + W1OFF + o * 64 + 4 * m);
        *reinterpret_cast<uint2*>(Wb + o * TSU + 2 * m) =
            make_uint2(bfpack(q.x, q.y), bfpack(q.z, q.w));
    }
    if (tid < 128) b1s[tid] = b1[tid];
    if (tid < 64) { n1ws[tid] = n1w[tid]; n1bs[tid] = n1b[tid]; }
    __syncthreads();

    const size_t xbase = (size_t)b * C * HWPIX;
    const size_t tb2   = (size_t)b * HWPIX * DW;
    const int w16 = wid * 16;
    const int p0 = w16 + g, p1 = p0 + 8;

    #pragma unroll 1
    for (int t = 0; t < 4; t++) {
        const int pix0 = (u * 32 + t * 8) * WW + v * 32;

        // LN per pixel (threads 0..255): load 64 ch (lane-coalesced), write bf16
        if (tid < 256) {
            const int gp = pix0 + ((tid >> 5) << 8) + (tid & 31);
            float va[64];
            float s = 0.f, sq = 0.f;
            #pragma unroll
            for (int ch = 0; ch < 64; ch++) {
                float tv = x[xbase + (size_t)ch * HWPIX + gp];
                va[ch] = tv; s += tv; sq += tv * tv;
            }
            const float mu = s * (1.f / 64.f);
            const float rstd = rsqrtf(sq * (1.f / 64.f) - mu * mu + 1e-6f);
            uint32_t* row = Ab + tid * TSU;
            #pragma unroll
            for (int m = 0; m < 8; m++) {
                const int c = 8 * m;
                uint4 q = make_uint4(
                    bfpack((va[c]     - mu) * rstd * n1ws[c]     + n1bs[c],
                           (va[c + 1] - mu) * rstd * n1ws[c + 1] + n1bs[c + 1]),
                    bfpack((va[c + 2] - mu) * rstd * n1ws[c + 2] + n1bs[c + 2],
                           (va[c + 3] - mu) * rstd * n1ws[c + 3] + n1bs[c + 3]),
                    bfpack((va[c + 4] - mu) * rstd * n1ws[c + 4] + n1bs[c + 4],
                           (va[c + 5] - mu) * rstd * n1ws[c + 5] + n1bs[c + 5]),
                    bfpack((va[c + 6] - mu) * rstd * n1ws[c + 6] + n1bs[c + 6],
                           (va[c + 7] - mu) * rstd * n1ws[c + 7] + n1bs[c + 7]));
                *reinterpret_cast<uint4*>(row + 4 * m) = q;
            }
        }
        __syncthreads();

        // GEMM: 16 pix x 128 out per warp, 4 k16 steps
        float acc[64];
        #pragma unroll
        for (int i = 0; i < 64; i++) acc[i] = 0.f;
        const uint32_t* aR0 = Ab + p0 * TSU;
        const uint32_t* aR1 = Ab + p1 * TSU;
        #pragma unroll
        for (int kt = 0; kt < 4; kt++) {
            const int k0 = kt * 8 + tig;
            uint32_t a0 = aR0[k0], a1 = aR1[k0], a2 = aR0[k0 + 4], a3 = aR1[k0 + 4];
            #pragma unroll
            for (int nt = 0; nt < 16; nt++) {
                const uint32_t* bw = Wb + (nt * 8 + g) * TSU + k0;
                mma_bf16(acc[nt * 4], acc[nt * 4 + 1], acc[nt * 4 + 2], acc[nt * 4 + 3],
                         a0, a1, a2, a3, bw[0], bw[4]);
            }
        }

        // direct channel-last f32 store
        {
            float* o0 = g_t + tb2 + (size_t)(pix0 + ((p0 >> 5) << 8) + (p0 & 31)) * DW;
            float* o1 = g_t + tb2 + (size_t)(pix0 + ((p1 >> 5) << 8) + (p1 & 31)) * DW;
            #pragma unroll
            for (int nt = 0; nt < 16; nt++) {
                const int o = nt * 8 + 2 * tig;
                *reinterpret_cast<float2*>(o0 + o) =
                    make_float2(acc[nt * 4]     + b1s[o], acc[nt * 4 + 1] + b1s[o + 1]);
                *reinterpret_cast<float2*>(o1 + o) =
                    make_float2(acc[nt * 4 + 2] + b1s[o], acc[nt * 4 + 3] + b1s[o + 1]);
            }
        }
        __syncthreads();
    }
}

// =====================================================================
// K2: depthwise 3x3 + SimpleGate + per-cell channel sums (channel-last IO).
// =====================================================================
#define K2_SMEMB (16 * 1156 * 4)
__global__ __launch_bounds__(256, 2) void k2_dw_gate(
    const float* __restrict__ w2, const float* __restrict__ b2,
    const float* __restrict__ mod2)
{
    extern __shared__ float tiles[];          // [16][1156]
    __shared__ float w2s[16 * 9];
    __shared__ float b2s[16];
    __shared__ float redbuf[64];

    const int bidx = blockIdx.x;
    const int b    = bidx >> 9;
    const int cell = (bidx >> 3) & 63;
    const int grp  = bidx & 7;
    const int u    = cell >> 3, v = cell & 7;
    const int tid  = threadIdx.x;
    const int cbase = grp * 8;

    if (tid < 16) {
        const int ch = (tid < 8) ? (cbase + tid) : (64 + cbase + tid - 8);
        const float m = mod2[(size_t)(b * DW + ch) * 64 + cell];
        float ss = 0.f;
        float wv[9];
        #pragma unroll
        for (int k = 0; k < 9; k++) { wv[k] = w2[ch * 9 + k] * m; ss += wv[k] * wv[k]; }
        const float rr = rsqrtf(ss);
        #pragma unroll
        for (int k = 0; k < 9; k++) w2s[tid * 9 + k] = wv[k] * rr;
        b2s[tid] = b2[ch];
    }
    __syncthreads();

    const size_t tb2 = (size_t)b * HWPIX * DW;
    const int h0 = u * 32 - 1, w0 = v * 32 - 1;

    for (int i = tid; i < 1156; i += 256) {
        const int ih = i / 34, iw = i - ih * 34;
        const int hh = h0 + ih, ww2 = w0 + iw;
        float4 qa0, qa1, qg0, qg1;
        if ((hh >= 0) & (hh < HH) & (ww2 >= 0) & (ww2 < WW)) {
            const float* bp = g_t + tb2 + (size_t)(hh * WW + ww2) * DW;
            qa0 = *reinterpret_cast<const float4*>(bp + cbase);
            qa1 = *reinterpret_cast<const float4*>(bp + cbase + 4);
            qg0 = *reinterpret_cast<const float4*>(bp + 64 + cbase);
            qg1 = *reinterpret_cast<const float4*>(bp + 64 + cbase + 4);
        } else {
            qa0 = qa1 = qg0 = qg1 = make_float4(0.f, 0.f, 0.f, 0.f);
        }
        tiles[0 * 1156 + i] = qa0.x;  tiles[1 * 1156 + i] = qa0.y;
        tiles[2 * 1156 + i] = qa0.z;  tiles[3 * 1156 + i] = qa0.w;
        tiles[4 * 1156 + i] = qa1.x;  tiles[5 * 1156 + i] = qa1.y;
        tiles[6 * 1156 + i] = qa1.z;  tiles[7 * 1156 + i] = qa1.w;
        tiles[8 * 1156 + i] = qg0.x;  tiles[9 * 1156 + i] = qg0.y;
        tiles[10 * 1156 + i] = qg0.z; tiles[11 * 1156 + i] = qg0.w;
        tiles[12 * 1156 + i] = qg1.x; tiles[13 * 1156 + i] = qg1.y;
        tiles[14 * 1156 + i] = qg1.z; tiles[15 * 1156 + i] = qg1.w;
    }
    __syncthreads();

    const int lane = tid & 31, warp = tid >> 5;
    const size_t ymb = (size_t)b * HWPIX * C;
    float csum[8];
    #pragma unroll
    for (int j = 0; j < 8; j++) csum[j] = 0.f;

    #pragma unroll
    for (int k = 0; k < 4; k++) {
        const int p = k * 256 + tid;
        const int ph = p >> 5, pw = p & 31;
        float ov[8];
        #pragma unroll
        for (int j = 0; j < 8; j++) {
            float a = b2s[j], gg = b2s[8 + j];
            const float* wA = w2s + j * 9;
            const float* wG = w2s + (8 + j) * 9;
            const float* tA = tiles + j * 1156;
            const float* tG = tiles + (8 + j) * 1156;
            #pragma unroll
            for (int dh = 0; dh < 3; dh++) {
                #pragma unroll
                for (int dw2 = 0; dw2 < 3; dw2++) {
                    const int ti = (ph + dh) * 34 + pw + dw2;
                    a += wA[dh * 3 + dw2] * tA[ti];
                    gg += wG[dh * 3 + dw2] * tG[ti];
                }
            }
            ov[j] = a * gg;
            csum[j] += ov[j];
        }
        float* yp = g_ymid + ymb + (size_t)((u * 32 + ph) * WW + v * 32 + pw) * C + cbase;
        *reinterpret_cast<float4*>(yp)     = make_float4(ov[0], ov[1], ov[2], ov[3]);
        *reinterpret_cast<float4*>(yp + 4) = make_float4(ov[4], ov[5], ov[6], ov[7]);
    }

    #pragma unroll
    for (int j = 0; j < 8; j++) {
        float ls = csum[j];
        for (int off = 16; off; off >>= 1) ls += __shfl_down_sync(0xffffffffu, ls, off);
        if (lane == 0) redbuf[j * 8 + warp] = ls;
    }
    __syncthreads();
    if (tid < 8) {
        float s = 0.f;
        #pragma unroll
        for (int i = 0; i < 8; i++) s += redbuf[tid * 8 + i];
        g_sums[((size_t)b * CELLS + cell) * C + cbase + tid] = s;
    }
}

// =====================================================================
// K4 (mma bf16 k16): SCA -> conv3 -> y1 -> folded-LN2 conv4+gate -> conv5 -> out
// grid=128, block=512.
// =====================================================================
#define K4_AB    0                          // 256*TSU u32 (act -> zc, bf16)
#define K4_YB    (256*TSU*4)                // 256*TSU u32 (y1 bf16)
#define K4_YS    (K4_YB + 256*TSU*4)        // 256*TSF f32 (y1 f32)
#define K4_W3B   (K4_YS + 256*TSF*4)        // 64*TSU u32
#define K4_W4B   (K4_W3B + 64*TSU*4)        // 128*TSU u32
#define K4_W5B   (K4_W4B + 128*TSU*4)       // 64*TSU u32
#define K4_MU    (K4_W5B + 64*TSU*4)        // 256 f32
#define K4_RS    (K4_MU + 256*4)            // 256 f32
#define K4_SSM   (K4_RS + 256*4)            // 64
#define K4_B3    (K4_SSM + 64*4)            // 64
#define K4_BE    (K4_B3 + 64*4)             // 64
#define K4_B5    (K4_BE + 64*4)             // 64
#define K4_GA    (K4_B5 + 64*4)             // 64
#define K4_AW    (K4_GA + 64*4)             // 128
#define K4_BW    (K4_AW + 128*4)            // 128
#define K4_SMEMB (K4_BW + 128*4)

__global__ __launch_bounds__(512) void k4_tc(
    const float* __restrict__ x,
    const float* __restrict__ b3, const float* __restrict__ b5,
    const float* __restrict__ beta, const float* __restrict__ gamma,
    const float* __restrict__ scaw, const float* __restrict__ scab,
    float* __restrict__ out)
{
    extern __shared__ char smc[];
    uint32_t* Ab  = reinterpret_cast<uint32_t*>(smc + K4_AB);
    uint32_t* Yb  = reinterpret_cast<uint32_t*>(smc + K4_YB);
    float* Ys  = reinterpret_cast<float*>(smc + K4_YS);
    uint32_t* w3b = reinterpret_cast<uint32_t*>(smc + K4_W3B);
    uint32_t* w4b = reinterpret_cast<uint32_t*>(smc + K4_W4B);
    uint32_t* w5b = reinterpret_cast<uint32_t*>(smc + K4_W5B);
    float* muA = reinterpret_cast<float*>(smc + K4_MU);
    float* rsA = reinterpret_cast<float*>(smc + K4_RS);
    float* ssm = reinterpret_cast<float*>(smc + K4_SSM);
    float* b3s = reinterpret_cast<float*>(smc + K4_B3);
    float* bes = reinterpret_cast<float*>(smc + K4_BE);
    float* b5s = reinterpret_cast<float*>(smc + K4_B5);
    float* gas = reinterpret_cast<float*>(smc + K4_GA);
    float* Aw  = reinterpret_cast<float*>(smc + K4_AW);
    float* Bw  = reinterpret_cast<float*>(smc + K4_BW);

    const int tid = threadIdx.x;
    const int wid = tid >> 5, lane = tid & 31;
    const int g = lane >> 2, tig = lane & 3;
    const int cta = blockIdx.x;
    const int b = cta >> 6, cell = cta & 63;
    const int u = cell >> 3, v = cell & 7;

    // ---- SCA in prologue (muA/rsA as scratch) ----
    if (tid < 256) {
        const int c = tid & 63, seg = tid >> 6;
        float s = 0.f;
        #pragma unroll 4
        for (int cl = seg * 16; cl < seg * 16 + 16; cl++)
            s += g_sums[((size_t)b * CELLS + cl) * C + c];
        muA[tid] = s;
    }
    // ---- stage weights (bf16) ----
    const float* cellw = g_wd + ((size_t)(b * 64 + cell)) * PERCELL;
    for (int i = tid; i < 1024; i += 512) {
        int o = i >> 4, m = i & 15;
        float4 q3 = *reinterpret_cast<const float4*>(cellw + W3OFF + o * 64 + 4 * m);
        float4 q5 = *reinterpret_cast<const float4*>(cellw + W5OFF + o * 64 + 4 * m);
        *reinterpret_cast<uint2*>(w3b + o * TSU + 2 * m) =
            make_uint2(bfpack(q3.x, q3.y), bfpack(q3.z, q3.w));
        *reinterpret_cast<uint2*>(w5b + o * TSU + 2 * m) =
            make_uint2(bfpack(q5.x, q5.y), bfpack(q5.z, q5.w));
    }
    for (int i = tid; i < 2048; i += 512) {
        int o = i >> 4, m = i & 15;
        float4 q = *reinterpret_cast<const float4*>(cellw + W4OFF + o * 64 + 4 * m);
        *reinterpret_cast<uint2*>(w4b + o * TSU + 2 * m) =
            make_uint2(bfpack(q.x, q.y), bfpack(q.z, q.w));
    }
    if (tid < 64) {
        b3s[tid] = b3[tid];
        bes[tid] = beta[tid];
        b5s[tid] = b5[tid];
        gas[tid] = gamma[tid];
    }
    if (tid < 128) { Aw[tid] = cellw[AOFF + tid]; Bw[tid] = cellw[BOFF + tid]; }
    __syncthreads();
    if (tid < 64)
        rsA[tid] = (muA[tid] + muA[64 + tid] + muA[128 + tid] + muA[192 + tid]) * (1.f / (float)HWPIX);
    __syncthreads();
    if (tid < 64) {
        float acc = scab[tid];
        #pragma unroll 8
        for (int cc = 0; cc < 64; cc++) acc += scaw[tid * 64 + cc] * rsA[cc];
        ssm[tid] = acc;
    }
    __syncthreads();

    const size_t xbase = (size_t)b * C * HWPIX;
    const size_t ymb   = (size_t)b * HWPIX * C;
    const int w16 = wid * 16;
    const int p0 = w16 + g, p1 = p0 + 8;

    #pragma unroll 1
    for (int t = 0; t < 4; t++) {
        const int pix0 = (u * 32 + t * 8) * WW + v * 32;
        const int gp0 = pix0 + ((p0 >> 5) << 8) + (p0 & 31);
        const int gp1 = pix0 + ((p1 >> 5) << 8) + (p1 & 31);

        // act = ymid*s staging (bf16)
        for (int i = tid; i < 4096; i += 512) {
            const int p = i >> 4, m = i & 15;
            const int gp = pix0 + ((p >> 5) << 8) + (p & 31);
            float4 y = *reinterpret_cast<const float4*>(g_ymid + ymb + (size_t)gp * C + 4 * m);
            const int c0 = 4 * m;
            *reinterpret_cast<uint2*>(Ab + p * TSU + 2 * m) = make_uint2(
                bfpack(y.x * ssm[c0],     y.y * ssm[c0 + 1]),
                bfpack(y.z * ssm[c0 + 2], y.w * ssm[c0 + 3]));
        }
        __syncthreads();

        const uint32_t* aR0 = Ab + p0 * TSU;
        const uint32_t* aR1 = Ab + p1 * TSU;
        const uint32_t* yR0 = Yb + p0 * TSU;
        const uint32_t* yR1 = Yb + p1 * TSU;

        // ---- GEMM1: conv3 (N=64); epilogue loads x direct, y1 -> Ys + Yb ----
        {
            float acc[32];
            #pragma unroll
            for (int i = 0; i < 32; i++) acc[i] = 0.f;
            #pragma unroll
            for (int kt = 0; kt < 4; kt++) {
                const int k0 = kt * 8 + tig;
                uint32_t a0 = aR0[k0], a1 = aR1[k0], a2 = aR0[k0 + 4], a3 = aR1[k0 + 4];
                #pragma unroll
                for (int nt = 0; nt < 8; nt++) {
                    const uint32_t* bw = w3b + (nt * 8 + g) * TSU + k0;
                    mma_bf16(acc[nt * 4], acc[nt * 4 + 1], acc[nt * 4 + 2], acc[nt * 4 + 3],
                             a0, a1, a2, a3, bw[0], bw[4]);
                }
            }
            #pragma unroll
            for (int nt = 0; nt < 8; nt++) {
                const int c = nt * 8 + 2 * tig;
                const float* xp0 = x + xbase + (size_t)c * HWPIX;
                const float y00 = xp0[gp0]         + (acc[nt * 4]     + b3s[c])     * bes[c];
                const float y10 = xp0[HWPIX + gp0] + (acc[nt * 4 + 1] + b3s[c + 1]) * bes[c + 1];
                const float y01 = xp0[gp1]         + (acc[nt * 4 + 2] + b3s[c])     * bes[c];
                const float y11 = xp0[HWPIX + gp1] + (acc[nt * 4 + 3] + b3s[c + 1]) * bes[c + 1];
                *reinterpret_cast<float2*>(Ys + p0 * TSF + c) = make_float2(y00, y10);
                *reinterpret_cast<float2*>(Ys + p1 * TSF + c) = make_float2(y01, y11);
                Yb[p0 * TSU + 4 * nt + tig] = bfpack(y00, y10);
                Yb[p1 * TSU + 4 * nt + tig] = bfpack(y01, y11);
            }
        }
        __syncthreads();

        // ---- LN2 stats per pixel ----
        if (tid < 256) {
            const float* row = Ys + tid * TSF;
            float s = 0.f, sq = 0.f;
            #pragma unroll
            for (int m = 0; m < 16; m++) {
                float4 r = reinterpret_cast<const float4*>(row)[m];
                s  += r.x + r.y + r.z + r.w;
                sq += r.x * r.x + r.y * r.y + r.z * r.z + r.w * r.w;
            }
            const float mu = s * (1.f / 64.f);
            muA[tid] = mu;
            rsA[tid] = rsqrtf(sq * (1.f / 64.f) - mu * mu + 1e-6f);
        }
        __syncthreads();

        // ---- GEMM2: conv4 (N=128, LN folded) + gate -> Ab (bf16 zc) ----
        {
            float acc[64];
            #pragma unroll
            for (int i = 0; i < 64; i++) acc[i] = 0.f;
            #pragma unroll
            for (int kt = 0; kt < 4; kt++) {
                const int k0 = kt * 8 + tig;
                uint32_t a0 = yR0[k0], a1 = yR1[k0], a2 = yR0[k0 + 4], a3 = yR1[k0 + 4];
                #pragma unroll
                for (int nt = 0; nt < 16; nt++) {
                    const uint32_t* bw = w4b + (nt * 8 + g) * TSU + k0;
                    mma_bf16(acc[nt * 4], acc[nt * 4 + 1], acc[nt * 4 + 2], acc[nt * 4 + 3],
                             a0, a1, a2, a3, bw[0], bw[4]);
                }
            }
            const float mu0 = muA[p0], rs0 = rsA[p0];
            const float mu1 = muA[p1], rs1 = rsA[p1];
            #pragma unroll
            for (int nt = 0; nt < 8; nt++) {
                const int c = nt * 8 + 2 * tig;
                float za00 = rs0 * (acc[nt * 4]           - mu0 * Aw[c])      + Bw[c];
                float za01 = rs0 * (acc[nt * 4 + 1]       - mu0 * Aw[c + 1])  + Bw[c + 1];
                float zg00 = rs0 * (acc[(nt + 8) * 4]     - mu0 * Aw[c + 64]) + Bw[c + 64];
                float zg01 = rs0 * (acc[(nt + 8) * 4 + 1] - mu0 * Aw[c + 65]) + Bw[c + 65];
                float za10 = rs1 * (acc[nt * 4 + 2]       - mu1 * Aw[c])      + Bw[c];
                float za11 = rs1 * (acc[nt * 4 + 3]       - mu1 * Aw[c + 1])  + Bw[c + 1];
                float zg10 = rs1 * (acc[(nt + 8) * 4 + 2] - mu1 * Aw[c + 64]) + Bw[c + 64];
                float zg11 = rs1 * (acc[(nt + 8) * 4 + 3] - mu1 * Aw[c + 65]) + Bw[c + 65];
                Ab[p0 * TSU + 4 * nt + tig] = bfpack(za00 * zg00, za01 * zg01);
                Ab[p1 * TSU + 4 * nt + tig] = bfpack(za10 * zg10, za11 * zg11);
            }
        }
        __syncthreads();

        // ---- GEMM3: conv5 (N=64) + final epilogue (direct STG) ----
        {
            float acc[32];
            #pragma unroll
            for (int i = 0; i < 32; i++) acc[i] = 0.f;
            #pragma unroll
            for (int kt = 0; kt < 4; kt++) {
                const int k0 = kt * 8 + tig;
                uint32_t a0 = aR0[k0], a1 = aR1[k0], a2 = aR0[k0 + 4], a3 = aR1[k0 + 4];
                #pragma unroll
                for (int nt = 0; nt < 8; nt++) {
                    const uint32_t* bw = w5b + (nt * 8 + g) * TSU + k0;
                    mma_bf16(acc[nt * 4], acc[nt * 4 + 1], acc[nt * 4 + 2], acc[nt * 4 + 3],
                             a0, a1, a2, a3, bw[0], bw[4]);
                }
            }
            #pragma unroll
            for (int nt = 0; nt < 8; nt++) {
                const int c = nt * 8 + 2 * tig;
                float2 y0 = *reinterpret_cast<const float2*>(Ys + p0 * TSF + c);
                float2 y1 = *reinterpret_cast<const float2*>(Ys + p1 * TSF + c);
                float* op0 = out + xbase + (size_t)c * HWPIX;
                op0[gp0]          = y0.x + (acc[nt * 4]     + b5s[c])     * gas[c];
                op0[HWPIX + gp0]  = y0.y + (acc[nt * 4 + 1] + b5s[c + 1]) * gas[c + 1];
                op0[gp1]          = y1.x + (acc[nt * 4 + 2] + b5s[c])     * gas[c];
                op0[HWPIX + gp1]  = y1.y + (acc[nt * 4 + 3] + b5s[c + 1]) * gas[c + 1];
            }
        }
        __syncthreads();
    }
}

// =====================================================================
// launch
// =====================================================================
extern "C" void kernel_launch(void* const* d_in, const int* in_sizes, int n_in,
                              void* d_out, int out_size)
{
    (void)in_sizes; (void)n_in; (void)out_size;
    const float* x     = (const float*)d_in[0];
    const float* w1    = (const float*)d_in[1];
    const float* b1    = (const float*)d_in[2];
    const float* w2    = (const float*)d_in[3];
    const float* b2    = (const float*)d_in[4];
    const float* w3    = (const float*)d_in[5];
    const float* b3    = (const float*)d_in[6];
    const float* scaw  = (const float*)d_in[7];
    const float* scab  = (const float*)d_in[8];
    const float* w4    = (const float*)d_in[9];
    const float* b4    = (const float*)d_in[10];
    const float* w5    = (const float*)d_in[11];
    const float* b5    = (const float*)d_in[12];
    const float* n1w   = (const float*)d_in[13];
    const float* n1b   = (const float*)d_in[14];
    const float* n2w   = (const float*)d_in[15];
    const float* n2b   = (const float*)d_in[16];
    const float* beta  = (const float*)d_in[17];
    const float* gamma = (const float*)d_in[18];
    const float* mod1  = (const float*)d_in[19];
    const float* mod2  = (const float*)d_in[20];
    const float* mod3  = (const float*)d_in[21];
    const float* mod4  = (const float*)d_in[22];
    const float* mod5  = (const float*)d_in[23];
    float* out = (float*)d_out;

    cudaFuncSetAttribute(k1_tc, cudaFuncAttributeMaxDynamicSharedMemorySize, K1_SMEMB);
    cudaFuncSetAttribute(k2_dw_gate, cudaFuncAttributeMaxDynamicSharedMemorySize, K2_SMEMB);
    cudaFuncSetAttribute(k4_tc, cudaFuncAttributeMaxDynamicSharedMemorySize, K4_SMEMB);

    k0_demod<<<2 * 384, 256>>>(w1, w3, w4, w5, b4, n2w, n2b, mod1, mod3, mod4, mod5);
    k1_tc<<<BATCH * CELLS, 512, K1_SMEMB>>>(x, b1, n1w, n1b);
    k2_dw_gate<<<1024, 256, K2_SMEMB>>>(w2, b2, mod2);
    k4_tc<<<BATCH * CELLS, 512, K4_SMEMB>>>(x, b3, b5, beta, gamma, scaw, scab, out);
}

// round 11
// speedup vs baseline: 2.6964x; 1.0891x over previous
#include <cuda_runtime.h>
#include <cuda_bf16.h>
#include <cstdint>

// ---------------- problem constants ----------------
#define BATCH 2
#define C 64
#define DW 128
#define HH 256
#define WW 256
#define HWPIX 65536
#define CELLS 64
#define TSU 36         // u32 row stride for bf16 weight tiles (36 % 32 == 4)
// per-cell demod weight scratch layout
#define W1OFF 0        // 128x64
#define W3OFF 8192     // 64x64
#define W4OFF 12288    // 128x64 (n2w-folded)
#define W5OFF 20480    // 64x64
#define AOFF  24576    // 128
#define BOFF  24704    // 128
#define PERCELL 24832

// ---------------- scratch ----------------
static __device__ float g_t[(size_t)BATCH * HWPIX * DW];     // channel-last
static __device__ float g_ymid[(size_t)BATCH * HWPIX * C];   // channel-last
static __device__ float g_sums[BATCH * CELLS * C];
static __device__ float g_wd[(size_t)BATCH * CELLS * PERCELL];

// ---------------- helpers ----------------
__device__ __forceinline__ uint32_t bfpack(float lo, float hi) {
    __nv_bfloat162 h = __floats2bfloat162_rn(lo, hi);
    return *reinterpret_cast<uint32_t*>(&h);
}
__device__ __forceinline__ void mma_bf16(float& d0, float& d1, float& d2, float& d3,
                                         uint32_t a0, uint32_t a1, uint32_t a2, uint32_t a3,
                                         uint32_t b0, uint32_t b1) {
    asm volatile(
        "mma.sync.aligned.m16n8k16.row.col.f32.bf16.bf16.f32 "
        "{%0,%1,%2,%3},{%4,%5,%6,%7},{%8,%9},{%0,%1,%2,%3};"
        : "+f"(d0), "+f"(d1), "+f"(d2), "+f"(d3)
        : "r"(a0), "r"(a1), "r"(a2), "r"(a3), "r"(b0), "r"(b1));
}
__device__ __forceinline__ float qsum(float v) {   // sum over quad (tig=0..3)
    v += __shfl_xor_sync(0xffffffffu, v, 1);
    v += __shfl_xor_sync(0xffffffffu, v, 2);
    return v;
}

// =====================================================================
// K0: demodulate all 1x1 conv weights once per (b, cell, output row).
// =====================================================================
__global__ __launch_bounds__(256) void k0_demod(
    const float* __restrict__ w1, const float* __restrict__ w3,
    const float* __restrict__ w4, const float* __restrict__ w5,
    const float* __restrict__ b4,
    const float* __restrict__ n2w, const float* __restrict__ n2b,
    const float* __restrict__ mod1, const float* __restrict__ mod3,
    const float* __restrict__ mod4, const float* __restrict__ mod5)
{
    __shared__ float tile[4096];
    __shared__ float psA[256];
    __shared__ float psB[256];
    __shared__ float ri[64];

    const int bid = blockIdx.x;
    const int b   = (bid >= 384) ? 1 : 0;
    const int rid = bid - 384 * b;
    const int tid = threadIdx.x;

    const float* wrow; const float* mblk; int dstoff; int isW4 = 0; int o;
    if (rid < 128)      { o = rid;       wrow = w1 + o * 64; mblk = mod1 + ((size_t)(b * 128 + o) << 12); dstoff = W1OFF + o * 64; }
    else if (rid < 192) { o = rid - 128; wrow = w3 + o * 64; mblk = mod3 + ((size_t)(b * 64  + o) << 12); dstoff = W3OFF + o * 64; }
    else if (rid < 320) { o = rid - 192; wrow = w4 + o * 64; mblk = mod4 + ((size_t)(b * 128 + o) << 12); dstoff = W4OFF + o * 64; isW4 = 1; }
    else                { o = rid - 320; wrow = w5 + o * 64; mblk = mod5 + ((size_t)(b * 64  + o) << 12); dstoff = W5OFF + o * 64; }

    for (int i = tid; i < 1024; i += 256)
        reinterpret_cast<float4*>(tile)[i] = reinterpret_cast<const float4*>(mblk)[i];
    __syncthreads();

    const int cell = tid & 63, part = tid >> 6;
    const int c0 = part * 16;
    float wv[16];
    float ss = 0.f;
    #pragma unroll
    for (int j = 0; j < 16; j++) {
        float t = wrow[c0 + j] * tile[(c0 + j) * 64 + cell];
        wv[j] = t; ss += t * t;
    }
    psA[part * 64 + cell] = ss;
    __syncthreads();
    if (tid < 64) ri[tid] = rsqrtf(psA[tid] + psA[64 + tid] + psA[128 + tid] + psA[192 + tid]);
    __syncthreads();
    const float r = ri[cell];
    float* dbase = g_wd + ((size_t)(b * 64 + cell)) * PERCELL + dstoff;

    if (!isW4) {
        #pragma unroll
        for (int j = 0; j < 16; j++) dbase[c0 + j] = wv[j] * r;
    } else {
        float aA = 0.f, bB = 0.f;
        #pragma unroll
        for (int j = 0; j < 16; j++) {
            float wd = wv[j] * r;
            float wn = wd * n2w[c0 + j];
            dbase[c0 + j] = wn;
            aA += wn;
            bB += wd * n2b[c0 + j];
        }
        psA[part * 64 + cell] = aA;
        psB[part * 64 + cell] = bB;
        __syncthreads();
        if (tid < 64) {
            float* cw = g_wd + ((size_t)(b * 64 + tid)) * PERCELL;
            cw[AOFF + o] = psA[tid] + psA[64 + tid] + psA[128 + tid] + psA[192 + tid];
            cw[BOFF + o] = psB[tid] + psB[64 + tid] + psB[128 + tid] + psB[192 + tid] + b4[o];
        }
    }
}

// =====================================================================
// K1 (bf16 mma, fully register-resident): LN1 + conv1x1 (64->128).
// grid=128, block=512. x fragment-loaded from global; LN via quad shfl.
// No per-tile syncs.
// =====================================================================
#define K1_WB    0                         // 128*TSU u32
#define K1_B1    (K1_WB + 128*TSU*4)       // 128 f32
#define K1_N1W   (K1_B1 + 128*4)           // 64 f32
#define K1_N1B   (K1_N1W + 64*4)           // 64 f32
#define K1_SMEMB (K1_N1B + 64*4)

__global__ __launch_bounds__(512) void k1_tc(
    const float* __restrict__ x, const float* __restrict__ b1,
    const float* __restrict__ n1w, const float* __restrict__ n1b)
{
    extern __shared__ char smc[];
    uint32_t* Wb  = reinterpret_cast<uint32_t*>(smc + K1_WB);
    float* b1s  = reinterpret_cast<float*>(smc + K1_B1);
    float* n1ws = reinterpret_cast<float*>(smc + K1_N1W);
    float* n1bs = reinterpret_cast<float*>(smc + K1_N1B);

    const int tid = threadIdx.x;
    const int wid = tid >> 5, lane = tid & 31;
    const int g = lane >> 2, tig = lane & 3;
    const int cta = blockIdx.x;
    const int b = cta >> 6, cell = cta & 63;
    const int u = cell >> 3, v = cell & 7;

    const float* cellw = g_wd + ((size_t)(b * 64 + cell)) * PERCELL;
    for (int i = tid; i < 2048; i += 512) {
        int o = i >> 4, m = i & 15;
        float4 q = *reinterpret_cast<const float4*>(cellw + W1OFF + o * 64 + 4 * m);
        *reinterpret_cast<uint2*>(Wb + o * TSU + 2 * m) =
            make_uint2(bfpack(q.x, q.y), bfpack(q.z, q.w));
    }
    if (tid < 128) b1s[tid] = b1[tid];
    if (tid < 64) { n1ws[tid] = n1w[tid]; n1bs[tid] = n1b[tid]; }
    __syncthreads();

    const size_t xbase = (size_t)b * C * HWPIX;
    const size_t tb2   = (size_t)b * HWPIX * DW;
    const int w16 = wid * 16;
    const int p0 = w16 + g, p1 = p0 + 8;

    #pragma unroll 1
    for (int t = 0; t < 4; t++) {
        const int pix0 = (u * 32 + t * 8) * WW + v * 32;
        const int gp0 = pix0 + ((p0 >> 5) << 8) + (p0 & 31);
        const int gp1 = pix0 + ((p1 >> 5) << 8) + (p1 & 31);

        // fragment-load x: 16 channels per thread per pixel row
        // index 4kt+j <-> channel 16kt+2tig+j ; 4kt+2+j <-> 16kt+8+2tig+j
        float xv0[16], xv1[16];
        #pragma unroll
        for (int kt = 0; kt < 4; kt++) {
            const int clo = 16 * kt + 2 * tig, chi = clo + 8;
            const float* xa = x + xbase + (size_t)clo * HWPIX;
            const float* xb = x + xbase + (size_t)chi * HWPIX;
            xv0[4 * kt]     = xa[gp0];          xv0[4 * kt + 1] = xa[HWPIX + gp0];
            xv0[4 * kt + 2] = xb[gp0];          xv0[4 * kt + 3] = xb[HWPIX + gp0];
            xv1[4 * kt]     = xa[gp1];          xv1[4 * kt + 1] = xa[HWPIX + gp1];
            xv1[4 * kt + 2] = xb[gp1];          xv1[4 * kt + 3] = xb[HWPIX + gp1];
        }

        // LN stats via quad reduction
        float s0 = 0.f, q0 = 0.f, s1 = 0.f, q1 = 0.f;
        #pragma unroll
        for (int i = 0; i < 16; i++) {
            s0 += xv0[i]; q0 += xv0[i] * xv0[i];
            s1 += xv1[i]; q1 += xv1[i] * xv1[i];
        }
        s0 = qsum(s0); q0 = qsum(q0); s1 = qsum(s1); q1 = qsum(q1);
        const float mu0 = s0 * (1.f / 64.f);
        const float rs0 = rsqrtf(q0 * (1.f / 64.f) - mu0 * mu0 + 1e-6f);
        const float mu1 = s1 * (1.f / 64.f);
        const float rs1 = rsqrtf(q1 * (1.f / 64.f) - mu1 * mu1 + 1e-6f);

        // GEMM: A frags built in regs
        float acc[64];
        #pragma unroll
        for (int i = 0; i < 64; i++) acc[i] = 0.f;
        #pragma unroll
        for (int kt = 0; kt < 4; kt++) {
            const int clo = 16 * kt + 2 * tig, chi = clo + 8;
            uint32_t a0 = bfpack((xv0[4 * kt]     - mu0) * rs0 * n1ws[clo]     + n1bs[clo],
                                 (xv0[4 * kt + 1] - mu0) * rs0 * n1ws[clo + 1] + n1bs[clo + 1]);
            uint32_t a1 = bfpack((xv1[4 * kt]     - mu1) * rs1 * n1ws[clo]     + n1bs[clo],
                                 (xv1[4 * kt + 1] - mu1) * rs1 * n1ws[clo + 1] + n1bs[clo + 1]);
            uint32_t a2 = bfpack((xv0[4 * kt + 2] - mu0) * rs0 * n1ws[chi]     + n1bs[chi],
                                 (xv0[4 * kt + 3] - mu0) * rs0 * n1ws[chi + 1] + n1bs[chi + 1]);
            uint32_t a3 = bfpack((xv1[4 * kt + 2] - mu1) * rs1 * n1ws[chi]     + n1bs[chi],
                                 (xv1[4 * kt + 3] - mu1) * rs1 * n1ws[chi + 1] + n1bs[chi + 1]);
            const int k0 = kt * 8 + tig;
            #pragma unroll
            for (int nt = 0; nt < 16; nt++) {
                const uint32_t* bw = Wb + (nt * 8 + g) * TSU + k0;
                mma_bf16(acc[nt * 4], acc[nt * 4 + 1], acc[nt * 4 + 2], acc[nt * 4 + 3],
                         a0, a1, a2, a3, bw[0], bw[4]);
            }
        }

        // direct channel-last f32 store
        float* o0 = g_t + tb2 + (size_t)gp0 * DW;
        float* o1 = g_t + tb2 + (size_t)gp1 * DW;
        #pragma unroll
        for (int nt = 0; nt < 16; nt++) {
            const int o = nt * 8 + 2 * tig;
            *reinterpret_cast<float2*>(o0 + o) =
                make_float2(acc[nt * 4]     + b1s[o], acc[nt * 4 + 1] + b1s[o + 1]);
            *reinterpret_cast<float2*>(o1 + o) =
                make_float2(acc[nt * 4 + 2] + b1s[o], acc[nt * 4 + 3] + b1s[o + 1]);
        }
    }
}

// =====================================================================
// K2: depthwise 3x3 + SimpleGate + per-cell channel sums (channel-last IO).
// =====================================================================
#define K2_SMEMB (16 * 1156 * 4)
__global__ __launch_bounds__(256, 2) void k2_dw_gate(
    const float* __restrict__ w2, const float* __restrict__ b2,
    const float* __restrict__ mod2)
{
    extern __shared__ float tiles[];          // [16][1156]
    __shared__ float w2s[16 * 9];
    __shared__ float b2s[16];
    __shared__ float redbuf[64];

    const int bidx = blockIdx.x;
    const int b    = bidx >> 9;
    const int cell = (bidx >> 3) & 63;
    const int grp  = bidx & 7;
    const int u    = cell >> 3, v = cell & 7;
    const int tid  = threadIdx.x;
    const int cbase = grp * 8;

    if (tid < 16) {
        const int ch = (tid < 8) ? (cbase + tid) : (64 + cbase + tid - 8);
        const float m = mod2[(size_t)(b * DW + ch) * 64 + cell];
        float ss = 0.f;
        float wv[9];
        #pragma unroll
        for (int k = 0; k < 9; k++) { wv[k] = w2[ch * 9 + k] * m; ss += wv[k] * wv[k]; }
        const float rr = rsqrtf(ss);
        #pragma unroll
        for (int k = 0; k < 9; k++) w2s[tid * 9 + k] = wv[k] * rr;
        b2s[tid] = b2[ch];
    }
    __syncthreads();

    const size_t tb2 = (size_t)b * HWPIX * DW;
    const int h0 = u * 32 - 1, w0 = v * 32 - 1;

    for (int i = tid; i < 1156; i += 256) {
        const int ih = i / 34, iw = i - ih * 34;
        const int hh = h0 + ih, ww2 = w0 + iw;
        float4 qa0, qa1, qg0, qg1;
        if ((hh >= 0) & (hh < HH) & (ww2 >= 0) & (ww2 < WW)) {
            const float* bp = g_t + tb2 + (size_t)(hh * WW + ww2) * DW;
            qa0 = *reinterpret_cast<const float4*>(bp + cbase);
            qa1 = *reinterpret_cast<const float4*>(bp + cbase + 4);
            qg0 = *reinterpret_cast<const float4*>(bp + 64 + cbase);
            qg1 = *reinterpret_cast<const float4*>(bp + 64 + cbase + 4);
        } else {
            qa0 = qa1 = qg0 = qg1 = make_float4(0.f, 0.f, 0.f, 0.f);
        }
        tiles[0 * 1156 + i] = qa0.x;  tiles[1 * 1156 + i] = qa0.y;
        tiles[2 * 1156 + i] = qa0.z;  tiles[3 * 1156 + i] = qa0.w;
        tiles[4 * 1156 + i] = qa1.x;  tiles[5 * 1156 + i] = qa1.y;
        tiles[6 * 1156 + i] = qa1.z;  tiles[7 * 1156 + i] = qa1.w;
        tiles[8 * 1156 + i] = qg0.x;  tiles[9 * 1156 + i] = qg0.y;
        tiles[10 * 1156 + i] = qg0.z; tiles[11 * 1156 + i] = qg0.w;
        tiles[12 * 1156 + i] = qg1.x; tiles[13 * 1156 + i] = qg1.y;
        tiles[14 * 1156 + i] = qg1.z; tiles[15 * 1156 + i] = qg1.w;
    }
    __syncthreads();

    const int lane = tid & 31, warp = tid >> 5;
    const size_t ymb = (size_t)b * HWPIX * C;
    float csum[8];
    #pragma unroll
    for (int j = 0; j < 8; j++) csum[j] = 0.f;

    #pragma unroll
    for (int k = 0; k < 4; k++) {
        const int p = k * 256 + tid;
        const int ph = p >> 5, pw = p & 31;
        float ov[8];
        #pragma unroll
        for (int j = 0; j < 8; j++) {
            float a = b2s[j], gg = b2s[8 + j];
            const float* wA = w2s + j * 9;
            const float* wG = w2s + (8 + j) * 9;
            const float* tA = tiles + j * 1156;
            const float* tG = tiles + (8 + j) * 1156;
            #pragma unroll
            for (int dh = 0; dh < 3; dh++) {
                #pragma unroll
                for (int dw2 = 0; dw2 < 3; dw2++) {
                    const int ti = (ph + dh) * 34 + pw + dw2;
                    a += wA[dh * 3 + dw2] * tA[ti];
                    gg += wG[dh * 3 + dw2] * tG[ti];
                }
            }
            ov[j] = a * gg;
            csum[j] += ov[j];
        }
        float* yp = g_ymid + ymb + (size_t)((u * 32 + ph) * WW + v * 32 + pw) * C + cbase;
        *reinterpret_cast<float4*>(yp)     = make_float4(ov[0], ov[1], ov[2], ov[3]);
        *reinterpret_cast<float4*>(yp + 4) = make_float4(ov[4], ov[5], ov[6], ov[7]);
    }

    #pragma unroll
    for (int j = 0; j < 8; j++) {
        float ls = csum[j];
        for (int off = 16; off; off >>= 1) ls += __shfl_down_sync(0xffffffffu, ls, off);
        if (lane == 0) redbuf[j * 8 + warp] = ls;
    }
    __syncthreads();
    if (tid < 8) {
        float s = 0.f;
        #pragma unroll
        for (int i = 0; i < 8; i++) s += redbuf[tid * 8 + i];
        g_sums[((size_t)b * CELLS + cell) * C + cbase + tid] = s;
    }
}

// =====================================================================
// K4 (bf16 mma, fully register-resident chain):
// SCA -> conv3 -> y1(regs) -> LN2(quad shfl) -> conv4+gate(regs) -> conv5 -> out
// grid=128, block=512. Smem = weights only. No per-tile syncs.
// =====================================================================
#define K4_W3B   0                          // 64*TSU u32
#define K4_W4B   (K4_W3B + 64*TSU*4)        // 128*TSU u32
#define K4_W5B   (K4_W4B + 128*TSU*4)       // 64*TSU u32
#define K4_SC1   (K4_W5B + 64*TSU*4)        // 256 f32 scratch
#define K4_SC2   (K4_SC1 + 256*4)           // 64 f32
#define K4_SSM   (K4_SC2 + 64*4)            // 64
#define K4_B3    (K4_SSM + 64*4)            // 64
#define K4_BE    (K4_B3 + 64*4)             // 64
#define K4_B5    (K4_BE + 64*4)             // 64
#define K4_GA    (K4_B5 + 64*4)             // 64
#define K4_AW    (K4_GA + 64*4)             // 128
#define K4_BW    (K4_AW + 128*4)            // 128
#define K4_SMEMB (K4_BW + 128*4)

__global__ __launch_bounds__(512) void k4_tc(
    const float* __restrict__ x,
    const float* __restrict__ b3, const float* __restrict__ b5,
    const float* __restrict__ beta, const float* __restrict__ gamma,
    const float* __restrict__ scaw, const float* __restrict__ scab,
    float* __restrict__ out)
{
    extern __shared__ char smc[];
    uint32_t* w3b = reinterpret_cast<uint32_t*>(smc + K4_W3B);
    uint32_t* w4b = reinterpret_cast<uint32_t*>(smc + K4_W4B);
    uint32_t* w5b = reinterpret_cast<uint32_t*>(smc + K4_W5B);
    float* sc1 = reinterpret_cast<float*>(smc + K4_SC1);
    float* sc2 = reinterpret_cast<float*>(smc + K4_SC2);
    float* ssm = reinterpret_cast<float*>(smc + K4_SSM);
    float* b3s = reinterpret_cast<float*>(smc + K4_B3);
    float* bes = reinterpret_cast<float*>(smc + K4_BE);
    float* b5s = reinterpret_cast<float*>(smc + K4_B5);
    float* gas = reinterpret_cast<float*>(smc + K4_GA);
    float* Aw  = reinterpret_cast<float*>(smc + K4_AW);
    float* Bw  = reinterpret_cast<float*>(smc + K4_BW);

    const int tid = threadIdx.x;
    const int wid = tid >> 5, lane = tid & 31;
    const int g = lane >> 2, tig = lane & 3;
    const int cta = blockIdx.x;
    const int b = cta >> 6, cell = cta & 63;
    const int u = cell >> 3, v = cell & 7;

    // ---- SCA in prologue ----
    if (tid < 256) {
        const int c = tid & 63, seg = tid >> 6;
        float s = 0.f;
        #pragma unroll 4
        for (int cl = seg * 16; cl < seg * 16 + 16; cl++)
            s += g_sums[((size_t)b * CELLS + cl) * C + c];
        sc1[tid] = s;
    }
    // ---- stage weights (bf16) ----
    const float* cellw = g_wd + ((size_t)(b * 64 + cell)) * PERCELL;
    for (int i = tid; i < 1024; i += 512) {
        int o = i >> 4, m = i & 15;
        float4 q3 = *reinterpret_cast<const float4*>(cellw + W3OFF + o * 64 + 4 * m);
        float4 q5 = *reinterpret_cast<const float4*>(cellw + W5OFF + o * 64 + 4 * m);
        *reinterpret_cast<uint2*>(w3b + o * TSU + 2 * m) =
            make_uint2(bfpack(q3.x, q3.y), bfpack(q3.z, q3.w));
        *reinterpret_cast<uint2*>(w5b + o * TSU + 2 * m) =
            make_uint2(bfpack(q5.x, q5.y), bfpack(q5.z, q5.w));
    }
    for (int i = tid; i < 2048; i += 512) {
        int o = i >> 4, m = i & 15;
        float4 q = *reinterpret_cast<const float4*>(cellw + W4OFF + o * 64 + 4 * m);
        *reinterpret_cast<uint2*>(w4b + o * TSU + 2 * m) =
            make_uint2(bfpack(q.x, q.y), bfpack(q.z, q.w));
    }
    if (tid < 64) {
        b3s[tid] = b3[tid];
        bes[tid] = beta[tid];
        b5s[tid] = b5[tid];
        gas[tid] = gamma[tid];
    }
    if (tid < 128) { Aw[tid] = cellw[AOFF + tid]; Bw[tid] = cellw[BOFF + tid]; }
    __syncthreads();
    if (tid < 64)
        sc2[tid] = (sc1[tid] + sc1[64 + tid] + sc1[128 + tid] + sc1[192 + tid]) * (1.f / (float)HWPIX);
    __syncthreads();
    if (tid < 64) {
        float acc = scab[tid];
        #pragma unroll 8
        for (int cc = 0; cc < 64; cc++) acc += scaw[tid * 64 + cc] * sc2[cc];
        ssm[tid] = acc;
    }
    __syncthreads();

    const size_t xbase = (size_t)b * C * HWPIX;
    const size_t ymb   = (size_t)b * HWPIX * C;
    const int w16 = wid * 16;
    const int p0 = w16 + g, p1 = p0 + 8;

    #pragma unroll 1
    for (int t = 0; t < 4; t++) {
        const int pix0 = (u * 32 + t * 8) * WW + v * 32;
        const int gp0 = pix0 + ((p0 >> 5) << 8) + (p0 & 31);
        const int gp1 = pix0 + ((p1 >> 5) << 8) + (p1 & 31);

        // ---- GEMM1: conv3 (N=64), A fragment-loaded from g_ymid ----
        float acc1[32];
        #pragma unroll
        for (int i = 0; i < 32; i++) acc1[i] = 0.f;
        #pragma unroll
        for (int kt = 0; kt < 4; kt++) {
            const int clo = 16 * kt + 2 * tig, chi = clo + 8;
            float2 l0 = *reinterpret_cast<const float2*>(g_ymid + ymb + (size_t)gp0 * C + clo);
            float2 l1 = *reinterpret_cast<const float2*>(g_ymid + ymb + (size_t)gp1 * C + clo);
            float2 h0 = *reinterpret_cast<const float2*>(g_ymid + ymb + (size_t)gp0 * C + chi);
            float2 h1 = *reinterpret_cast<const float2*>(g_ymid + ymb + (size_t)gp1 * C + chi);
            uint32_t a0 = bfpack(l0.x * ssm[clo], l0.y * ssm[clo + 1]);
            uint32_t a1 = bfpack(l1.x * ssm[clo], l1.y * ssm[clo + 1]);
            uint32_t a2 = bfpack(h0.x * ssm[chi], h0.y * ssm[chi + 1]);
            uint32_t a3 = bfpack(h1.x * ssm[chi], h1.y * ssm[chi + 1]);
            const int k0 = kt * 8 + tig;
            #pragma unroll
            for (int nt = 0; nt < 8; nt++) {
                const uint32_t* bw = w3b + (nt * 8 + g) * TSU + k0;
                mma_bf16(acc1[nt * 4], acc1[nt * 4 + 1], acc1[nt * 4 + 2], acc1[nt * 4 + 3],
                         a0, a1, a2, a3, bw[0], bw[4]);
            }
        }

        // ---- y1 in registers: y0f/y1f[2nt+j] = pixel p0/p1, channel 8nt+2tig+j ----
        float y0f[16], y1f[16];
        #pragma unroll
        for (int nt = 0; nt < 8; nt++) {
            const int c = nt * 8 + 2 * tig;
            const float* xp0 = x + xbase + (size_t)c * HWPIX;
            y0f[2 * nt]     = xp0[gp0]         + (acc1[nt * 4]     + b3s[c])     * bes[c];
            y0f[2 * nt + 1] = xp0[HWPIX + gp0] + (acc1[nt * 4 + 1] + b3s[c + 1]) * bes[c + 1];
            y1f[2 * nt]     = xp0[gp1]         + (acc1[nt * 4 + 2] + b3s[c])     * bes[c];
            y1f[2 * nt + 1] = xp0[HWPIX + gp1] + (acc1[nt * 4 + 3] + b3s[c + 1]) * bes[c + 1];
        }

        // ---- LN2 stats via quad reduction ----
        float s0 = 0.f, q0 = 0.f, s1 = 0.f, q1 = 0.f;
        #pragma unroll
        for (int i = 0; i < 16; i++) {
            s0 += y0f[i]; q0 += y0f[i] * y0f[i];
            s1 += y1f[i]; q1 += y1f[i] * y1f[i];
        }
        s0 = qsum(s0); q0 = qsum(q0); s1 = qsum(s1); q1 = qsum(q1);
        const float mu0 = s0 * (1.f / 64.f);
        const float rs0 = rsqrtf(q0 * (1.f / 64.f) - mu0 * mu0 + 1e-6f);
        const float mu1 = s1 * (1.f / 64.f);
        const float rs1 = rsqrtf(q1 * (1.f / 64.f) - mu1 * mu1 + 1e-6f);

        // ---- GEMM2: conv4 (N=128, LN folded), A from y1 registers ----
        float acc2[64];
        #pragma unroll
        for (int i = 0; i < 64; i++) acc2[i] = 0.f;
        #pragma unroll
        for (int kt = 0; kt < 4; kt++) {
            uint32_t a0 = bfpack(y0f[4 * kt],     y0f[4 * kt + 1]);
            uint32_t a1 = bfpack(y1f[4 * kt],     y1f[4 * kt + 1]);
            uint32_t a2 = bfpack(y0f[4 * kt + 2], y0f[4 * kt + 3]);
            uint32_t a3 = bfpack(y1f[4 * kt + 2], y1f[4 * kt + 3]);
            const int k0 = kt * 8 + tig;
            #pragma unroll
            for (int nt = 0; nt < 16; nt++) {
                const uint32_t* bw = w4b + (nt * 8 + g) * TSU + k0;
                mma_bf16(acc2[nt * 4], acc2[nt * 4 + 1], acc2[nt * 4 + 2], acc2[nt * 4 + 3],
                         a0, a1, a2, a3, bw[0], bw[4]);
            }
        }

        // ---- gate -> zc registers ----
        float z0f[16], z1f[16];
        #pragma unroll
        for (int nt = 0; nt < 8; nt++) {
            const int c = nt * 8 + 2 * tig;
            float za00 = rs0 * (acc2[nt * 4]           - mu0 * Aw[c])      + Bw[c];
            float za01 = rs0 * (acc2[nt * 4 + 1]       - mu0 * Aw[c + 1])  + Bw[c + 1];
            float zg00 = rs0 * (acc2[(nt + 8) * 4]     - mu0 * Aw[c + 64]) + Bw[c + 64];
            float zg01 = rs0 * (acc2[(nt + 8) * 4 + 1] - mu0 * Aw[c + 65]) + Bw[c + 65];
            float za10 = rs1 * (acc2[nt * 4 + 2]       - mu1 * Aw[c])      + Bw[c];
            float za11 = rs1 * (acc2[nt * 4 + 3]       - mu1 * Aw[c + 1])  + Bw[c + 1];
            float zg10 = rs1 * (acc2[(nt + 8) * 4 + 2] - mu1 * Aw[c + 64]) + Bw[c + 64];
            float zg11 = rs1 * (acc2[(nt + 8) * 4 + 3] - mu1 * Aw[c + 65]) + Bw[c + 65];
            z0f[2 * nt]     = za00 * zg00;
            z0f[2 * nt + 1] = za01 * zg01;
            z1f[2 * nt]     = za10 * zg10;
            z1f[2 * nt + 1] = za11 * zg11;
        }

        // ---- GEMM3: conv5 (N=64), A from zc registers ----
        float acc3[32];
        #pragma unroll
        for (int i = 0; i < 32; i++) acc3[i] = 0.f;
        #pragma unroll
        for (int kt = 0; kt < 4; kt++) {
            uint32_t a0 = bfpack(z0f[4 * kt],     z0f[4 * kt + 1]);
            uint32_t a1 = bfpack(z1f[4 * kt],     z1f[4 * kt + 1]);
            uint32_t a2 = bfpack(z0f[4 * kt + 2], z0f[4 * kt + 3]);
            uint32_t a3 = bfpack(z1f[4 * kt + 2], z1f[4 * kt + 3]);
            const int k0 = kt * 8 + tig;
            #pragma unroll
            for (int nt = 0; nt < 8; nt++) {
                const uint32_t* bw = w5b + (nt * 8 + g) * TSU + k0;
                mma_bf16(acc3[nt * 4], acc3[nt * 4 + 1], acc3[nt * 4 + 2], acc3[nt * 4 + 3],
                         a0, a1, a2, a3, bw[0], bw[4]);
            }
        }

        // ---- final epilogue (direct STG) ----
        #pragma unroll
        for (int nt = 0; nt < 8; nt++) {
            const int c = nt * 8 + 2 * tig;
            float* op0 = out + xbase + (size_t)c * HWPIX;
            op0[gp0]          = y0f[2 * nt]     + (acc3[nt * 4]     + b5s[c])     * gas[c];
            op0[HWPIX + gp0]  = y0f[2 * nt + 1] + (acc3[nt * 4 + 1] + b5s[c + 1]) * gas[c + 1];
            op0[gp1]          = y1f[2 * nt]     + (acc3[nt * 4 + 2] + b5s[c])     * gas[c];
            op0[HWPIX + gp1]  = y1f[2 * nt + 1] + (acc3[nt * 4 + 3] + b5s[c + 1]) * gas[c + 1];
        }
    }
}

// =====================================================================
// launch
// =====================================================================
extern "C" void kernel_launch(void* const* d_in, const int* in_sizes, int n_in,
                              void* d_out, int out_size)
{
    (void)in_sizes; (void)n_in; (void)out_size;
    const float* x     = (const float*)d_in[0];
    const float* w1    = (const float*)d_in[1];
    const float* b1    = (const float*)d_in[2];
    const float* w2    = (const float*)d_in[3];
    const float* b2    = (const float*)d_in[4];
    const float* w3    = (const float*)d_in[5];
    const float* b3    = (const float*)d_in[6];
    const float* scaw  = (const float*)d_in[7];
    const float* scab  = (const float*)d_in[8];
    const float* w4    = (const float*)d_in[9];
    const float* b4    = (const float*)d_in[10];
    const float* w5    = (const float*)d_in[11];
    const float* b5    = (const float*)d_in[12];
    const float* n1w   = (const float*)d_in[13];
    const float* n1b   = (const float*)d_in[14];
    const float* n2w   = (const float*)d_in[15];
    const float* n2b   = (const float*)d_in[16];
    const float* beta  = (const float*)d_in[17];
    const float* gamma = (const float*)d_in[18];
    const float* mod1  = (const float*)d_in[19];
    const float* mod2  = (const float*)d_in[20];
    const float* mod3  = (const float*)d_in[21];
    const float* mod4  = (const float*)d_in[22];
    const float* mod5  = (const float*)d_in[23];
    float* out = (float*)d_out;

    cudaFuncSetAttribute(k1_tc, cudaFuncAttributeMaxDynamicSharedMemorySize, K1_SMEMB);
    cudaFuncSetAttribute(k2_dw_gate, cudaFuncAttributeMaxDynamicSharedMemorySize, K2_SMEMB);
    cudaFuncSetAttribute(k4_tc, cudaFuncAttributeMaxDynamicSharedMemorySize, K4_SMEMB);

    k0_demod<<<2 * 384, 256>>>(w1, w3, w4, w5, b4, n2w, n2b, mod1, mod3, mod4, mod5);
    k1_tc<<<BATCH * CELLS, 512, K1_SMEMB>>>(x, b1, n1w, n1b);
    k2_dw_gate<<<1024, 256, K2_SMEMB>>>(w2, b2, mod2);
    k4_tc<<<BATCH * CELLS, 512, K4_SMEMB>>>(x, b3, b5, beta, gamma, scaw, scab, out);
}